// round 2
// baseline (speedup 1.0000x reference)
#include <cuda_runtime.h>
#include <math.h>

#define BATCH   4
#define LSEQ    4096
#define MTOT    16384          // BATCH*LSEQ
#define DMODEL  128
#define DINNER  256
#define DSTATE  16
#define NCHUNK  64
#define LCHUNK  64

// ---------------- static scratch (no cudaMalloc anywhere) -------------------
__device__ float g_seqT  [DMODEL  * MTOT];    // [c][m] concat(up,skip)
__device__ float g_xzT   [2*DINNER* MTOT];    // [n][m] rows 0..255 u_raw, 256..511 z
__device__ float g_uT    [DINNER  * MTOT];    // [d][m] conv1d+silu
__device__ float g_deltaT[DINNER  * MTOT];    // [d][m]
__device__ float g_dbc   [MTOT * 40];         // [m][40]  0..7 dt, 8..23 B, 24..39 C
__device__ float g_yT    [DINNER  * MTOT];    // [d][m] scan out * silu(z)
__device__ float g_ym    [MTOT * DMODEL];     // [m][128] out_proj out
__device__ float g_lnT   [DMODEL  * MTOT];    // [c][m] LN+silu out
__device__ float g_hend  [BATCH*DINNER*NCHUNK*DSTATE];
__device__ float g_hin   [BATCH*DINNER*NCHUNK*DSTATE];
__device__ float g_sumd  [BATCH*DINNER*NCHUNK];
__device__ float g_upwT  [256*128];           // [o*4+ij][cin]

__device__ __forceinline__ float silu_f(float x) {
    return x / (1.0f + __expf(-x));
}

// ---------------------------------------------------------------------------
// 0. transpose up_w (128,64,2,2) -> [n=o*4+ij][cin]
// ---------------------------------------------------------------------------
__global__ void k_transpose_upw(const float* __restrict__ upw)
{
    int cin = blockIdx.x;            // 128
    int n   = threadIdx.x;           // 256
    g_upwT[n*128 + cin] = upw[cin*256 + n];
}

// ---------------------------------------------------------------------------
// 1. ConvTranspose2d k=2 s=2 -> channels 0..63 of g_seqT
//    grid: 4 batches * 64 groups of 16 input pixels ; 256 thr = (o,ij)
// ---------------------------------------------------------------------------
__global__ __launch_bounds__(256) void k_upsample(
    const float* __restrict__ x, const float* __restrict__ upb)
{
    __shared__ float xs[16][128];
    int t  = threadIdx.x;
    int b  = blockIdx.x >> 6;
    int p0 = (blockIdx.x & 63) << 4;

    for (int i = t; i < 16*128; i += 256) {
        int pix = i & 15, cin = i >> 4;
        xs[pix][cin] = x[(b*128 + cin)*1024 + p0 + pix];
    }
    __syncthreads();

    int o  = t >> 2;
    int ij = t & 3;
    int ii = ij >> 1, jj = ij & 1;

    float acc[16];
#pragma unroll
    for (int p = 0; p < 16; p++) acc[p] = 0.f;

    const float* wrow = g_upwT + t*128;
    for (int c4 = 0; c4 < 32; c4++) {
        float4 w4 = *reinterpret_cast<const float4*>(wrow + c4*4);
#pragma unroll
        for (int p = 0; p < 16; p++) {
            float4 x4 = *reinterpret_cast<const float4*>(&xs[p][c4*4]);
            acc[p] += x4.x*w4.x + x4.y*w4.y + x4.z*w4.z + x4.w*w4.w;
        }
    }
    float bias = upb[o];
#pragma unroll
    for (int p = 0; p < 16; p++) {
        int hp = (p0 + p) >> 5, wp = (p0 + p) & 31;
        int l  = (2*hp + ii)*64 + 2*wp + jj;
        g_seqT[o*MTOT + b*LSEQ + l] = acc[p] + bias;
    }
}

// ---------------------------------------------------------------------------
// 2. copy skip_x into g_seqT channels 64..127
// ---------------------------------------------------------------------------
__global__ void k_copy_skip(const float* __restrict__ skip)
{
    int idx = blockIdx.x*256 + threadIdx.x;   // 4*64*4096 total
    int l = idx & 4095;
    int c = (idx >> 12) & 63;
    int b = idx >> 18;
    g_seqT[(64 + c)*MTOT + b*LSEQ + l] = skip[idx];
}

// ---------------------------------------------------------------------------
// 3. SGEMM: C[n][m] = sum_k W[n][k] * Bm[k][m],  M = 16384 fixed.
//    64x64 tiles, K-step 16, 256 threads, 4x4 microtile.
//    mode 0: C channel-major [n][MTOT]
//    mode 1: C row-major     [m][ldc] (transposed store)
//    mode 2: NCHW 4D output  [(m>>12)*64 + n][4096] + bias[n]
// ---------------------------------------------------------------------------
__global__ __launch_bounds__(256) void k_sgemm(
    const float* __restrict__ W, const float* __restrict__ Bm,
    float* __restrict__ C, const float* __restrict__ bias,
    int N, int K, int mode, int ldc)
{
    __shared__ float Ws[16][68];
    __shared__ float Bs[16][68];

    int tid = threadIdx.x;
    int tx = tid & 15;            // m microtile
    int ty = tid >> 4;            // n microtile
    int m0 = blockIdx.x * 64;
    int n0 = blockIdx.y * 64;

    float acc[4][4];
#pragma unroll
    for (int i = 0; i < 4; i++)
#pragma unroll
        for (int j = 0; j < 4; j++) acc[i][j] = 0.f;

    int lw_k = tid & 15;          // Ws load: k
    int lw_n = tid >> 4;          //          n base (stride 16)
    int lb_k = tid >> 4;          // Bs load: k
    int lb_m = (tid & 15) * 4;    //          m (float4)

    for (int k0 = 0; k0 < K; k0 += 16) {
#pragma unroll
        for (int q = 0; q < 4; q++) {
            int n = lw_n + q*16;
            float v = 0.f;
            if (n0 + n < N) v = W[(n0 + n)*K + k0 + lw_k];
            Ws[lw_k][n] = v;
        }
        {
            float4 v = *reinterpret_cast<const float4*>(
                Bm + (size_t)(k0 + lb_k)*MTOT + m0 + lb_m);
            *reinterpret_cast<float4*>(&Bs[lb_k][lb_m]) = v;
        }
        __syncthreads();

#pragma unroll
        for (int k = 0; k < 16; k++) {
            float4 wf = *reinterpret_cast<const float4*>(&Ws[k][ty*4]);
            float4 bf = *reinterpret_cast<const float4*>(&Bs[k][tx*4]);
            float wa[4] = {wf.x, wf.y, wf.z, wf.w};
            float ba[4] = {bf.x, bf.y, bf.z, bf.w};
#pragma unroll
            for (int i = 0; i < 4; i++)
#pragma unroll
                for (int j = 0; j < 4; j++)
                    acc[i][j] += wa[i]*ba[j];
        }
        __syncthreads();
    }

    if (mode == 0) {
#pragma unroll
        for (int i = 0; i < 4; i++) {
            int n = n0 + ty*4 + i;
            if (n < N) {
                float4 v = make_float4(acc[i][0], acc[i][1], acc[i][2], acc[i][3]);
                *reinterpret_cast<float4*>(C + (size_t)n*MTOT + m0 + tx*4) = v;
            }
        }
    } else if (mode == 1) {
        int cy = n0 + ty*4;
        if (cy < N) {
#pragma unroll
            for (int j = 0; j < 4; j++) {
                int m = m0 + tx*4 + j;
                float4 v = make_float4(acc[0][j], acc[1][j], acc[2][j], acc[3][j]);
                *reinterpret_cast<float4*>(C + (size_t)m*ldc + cy) = v;
            }
        }
    } else {
        int bidx = m0 >> 12;
        int lrem = (m0 & 4095) + tx*4;
#pragma unroll
        for (int i = 0; i < 4; i++) {
            int n = n0 + ty*4 + i;
            if (n < N) {
                float bb = bias ? bias[n] : 0.f;
                float4 v = make_float4(acc[i][0]+bb, acc[i][1]+bb,
                                       acc[i][2]+bb, acc[i][3]+bb);
                *reinterpret_cast<float4*>(C + (size_t)bidx*262144 + (size_t)n*4096 + lrem) = v;
            }
        }
    }
}

// ---------------------------------------------------------------------------
// 4. depthwise causal conv1d (D_CONV=4) + bias + silu
//    grid (64 m-chunks, 256 d) ; block 256 over m
// ---------------------------------------------------------------------------
__global__ void k_conv1d_silu(const float* __restrict__ cw,
                              const float* __restrict__ cb)
{
    int d = blockIdx.y;
    int m = blockIdx.x*256 + threadIdx.x;
    int l = m & 4095;
    const float* row = g_xzT + (size_t)d*MTOT;
    float w0 = cw[d*4+0], w1 = cw[d*4+1], w2 = cw[d*4+2], w3 = cw[d*4+3];
    float acc = cb[d];
    if (l >= 3) acc += w0*row[m-3];
    if (l >= 2) acc += w1*row[m-2];
    if (l >= 1) acc += w2*row[m-1];
    acc += w3*row[m];
    g_uT[(size_t)d*MTOT + m] = silu_f(acc);
}

// ---------------------------------------------------------------------------
// 5. delta = softplus(dt @ dt_proj_w.T + dt_proj_b) -> g_deltaT [d][m]
//    block per 64 m ; 256 threads
// ---------------------------------------------------------------------------
__global__ void k_delta(const float* __restrict__ dtw,
                        const float* __restrict__ dtb)
{
    __shared__ float sdt[64][8];
    int tid = threadIdx.x;
    int m0 = blockIdx.x*64;
    if (tid < 512) {
        int ml = tid >> 3, r = tid & 7;
        sdt[ml][r] = g_dbc[(size_t)(m0 + ml)*40 + r];
    }
    __syncthreads();
    int ml = tid & 63;
    int dl = tid >> 6;   // 0..3
    for (int it = 0; it < 64; it++) {
        int d = it*4 + dl;
        const float* wr = dtw + d*8;
        float x = dtb[d];
#pragma unroll
        for (int r = 0; r < 8; r++) x += wr[r]*sdt[ml][r];
        float sp = (x > 20.f) ? x : log1pf(__expf(x));
        g_deltaT[(size_t)d*MTOT + m0 + ml] = sp;
    }
}

// ---------------------------------------------------------------------------
// 6. scan pass 1: per-chunk partial scan from h=0, record h_end & sum(delta)
//    warp handles 2 channels d, 16 states each. 32768 warps.
// ---------------------------------------------------------------------------
__global__ __launch_bounds__(128) void k_scan1(const float* __restrict__ A_log)
{
    int lane = threadIdx.x & 31;
    int wgid = blockIdx.x*4 + (threadIdx.x >> 5);
    int ch = wgid & 63;
    int dp = (wgid >> 6) & 127;
    int b  = wgid >> 13;
    int dd = lane >> 4, n = lane & 15;
    int d  = dp*2 + dd;

    float A = -__expf(A_log[d*DSTATE + n]);
    int m0 = b*LSEQ + ch*LCHUNK;
    const float* drow = g_deltaT + (size_t)d*MTOT;
    const float* urow = g_uT     + (size_t)d*MTOT;

    float h = 0.f, sumd = 0.f;
#pragma unroll 4
    for (int l = 0; l < LCHUNK; l++) {
        int m = m0 + l;
        float dt = drow[m];
        float uu = urow[m];
        float Bn = g_dbc[(size_t)m*40 + 8 + n];
        h = __expf(dt*A)*h + dt*Bn*uu;
        sumd += dt;
    }
    int bd = b*DINNER + d;
    g_hend[((size_t)bd*NCHUNK + ch)*DSTATE + n] = h;
    if (n == 0) g_sumd[(size_t)bd*NCHUNK + ch] = sumd;
}

// ---------------------------------------------------------------------------
// 7. scan pass 2: serial carry over 64 chunks per (b,d)
// ---------------------------------------------------------------------------
__global__ void k_scan2(const float* __restrict__ A_log)
{
    int gt = blockIdx.x*256 + threadIdx.x;
    int w  = gt >> 5;               // 0..511
    int lane = gt & 31;
    int dd = lane >> 4, n = lane & 15;
    int bd = w*2 + dd;              // 0..1023
    int d  = bd & 255;

    float A = -__expf(A_log[d*DSTATE + n]);
    float h = 0.f;
    for (int ch = 0; ch < NCHUNK; ch++) {
        size_t base = ((size_t)bd*NCHUNK + ch)*DSTATE + n;
        g_hin[base] = h;
        float sd = g_sumd[(size_t)bd*NCHUNK + ch];
        h = __expf(sd*A)*h + g_hend[base];
    }
}

// ---------------------------------------------------------------------------
// 8. scan pass 3: rescan with correct entry state, emit
//    y = (sum_n h*C + u*Dp) * silu(z)  ->  g_yT [d][m]
// ---------------------------------------------------------------------------
__global__ __launch_bounds__(128) void k_scan3(const float* __restrict__ A_log,
                                               const float* __restrict__ Dp)
{
    int lane = threadIdx.x & 31;
    int wgid = blockIdx.x*4 + (threadIdx.x >> 5);
    int ch = wgid & 63;
    int dp = (wgid >> 6) & 127;
    int b  = wgid >> 13;
    int dd = lane >> 4, n = lane & 15;
    int d  = dp*2 + dd;
    int bd = b*DINNER + d;

    float A = -__expf(A_log[d*DSTATE + n]);
    float Dd = Dp[d];
    int m0 = b*LSEQ + ch*LCHUNK;
    const float* drow = g_deltaT + (size_t)d*MTOT;
    const float* urow = g_uT     + (size_t)d*MTOT;
    const float* zrow = g_xzT    + (size_t)(DINNER + d)*MTOT;
    float*       yrow = g_yT     + (size_t)d*MTOT;

    float h = g_hin[((size_t)bd*NCHUNK + ch)*DSTATE + n];

    for (int l = 0; l < LCHUNK; l++) {
        int m = m0 + l;
        float dt = drow[m];
        float uu = urow[m];
        float Bn = g_dbc[(size_t)m*40 + 8 + n];
        float Cn = g_dbc[(size_t)m*40 + 24 + n];
        h = __expf(dt*A)*h + dt*Bn*uu;
        float y = h*Cn;
        y += __shfl_xor_sync(0xffffffffu, y, 8, 16);
        y += __shfl_xor_sync(0xffffffffu, y, 4, 16);
        y += __shfl_xor_sync(0xffffffffu, y, 2, 16);
        y += __shfl_xor_sync(0xffffffffu, y, 1, 16);
        if (n == 0) {
            float z = zrow[m];
            yrow[m] = (y + uu*Dd) * silu_f(z);
        }
    }
}

// ---------------------------------------------------------------------------
// 9. LayerNorm over 128 channels + silu ; write channel-major g_lnT
//    block = 8 warps * 4 iters = 32 m
// ---------------------------------------------------------------------------
__global__ __launch_bounds__(256) void k_ln_silu(const float* __restrict__ gamma,
                                                 const float* __restrict__ beta)
{
    __shared__ float sT[128][36];
    int tid = threadIdx.x;
    int wid = tid >> 5, lane = tid & 31;
    int m_base = blockIdx.x*32;

    for (int r = 0; r < 4; r++) {
        int mloc = r*8 + wid;
        int m = m_base + mloc;
        float4 v = *reinterpret_cast<const float4*>(g_ym + (size_t)m*128 + lane*4);
        float s  = v.x + v.y + v.z + v.w;
        float s2 = v.x*v.x + v.y*v.y + v.z*v.z + v.w*v.w;
#pragma unroll
        for (int k = 16; k >= 1; k >>= 1) {
            s  += __shfl_xor_sync(0xffffffffu, s,  k);
            s2 += __shfl_xor_sync(0xffffffffu, s2, k);
        }
        float mean = s * (1.f/128.f);
        float var  = s2 * (1.f/128.f) - mean*mean;
        float rstd = rsqrtf(var + 1e-5f);
        float va[4] = {v.x, v.y, v.z, v.w};
#pragma unroll
        for (int i = 0; i < 4; i++) {
            int c = lane*4 + i;
            float t = (va[i] - mean)*rstd*gamma[c] + beta[c];
            sT[c][mloc] = silu_f(t);
        }
    }
    __syncthreads();

    int mq = tid & 7;          // 8 float4 columns over m
    int c0 = tid >> 3;         // 0..31
    for (int cc = c0; cc < 128; cc += 32) {
        float4 v = *reinterpret_cast<const float4*>(&sT[cc][mq*4]);
        *reinterpret_cast<float4*>(g_lnT + (size_t)cc*MTOT + m_base + mq*4) = v;
    }
}

// ---------------------------------------------------------------------------
extern "C" void kernel_launch(void* const* d_in, const int* in_sizes, int n_in,
                              void* d_out, int out_size)
{
    const float* x        = (const float*)d_in[0];
    const float* skip_x   = (const float*)d_in[1];
    const float* up_w     = (const float*)d_in[2];
    const float* up_b     = (const float*)d_in[3];
    const float* in_proj  = (const float*)d_in[4];
    const float* conv1d_w = (const float*)d_in[5];
    const float* conv1d_b = (const float*)d_in[6];
    const float* x_proj   = (const float*)d_in[7];
    const float* dt_proj_w= (const float*)d_in[8];
    const float* dt_proj_b= (const float*)d_in[9];
    const float* A_log    = (const float*)d_in[10];
    const float* Dp       = (const float*)d_in[11];
    const float* out_proj = (const float*)d_in[12];
    const float* ln_gamma = (const float*)d_in[13];
    const float* ln_beta  = (const float*)d_in[14];
    const float* convout_w= (const float*)d_in[15];
    const float* convout_b= (const float*)d_in[16];
    float* out = (float*)d_out;

    float *p_seqT, *p_xzT, *p_uT, *p_yT, *p_lnT, *p_dbc, *p_ym;
    cudaGetSymbolAddress((void**)&p_seqT, g_seqT);
    cudaGetSymbolAddress((void**)&p_xzT,  g_xzT);
    cudaGetSymbolAddress((void**)&p_uT,   g_uT);
    cudaGetSymbolAddress((void**)&p_yT,   g_yT);
    cudaGetSymbolAddress((void**)&p_lnT,  g_lnT);
    cudaGetSymbolAddress((void**)&p_dbc,  g_dbc);
    cudaGetSymbolAddress((void**)&p_ym,   g_ym);

    // 0-2: build seq (channel-major)
    k_transpose_upw<<<128, 256>>>(up_w);
    k_upsample<<<BATCH*64, 256>>>(x, up_b);
    k_copy_skip<<<(BATCH*64*4096)/256, 256>>>(skip_x);

    // 3: in_proj  (N=512, K=128) -> g_xzT channel-major
    k_sgemm<<<dim3(MTOT/64, 512/64), 256>>>(in_proj, p_seqT, p_xzT, nullptr,
                                            512, 128, 0, 0);
    // 4: conv1d + silu -> g_uT
    k_conv1d_silu<<<dim3(MTOT/256, DINNER), 256>>>(conv1d_w, conv1d_b);

    // 5: x_proj (N=40, K=256) -> g_dbc row-major [m][40]
    k_sgemm<<<dim3(MTOT/64, 1), 256>>>(x_proj, p_uT, p_dbc, nullptr,
                                       40, 256, 1, 40);
    // 6: delta
    k_delta<<<MTOT/64, 256>>>(dt_proj_w, dt_proj_b);

    // 7-9: chunked selective scan
    k_scan1<<<8192, 128>>>(A_log);
    k_scan2<<<64, 256>>>(A_log);
    k_scan3<<<8192, 128>>>(A_log, Dp);

    // 10: out_proj (N=128, K=256) -> g_ym row-major [m][128]
    k_sgemm<<<dim3(MTOT/64, 2), 256>>>(out_proj, p_yT, p_ym, nullptr,
                                       128, 256, 1, 128);
    // 11: LayerNorm + silu -> g_lnT channel-major
    k_ln_silu<<<MTOT/32, 256>>>(ln_gamma, ln_beta);

    // 12: convout 1x1 (N=64, K=128) -> d_out NCHW + bias
    k_sgemm<<<dim3(MTOT/64, 1), 256>>>(convout_w, p_lnT, out, convout_b,
                                       64, 128, 2, 0);
}

// round 4
// speedup vs baseline: 1.0001x; 1.0001x over previous
#include <cuda_runtime.h>
#include <math.h>

#define BATCH   4
#define LSEQ    4096
#define MTOT    16384          // BATCH*LSEQ
#define DMODEL  128
#define DINNER  256
#define DSTATE  16
#define NCHUNK  64
#define LCHUNK  64

// ---------------- static scratch (no cudaMalloc anywhere) -------------------
__device__ float g_seqT  [DMODEL  * MTOT];    // [c][m] concat(up,skip)
__device__ float g_xzT   [2*DINNER* MTOT];    // [n][m] rows 0..255 u_raw, 256..511 z
__device__ float g_uT    [DINNER  * MTOT];    // [d][m] conv1d+silu
__device__ float g_deltaT[DINNER  * MTOT];    // [d][m]
__device__ float g_dbc   [MTOT * 40];         // [m][40]  0..7 dt, 8..23 B, 24..39 C
__device__ float g_yT    [DINNER  * MTOT];    // [d][m] scan out * silu(z)
__device__ float g_ym    [MTOT * DMODEL];     // [m][128] out_proj out
__device__ float g_lnT   [DMODEL  * MTOT];    // [c][m] LN+silu out
__device__ float g_hend  [BATCH*DINNER*NCHUNK*DSTATE];
__device__ float g_hin   [BATCH*DINNER*NCHUNK*DSTATE];
__device__ float g_sumd  [BATCH*DINNER*NCHUNK];
__device__ float g_upwT  [256*128];           // [o*4+ij][cin]

__device__ __forceinline__ float silu_f(float x) {
    return x / (1.0f + __expf(-x));
}

// packed f32x2 helpers (sm_100+)
__device__ __forceinline__ unsigned long long pack2(float x) {
    unsigned long long r;
    unsigned int u = __float_as_uint(x);
    asm("mov.b64 %0, {%1, %1};" : "=l"(r) : "r"(u));
    return r;
}
__device__ __forceinline__ void ffma2(unsigned long long &acc,
                                      unsigned long long a,
                                      unsigned long long b) {
    asm("fma.rn.f32x2 %0, %1, %2, %0;" : "+l"(acc) : "l"(a), "l"(b));
}
__device__ __forceinline__ float2 unpk(unsigned long long v) {
    float2 r;
    asm("mov.b64 {%0, %1}, %2;" : "=f"(r.x), "=f"(r.y) : "l"(v));
    return r;
}

// ---------------------------------------------------------------------------
// 0. transpose up_w (128,64,2,2) -> [n=o*4+ij][cin]
// ---------------------------------------------------------------------------
__global__ void k_transpose_upw(const float* __restrict__ upw)
{
    int cin = blockIdx.x;            // 128
    int n   = threadIdx.x;           // 256
    g_upwT[n*128 + cin] = upw[cin*256 + n];
}

// ---------------------------------------------------------------------------
// 1. ConvTranspose2d k=2 s=2 -> channels 0..63 of g_seqT
// ---------------------------------------------------------------------------
__global__ __launch_bounds__(256) void k_upsample(
    const float* __restrict__ x, const float* __restrict__ upb)
{
    __shared__ float xs[16][128];
    int t  = threadIdx.x;
    int b  = blockIdx.x >> 6;
    int p0 = (blockIdx.x & 63) << 4;

    for (int i = t; i < 16*128; i += 256) {
        int pix = i & 15, cin = i >> 4;
        xs[pix][cin] = x[(b*128 + cin)*1024 + p0 + pix];
    }
    __syncthreads();

    int o  = t >> 2;
    int ij = t & 3;
    int ii = ij >> 1, jj = ij & 1;

    float acc[16];
#pragma unroll
    for (int p = 0; p < 16; p++) acc[p] = 0.f;

    const float* wrow = g_upwT + t*128;
    for (int c4 = 0; c4 < 32; c4++) {
        float4 w4 = *reinterpret_cast<const float4*>(wrow + c4*4);
#pragma unroll
        for (int p = 0; p < 16; p++) {
            float4 x4 = *reinterpret_cast<const float4*>(&xs[p][c4*4]);
            acc[p] += x4.x*w4.x + x4.y*w4.y + x4.z*w4.z + x4.w*w4.w;
        }
    }
    float bias = upb[o];
#pragma unroll
    for (int p = 0; p < 16; p++) {
        int hp = (p0 + p) >> 5, wp = (p0 + p) & 31;
        int l  = (2*hp + ii)*64 + 2*wp + jj;
        g_seqT[o*MTOT + b*LSEQ + l] = acc[p] + bias;
    }
}

// ---------------------------------------------------------------------------
// 2. copy skip_x into g_seqT channels 64..127
// ---------------------------------------------------------------------------
__global__ void k_copy_skip(const float* __restrict__ skip)
{
    int idx = blockIdx.x*256 + threadIdx.x;
    int l = idx & 4095;
    int c = (idx >> 12) & 63;
    int b = idx >> 18;
    g_seqT[(64 + c)*MTOT + b*LSEQ + l] = skip[idx];
}

// ---------------------------------------------------------------------------
// 3. SGEMM v3: C[n][m] = sum_k W[n][k]*Bm[k][m]
//    128(m) x 64(n) tile, K-step 16, 256 threads.
//    Microtile per thread: 8 m (tx*4, 64+tx*4) x 4 n (ty*4..+3). FFMA2.
//    mode 0: channel-major [n][MTOT]
//    mode 1: row-major     [m][ldc]
//    mode 2: NCHW + bias   [(m>>12)*N + n][4096]
// ---------------------------------------------------------------------------
__global__ __launch_bounds__(256) void k_sgemm3(
    const float* __restrict__ W, const float* __restrict__ Bm,
    float* __restrict__ C, const float* __restrict__ bias,
    int N, int K, int mode, int ldc)
{
    __shared__ float Bs[16][128];                       // 8 KB
    __shared__ unsigned long long Ws2[16][66];          // (w,w) pairs, pad 2

    int tid = threadIdx.x;
    int tx = tid & 15;            // m: tx*4 and 64+tx*4
    int ty = tid >> 4;            // n: ty*4 .. ty*4+3   (ty 0..15 covers 64)
    int m0 = blockIdx.x * 128;
    int n0 = blockIdx.y * 64;

    // acc[n 0..3][m-pair 0..3]  (pairs 0,1 = m tx*4..+3 ; pairs 2,3 = 64+tx*4..+3)
    unsigned long long acc[4][4];
#pragma unroll
    for (int i = 0; i < 4; i++)
#pragma unroll
        for (int p = 0; p < 4; p++) acc[i][p] = 0ULL;

    int lb_k = tid >> 5;          // 0..7 (+8)
    int lb_m = (tid & 31) * 4;
    int lw_k = tid & 15;
    int lw_n = tid >> 4;          // 0..15 (+16,+32,+48)

    for (int k0 = 0; k0 < K; k0 += 16) {
#pragma unroll
        for (int j = 0; j < 2; j++) {
            int k = lb_k + j*8;
            float4 v = *reinterpret_cast<const float4*>(
                Bm + (size_t)(k0 + k)*MTOT + m0 + lb_m);
            *reinterpret_cast<float4*>(&Bs[k][lb_m]) = v;
        }
#pragma unroll
        for (int j = 0; j < 4; j++) {
            int n = lw_n + j*16;
            float v = 0.f;
            if (n0 + n < N) v = W[(size_t)(n0 + n)*K + k0 + lw_k];
            Ws2[lw_k][n] = pack2(v);
        }
        __syncthreads();

#pragma unroll
        for (int k = 0; k < 16; k++) {
            ulonglong2 b01 = *reinterpret_cast<const ulonglong2*>(&Bs[k][tx*4]);
            ulonglong2 b23 = *reinterpret_cast<const ulonglong2*>(&Bs[k][64 + tx*4]);
            ulonglong2 w01 = *reinterpret_cast<const ulonglong2*>(&Ws2[k][ty*4]);
            ulonglong2 w23 = *reinterpret_cast<const ulonglong2*>(&Ws2[k][ty*4 + 2]);
            unsigned long long bm[4] = {b01.x, b01.y, b23.x, b23.y};
            unsigned long long wn[4] = {w01.x, w01.y, w23.x, w23.y};
#pragma unroll
            for (int i = 0; i < 4; i++)
#pragma unroll
                for (int p = 0; p < 4; p++)
                    ffma2(acc[i][p], bm[p], wn[i]);
        }
        __syncthreads();
    }

    if (mode == 0 || mode == 2) {
#pragma unroll
        for (int i = 0; i < 4; i++) {
            int n = n0 + ty*4 + i;
            if (n >= N) continue;
            float bb = (mode == 2 && bias) ? bias[n] : 0.f;
            float2 p0 = unpk(acc[i][0]), p1 = unpk(acc[i][1]);
            float2 p2 = unpk(acc[i][2]), p3 = unpk(acc[i][3]);
            float4 lo = make_float4(p0.x+bb, p0.y+bb, p1.x+bb, p1.y+bb);
            float4 hi = make_float4(p2.x+bb, p2.y+bb, p3.x+bb, p3.y+bb);
            if (mode == 0) {
                *reinterpret_cast<float4*>(C + (size_t)n*MTOT + m0 + tx*4)      = lo;
                *reinterpret_cast<float4*>(C + (size_t)n*MTOT + m0 + 64 + tx*4) = hi;
            } else {
                int bidx = m0 >> 12;
                int l0   = (m0 & 4095) + tx*4;
                float* base = C + (size_t)bidx*N*4096 + (size_t)n*4096;
                *reinterpret_cast<float4*>(base + l0)      = lo;
                *reinterpret_cast<float4*>(base + l0 + 64) = hi;
            }
        }
    } else {
        // mode 1: row-major [m][ldc]; this thread owns n columns n0+ty*4..+3
        bool ok = (n0 + ty*4) < N;     // N multiple of 4 => whole float4 in range
        if (ok) {
#pragma unroll
            for (int g = 0; g < 2; g++) {
#pragma unroll
                for (int q = 0; q < 4; q++) {
                    int m = m0 + g*64 + tx*4 + q;
                    int p = g*2 + (q >> 1);
                    int h = q & 1;
                    float v[4];
#pragma unroll
                    for (int i = 0; i < 4; i++) {
                        float2 f = unpk(acc[i][p]);
                        v[i] = h ? f.y : f.x;
                    }
                    *reinterpret_cast<float4*>(C + (size_t)m*ldc + n0 + ty*4) =
                        make_float4(v[0], v[1], v[2], v[3]);
                }
            }
        }
    }
}

// ---------------------------------------------------------------------------
// 4. depthwise causal conv1d (D_CONV=4) + bias + silu
// ---------------------------------------------------------------------------
__global__ void k_conv1d_silu(const float* __restrict__ cw,
                              const float* __restrict__ cb)
{
    int d = blockIdx.y;
    int m = blockIdx.x*256 + threadIdx.x;
    int l = m & 4095;
    const float* row = g_xzT + (size_t)d*MTOT;
    float w0 = cw[d*4+0], w1 = cw[d*4+1], w2 = cw[d*4+2], w3 = cw[d*4+3];
    float acc = cb[d];
    if (l >= 3) acc += w0*row[m-3];
    if (l >= 2) acc += w1*row[m-2];
    if (l >= 1) acc += w2*row[m-1];
    acc += w3*row[m];
    g_uT[(size_t)d*MTOT + m] = silu_f(acc);
}

// ---------------------------------------------------------------------------
// 5. delta = softplus(dt @ dt_proj_w.T + dt_proj_b) -> g_deltaT [d][m]
// ---------------------------------------------------------------------------
__global__ void k_delta(const float* __restrict__ dtw,
                        const float* __restrict__ dtb)
{
    __shared__ float sdt[64][8];
    int tid = threadIdx.x;
    int m0 = blockIdx.x*64;
    for (int i = tid; i < 512; i += 256) {
        int ml = i >> 3, r = i & 7;
        sdt[ml][r] = g_dbc[(size_t)(m0 + ml)*40 + r];
    }
    __syncthreads();
    int ml = tid & 63;
    int dl = tid >> 6;   // 0..3
    for (int it = 0; it < 64; it++) {
        int d = it*4 + dl;
        const float* wr = dtw + d*8;
        float x = dtb[d];
#pragma unroll
        for (int r = 0; r < 8; r++) x += wr[r]*sdt[ml][r];
        float sp = (x > 20.f) ? x : log1pf(__expf(x));
        g_deltaT[(size_t)d*MTOT + m0 + ml] = sp;
    }
}

// ---------------------------------------------------------------------------
// 6. scan pass 1: per-chunk partial scan from h=0, record h_end & sum(delta)
// ---------------------------------------------------------------------------
__global__ __launch_bounds__(128) void k_scan1(const float* __restrict__ A_log)
{
    int lane = threadIdx.x & 31;
    int wgid = blockIdx.x*4 + (threadIdx.x >> 5);
    int ch = wgid & 63;
    int dp = (wgid >> 6) & 127;
    int b  = wgid >> 13;
    int dd = lane >> 4, n = lane & 15;
    int d  = dp*2 + dd;

    float A = -__expf(A_log[d*DSTATE + n]);
    int m0 = b*LSEQ + ch*LCHUNK;
    const float* drow = g_deltaT + (size_t)d*MTOT;
    const float* urow = g_uT     + (size_t)d*MTOT;

    float h = 0.f, sumd = 0.f;
#pragma unroll 4
    for (int l = 0; l < LCHUNK; l++) {
        int m = m0 + l;
        float dt = drow[m];
        float uu = urow[m];
        float Bn = g_dbc[(size_t)m*40 + 8 + n];
        h = __expf(dt*A)*h + dt*Bn*uu;
        sumd += dt;
    }
    int bd = b*DINNER + d;
    g_hend[((size_t)bd*NCHUNK + ch)*DSTATE + n] = h;
    if (n == 0) g_sumd[(size_t)bd*NCHUNK + ch] = sumd;
}

// ---------------------------------------------------------------------------
// 7. scan pass 2: serial carry over 64 chunks per (b,d)
// ---------------------------------------------------------------------------
__global__ void k_scan2(const float* __restrict__ A_log)
{
    int gt = blockIdx.x*256 + threadIdx.x;
    int w  = gt >> 5;
    int lane = gt & 31;
    int dd = lane >> 4, n = lane & 15;
    int bd = w*2 + dd;
    int d  = bd & 255;

    float A = -__expf(A_log[d*DSTATE + n]);
    float h = 0.f;
    for (int ch = 0; ch < NCHUNK; ch++) {
        size_t base = ((size_t)bd*NCHUNK + ch)*DSTATE + n;
        g_hin[base] = h;
        float sd = g_sumd[(size_t)bd*NCHUNK + ch];
        h = __expf(sd*A)*h + g_hend[base];
    }
}

// ---------------------------------------------------------------------------
// 8. scan pass 3: rescan with entry state; y=(h.C + u*Dp)*silu(z)
// ---------------------------------------------------------------------------
__global__ __launch_bounds__(128) void k_scan3(const float* __restrict__ A_log,
                                               const float* __restrict__ Dp)
{
    int lane = threadIdx.x & 31;
    int wgid = blockIdx.x*4 + (threadIdx.x >> 5);
    int ch = wgid & 63;
    int dp = (wgid >> 6) & 127;
    int b  = wgid >> 13;
    int dd = lane >> 4, n = lane & 15;
    int d  = dp*2 + dd;
    int bd = b*DINNER + d;

    float A = -__expf(A_log[d*DSTATE + n]);
    float Dd = Dp[d];
    int m0 = b*LSEQ + ch*LCHUNK;
    const float* drow = g_deltaT + (size_t)d*MTOT;
    const float* urow = g_uT     + (size_t)d*MTOT;
    const float* zrow = g_xzT    + (size_t)(DINNER + d)*MTOT;
    float*       yrow = g_yT     + (size_t)d*MTOT;

    float h = g_hin[((size_t)bd*NCHUNK + ch)*DSTATE + n];

    for (int l = 0; l < LCHUNK; l++) {
        int m = m0 + l;
        float dt = drow[m];
        float uu = urow[m];
        float Bn = g_dbc[(size_t)m*40 + 8 + n];
        float Cn = g_dbc[(size_t)m*40 + 24 + n];
        h = __expf(dt*A)*h + dt*Bn*uu;
        float y = h*Cn;
        y += __shfl_xor_sync(0xffffffffu, y, 8, 16);
        y += __shfl_xor_sync(0xffffffffu, y, 4, 16);
        y += __shfl_xor_sync(0xffffffffu, y, 2, 16);
        y += __shfl_xor_sync(0xffffffffu, y, 1, 16);
        if (n == 0) {
            float z = zrow[m];
            yrow[m] = (y + uu*Dd) * silu_f(z);
        }
    }
}

// ---------------------------------------------------------------------------
// 9. LayerNorm over 128 channels + silu ; write channel-major g_lnT
// ---------------------------------------------------------------------------
__global__ __launch_bounds__(256) void k_ln_silu(const float* __restrict__ gamma,
                                                 const float* __restrict__ beta)
{
    __shared__ float sT[128][36];
    int tid = threadIdx.x;
    int wid = tid >> 5, lane = tid & 31;
    int m_base = blockIdx.x*32;

    for (int r = 0; r < 4; r++) {
        int mloc = r*8 + wid;
        int m = m_base + mloc;
        float4 v = *reinterpret_cast<const float4*>(g_ym + (size_t)m*128 + lane*4);
        float s  = v.x + v.y + v.z + v.w;
        float s2 = v.x*v.x + v.y*v.y + v.z*v.z + v.w*v.w;
#pragma unroll
        for (int k = 16; k >= 1; k >>= 1) {
            s  += __shfl_xor_sync(0xffffffffu, s,  k);
            s2 += __shfl_xor_sync(0xffffffffu, s2, k);
        }
        float mean = s * (1.f/128.f);
        float var  = s2 * (1.f/128.f) - mean*mean;
        float rstd = rsqrtf(var + 1e-5f);
        float va[4] = {v.x, v.y, v.z, v.w};
#pragma unroll
        for (int i = 0; i < 4; i++) {
            int c = lane*4 + i;
            float t = (va[i] - mean)*rstd*gamma[c] + beta[c];
            sT[c][mloc] = silu_f(t);
        }
    }
    __syncthreads();

    int mq = tid & 7;
    int c0 = tid >> 3;
    for (int cc = c0; cc < 128; cc += 32) {
        float4 v = *reinterpret_cast<const float4*>(&sT[cc][mq*4]);
        *reinterpret_cast<float4*>(g_lnT + (size_t)cc*MTOT + m_base + mq*4) = v;
    }
}

// ---------------------------------------------------------------------------
extern "C" void kernel_launch(void* const* d_in, const int* in_sizes, int n_in,
                              void* d_out, int out_size)
{
    const float* x        = (const float*)d_in[0];
    const float* skip_x   = (const float*)d_in[1];
    const float* up_w     = (const float*)d_in[2];
    const float* up_b     = (const float*)d_in[3];
    const float* in_proj  = (const float*)d_in[4];
    const float* conv1d_w = (const float*)d_in[5];
    const float* conv1d_b = (const float*)d_in[6];
    const float* x_proj   = (const float*)d_in[7];
    const float* dt_proj_w= (const float*)d_in[8];
    const float* dt_proj_b= (const float*)d_in[9];
    const float* A_log    = (const float*)d_in[10];
    const float* Dp       = (const float*)d_in[11];
    const float* out_proj = (const float*)d_in[12];
    const float* ln_gamma = (const float*)d_in[13];
    const float* ln_beta  = (const float*)d_in[14];
    const float* convout_w= (const float*)d_in[15];
    const float* convout_b= (const float*)d_in[16];
    float* out = (float*)d_out;

    float *p_seqT, *p_xzT, *p_uT, *p_yT, *p_lnT, *p_dbc, *p_ym;
    cudaGetSymbolAddress((void**)&p_seqT, g_seqT);
    cudaGetSymbolAddress((void**)&p_xzT,  g_xzT);
    cudaGetSymbolAddress((void**)&p_uT,   g_uT);
    cudaGetSymbolAddress((void**)&p_yT,   g_yT);
    cudaGetSymbolAddress((void**)&p_lnT,  g_lnT);
    cudaGetSymbolAddress((void**)&p_dbc,  g_dbc);
    cudaGetSymbolAddress((void**)&p_ym,   g_ym);

    // 0-2: build seq (channel-major)
    k_transpose_upw<<<128, 256>>>(up_w);
    k_upsample<<<BATCH*64, 256>>>(x, up_b);
    k_copy_skip<<<(BATCH*64*4096)/256, 256>>>(skip_x);

    // 3: in_proj  (N=512, K=128) -> g_xzT channel-major
    k_sgemm3<<<dim3(MTOT/128, 8), 256>>>(in_proj, p_seqT, p_xzT, nullptr,
                                         512, 128, 0, 0);
    // 4: conv1d + silu -> g_uT
    k_conv1d_silu<<<dim3(MTOT/256, DINNER), 256>>>(conv1d_w, conv1d_b);

    // 5: x_proj (N=40, K=256) -> g_dbc row-major [m][40]
    k_sgemm3<<<dim3(MTOT/128, 1), 256>>>(x_proj, p_uT, p_dbc, nullptr,
                                         40, 256, 1, 40);
    // 6: delta
    k_delta<<<MTOT/64, 256>>>(dt_proj_w, dt_proj_b);

    // 7-9: chunked selective scan
    k_scan1<<<8192, 128>>>(A_log);
    k_scan2<<<64, 256>>>(A_log);
    k_scan3<<<8192, 128>>>(A_log, Dp);

    // 10: out_proj (N=128, K=256) -> g_ym row-major [m][128]
    k_sgemm3<<<dim3(MTOT/128, 2), 256>>>(out_proj, p_yT, p_ym, nullptr,
                                         128, 256, 1, 128);
    // 11: LayerNorm + silu -> g_lnT channel-major
    k_ln_silu<<<MTOT/32, 256>>>(ln_gamma, ln_beta);

    // 12: convout 1x1 (N=64, K=128) -> d_out NCHW + bias
    k_sgemm3<<<dim3(MTOT/128, 1), 256>>>(convout_w, p_lnT, out, convout_b,
                                         64, 128, 2, 0);
}

// round 5
// speedup vs baseline: 1.0240x; 1.0239x over previous
#include <cuda_runtime.h>
#include <math.h>

#define BATCH   4
#define LSEQ    4096
#define MTOT    16384          // BATCH*LSEQ
#define DMODEL  128
#define DINNER  256
#define DSTATE  16
#define NCHUNK  64
#define LCHUNK  64

// ---------------- static scratch (no cudaMalloc anywhere) -------------------
__device__ float g_seqT  [DMODEL  * MTOT];    // [c][m] concat(up,skip)
__device__ float g_xzT   [2*DINNER* MTOT];    // [n][m] rows 0..255 u_raw, 256..511 z
__device__ float g_uT    [DINNER  * MTOT];    // [d][m] conv1d+silu
__device__ float g_deltaT[DINNER  * MTOT];    // [d][m]
__device__ float g_dbc   [MTOT * 40];         // [m][40]  0..7 dt, 8..23 B, 24..39 C
__device__ float g_yT    [DINNER  * MTOT];    // [d][m] scan out * silu(z)
__device__ float g_ym    [MTOT * DMODEL];     // [m][128] out_proj out
__device__ float g_lnT   [DMODEL  * MTOT];    // [c][m] LN+silu out
__device__ float g_hend  [BATCH*DINNER*NCHUNK*DSTATE];
__device__ float g_hin   [BATCH*DINNER*NCHUNK*DSTATE];
__device__ float g_sumd  [BATCH*DINNER*NCHUNK];
__device__ float g_upwT  [256*128];           // [o*4+ij][cin]

__device__ __forceinline__ float silu_f(float x) {
    return x / (1.0f + __expf(-x));
}

// packed f32x2 helpers (sm_100+)
__device__ __forceinline__ unsigned long long pack2(float x) {
    unsigned long long r;
    unsigned int u = __float_as_uint(x);
    asm("mov.b64 %0, {%1, %1};" : "=l"(r) : "r"(u));
    return r;
}
__device__ __forceinline__ void ffma2(unsigned long long &acc,
                                      unsigned long long a,
                                      unsigned long long b) {
    asm("fma.rn.f32x2 %0, %1, %2, %0;" : "+l"(acc) : "l"(a), "l"(b));
}
__device__ __forceinline__ float2 unpk(unsigned long long v) {
    float2 r;
    asm("mov.b64 {%0, %1}, %2;" : "=f"(r.x), "=f"(r.y) : "l"(v));
    return r;
}

// ---------------------------------------------------------------------------
// 0. transpose up_w (128,64,2,2) -> [n=o*4+ij][cin]
// ---------------------------------------------------------------------------
__global__ void k_transpose_upw(const float* __restrict__ upw)
{
    int cin = blockIdx.x;            // 128
    int n   = threadIdx.x;           // 256
    g_upwT[n*128 + cin] = upw[cin*256 + n];
}

// ---------------------------------------------------------------------------
// 1. ConvTranspose2d k=2 s=2 -> channels 0..63 of g_seqT
// ---------------------------------------------------------------------------
__global__ __launch_bounds__(256) void k_upsample(
    const float* __restrict__ x, const float* __restrict__ upb)
{
    __shared__ float xs[16][128];
    int t  = threadIdx.x;
    int b  = blockIdx.x >> 6;
    int p0 = (blockIdx.x & 63) << 4;

    for (int i = t; i < 16*128; i += 256) {
        int pix = i & 15, cin = i >> 4;
        xs[pix][cin] = x[(b*128 + cin)*1024 + p0 + pix];
    }
    __syncthreads();

    int o  = t >> 2;
    int ij = t & 3;
    int ii = ij >> 1, jj = ij & 1;

    float acc[16];
#pragma unroll
    for (int p = 0; p < 16; p++) acc[p] = 0.f;

    const float* wrow = g_upwT + t*128;
    for (int c4 = 0; c4 < 32; c4++) {
        float4 w4 = *reinterpret_cast<const float4*>(wrow + c4*4);
#pragma unroll
        for (int p = 0; p < 16; p++) {
            float4 x4 = *reinterpret_cast<const float4*>(&xs[p][c4*4]);
            acc[p] += x4.x*w4.x + x4.y*w4.y + x4.z*w4.z + x4.w*w4.w;
        }
    }
    float bias = upb[o];
#pragma unroll
    for (int p = 0; p < 16; p++) {
        int hp = (p0 + p) >> 5, wp = (p0 + p) & 31;
        int l  = (2*hp + ii)*64 + 2*wp + jj;
        g_seqT[o*MTOT + b*LSEQ + l] = acc[p] + bias;
    }
}

// ---------------------------------------------------------------------------
// 2. copy skip_x into g_seqT channels 64..127
// ---------------------------------------------------------------------------
__global__ void k_copy_skip(const float* __restrict__ skip)
{
    int idx = blockIdx.x*256 + threadIdx.x;
    int l = idx & 4095;
    int c = (idx >> 12) & 63;
    int b = idx >> 18;
    g_seqT[(64 + c)*MTOT + b*LSEQ + l] = skip[idx];
}

// ---------------------------------------------------------------------------
// 3. SGEMM v4: software-pipelined (register prefetch) FFMA2 GEMM.
//    C[n][m] = sum_k W[n][k]*Bm[k][m]
//    128(m) x 64(n) tile, K-step 16, 256 threads, 8m x 4n microtile.
//    mode 0: channel-major [n][MTOT]
//    mode 1: row-major     [m][ldc]
//    mode 2: NCHW + bias   [(m>>12)*N + n][4096]
// ---------------------------------------------------------------------------
__global__ __launch_bounds__(256) void k_sgemm4(
    const float* __restrict__ W, const float* __restrict__ Bm,
    float* __restrict__ C, const float* __restrict__ bias,
    int N, int K, int mode, int ldc)
{
    __shared__ float Bs[16][128];
    __shared__ unsigned long long Ws2[16][66];

    int tid = threadIdx.x;
    int tx = tid & 15;            // m: tx*4 and 64+tx*4
    int ty = tid >> 4;            // n: ty*4 .. +3
    int m0 = blockIdx.x * 128;
    int n0 = blockIdx.y * 64;

    unsigned long long acc[4][4];
#pragma unroll
    for (int i = 0; i < 4; i++)
#pragma unroll
        for (int p = 0; p < 4; p++) acc[i][p] = 0ULL;

    int lb_k = tid >> 5;          // 0..7 (rows lb_k, lb_k+8)
    int lb_m = (tid & 31) * 4;
    int lw_k = tid & 15;
    int lw_n = tid >> 4;          // 0..15 (+16,+32,+48)

    const float* pB0 = Bm + (size_t)lb_k*MTOT + m0 + lb_m;
    const float* pB1 = Bm + (size_t)(lb_k + 8)*MTOT + m0 + lb_m;

    // prologue prefetch
    float4 pb0 = *reinterpret_cast<const float4*>(pB0);
    float4 pb1 = *reinterpret_cast<const float4*>(pB1);
    float  pw[4];
#pragma unroll
    for (int j = 0; j < 4; j++) {
        int n = n0 + lw_n + j*16;
        pw[j] = (n < N) ? W[(size_t)n*K + lw_k] : 0.f;
    }

    for (int k0 = 0; k0 < K; k0 += 16) {
        // commit staged tile to smem
        *reinterpret_cast<float4*>(&Bs[lb_k][lb_m])     = pb0;
        *reinterpret_cast<float4*>(&Bs[lb_k + 8][lb_m]) = pb1;
#pragma unroll
        for (int j = 0; j < 4; j++)
            Ws2[lw_k][lw_n + j*16] = pack2(pw[j]);
        __syncthreads();

        // prefetch next tile (latency hidden under compute)
        if (k0 + 16 < K) {
            pb0 = *reinterpret_cast<const float4*>(pB0 + (size_t)(k0 + 16)*MTOT);
            pb1 = *reinterpret_cast<const float4*>(pB1 + (size_t)(k0 + 16)*MTOT);
#pragma unroll
            for (int j = 0; j < 4; j++) {
                int n = n0 + lw_n + j*16;
                pw[j] = (n < N) ? W[(size_t)n*K + k0 + 16 + lw_k] : 0.f;
            }
        }

#pragma unroll
        for (int k = 0; k < 16; k++) {
            ulonglong2 b01 = *reinterpret_cast<const ulonglong2*>(&Bs[k][tx*4]);
            ulonglong2 b23 = *reinterpret_cast<const ulonglong2*>(&Bs[k][64 + tx*4]);
            ulonglong2 w01 = *reinterpret_cast<const ulonglong2*>(&Ws2[k][ty*4]);
            ulonglong2 w23 = *reinterpret_cast<const ulonglong2*>(&Ws2[k][ty*4 + 2]);
            unsigned long long bm[4] = {b01.x, b01.y, b23.x, b23.y};
            unsigned long long wn[4] = {w01.x, w01.y, w23.x, w23.y};
#pragma unroll
            for (int i = 0; i < 4; i++)
#pragma unroll
                for (int p = 0; p < 4; p++)
                    ffma2(acc[i][p], bm[p], wn[i]);
        }
        __syncthreads();
    }

    if (mode == 0 || mode == 2) {
#pragma unroll
        for (int i = 0; i < 4; i++) {
            int n = n0 + ty*4 + i;
            if (n >= N) continue;
            float bb = (mode == 2 && bias) ? bias[n] : 0.f;
            float2 p0 = unpk(acc[i][0]), p1 = unpk(acc[i][1]);
            float2 p2 = unpk(acc[i][2]), p3 = unpk(acc[i][3]);
            float4 lo = make_float4(p0.x+bb, p0.y+bb, p1.x+bb, p1.y+bb);
            float4 hi = make_float4(p2.x+bb, p2.y+bb, p3.x+bb, p3.y+bb);
            if (mode == 0) {
                *reinterpret_cast<float4*>(C + (size_t)n*MTOT + m0 + tx*4)      = lo;
                *reinterpret_cast<float4*>(C + (size_t)n*MTOT + m0 + 64 + tx*4) = hi;
            } else {
                int bidx = m0 >> 12;
                int l0   = (m0 & 4095) + tx*4;
                float* base = C + (size_t)bidx*N*4096 + (size_t)n*4096;
                *reinterpret_cast<float4*>(base + l0)      = lo;
                *reinterpret_cast<float4*>(base + l0 + 64) = hi;
            }
        }
    } else {
        bool ok = (n0 + ty*4) < N;
        if (ok) {
#pragma unroll
            for (int g = 0; g < 2; g++) {
#pragma unroll
                for (int q = 0; q < 4; q++) {
                    int m = m0 + g*64 + tx*4 + q;
                    int p = g*2 + (q >> 1);
                    int h = q & 1;
                    float v[4];
#pragma unroll
                    for (int i = 0; i < 4; i++) {
                        float2 f = unpk(acc[i][p]);
                        v[i] = h ? f.y : f.x;
                    }
                    *reinterpret_cast<float4*>(C + (size_t)m*ldc + n0 + ty*4) =
                        make_float4(v[0], v[1], v[2], v[3]);
                }
            }
        }
    }
}

// ---------------------------------------------------------------------------
// 4. depthwise causal conv1d (D_CONV=4) + bias + silu
// ---------------------------------------------------------------------------
__global__ void k_conv1d_silu(const float* __restrict__ cw,
                              const float* __restrict__ cb)
{
    int d = blockIdx.y;
    int m = blockIdx.x*256 + threadIdx.x;
    int l = m & 4095;
    const float* row = g_xzT + (size_t)d*MTOT;
    float w0 = cw[d*4+0], w1 = cw[d*4+1], w2 = cw[d*4+2], w3 = cw[d*4+3];
    float acc = cb[d];
    if (l >= 3) acc += w0*row[m-3];
    if (l >= 2) acc += w1*row[m-2];
    if (l >= 1) acc += w2*row[m-1];
    acc += w3*row[m];
    g_uT[(size_t)d*MTOT + m] = silu_f(acc);
}

// ---------------------------------------------------------------------------
// 5. delta = softplus(dt @ dt_proj_w.T + dt_proj_b) -> g_deltaT [d][m]
// ---------------------------------------------------------------------------
__global__ void k_delta(const float* __restrict__ dtw,
                        const float* __restrict__ dtb)
{
    __shared__ float sdt[64][8];
    int tid = threadIdx.x;
    int m0 = blockIdx.x*64;
    for (int i = tid; i < 512; i += 256) {
        int ml = i >> 3, r = i & 7;
        sdt[ml][r] = g_dbc[(size_t)(m0 + ml)*40 + r];
    }
    __syncthreads();
    int ml = tid & 63;
    int dl = tid >> 6;   // 0..3
    for (int it = 0; it < 64; it++) {
        int d = it*4 + dl;
        const float* wr = dtw + d*8;
        float x = dtb[d];
#pragma unroll
        for (int r = 0; r < 8; r++) x += wr[r]*sdt[ml][r];
        float sp = (x > 20.f) ? x : log1pf(__expf(x));
        g_deltaT[(size_t)d*MTOT + m0 + ml] = sp;
    }
}

// ---------------------------------------------------------------------------
// 6. scan pass 1: per-chunk partial scan from h=0, record h_end & sum(delta)
// ---------------------------------------------------------------------------
__global__ __launch_bounds__(128) void k_scan1(const float* __restrict__ A_log)
{
    int lane = threadIdx.x & 31;
    int wgid = blockIdx.x*4 + (threadIdx.x >> 5);
    int ch = wgid & 63;
    int dp = (wgid >> 6) & 127;
    int b  = wgid >> 13;
    int dd = lane >> 4, n = lane & 15;
    int d  = dp*2 + dd;

    float A = -__expf(A_log[d*DSTATE + n]);
    int m0 = b*LSEQ + ch*LCHUNK;
    const float* drow = g_deltaT + (size_t)d*MTOT;
    const float* urow = g_uT     + (size_t)d*MTOT;
    const float* dbc  = g_dbc;

    float h = 0.f, sumd = 0.f;
#pragma unroll 8
    for (int l = 0; l < LCHUNK; l++) {
        int m = m0 + l;
        float dt = drow[m];
        float uu = urow[m];
        float Bn = dbc[(size_t)m*40 + 8 + n];
        h = __expf(dt*A)*h + dt*Bn*uu;
        sumd += dt;
    }
    int bd = b*DINNER + d;
    g_hend[((size_t)bd*NCHUNK + ch)*DSTATE + n] = h;
    if (n == 0) g_sumd[(size_t)bd*NCHUNK + ch] = sumd;
}

// ---------------------------------------------------------------------------
// 7. scan pass 2: serial carry over 64 chunks per (b,d)
// ---------------------------------------------------------------------------
__global__ void k_scan2(const float* __restrict__ A_log)
{
    int gt = blockIdx.x*256 + threadIdx.x;
    int w  = gt >> 5;
    int lane = gt & 31;
    int dd = lane >> 4, n = lane & 15;
    int bd = w*2 + dd;
    int d  = bd & 255;

    float A = -__expf(A_log[d*DSTATE + n]);
    float h = 0.f;
    for (int ch = 0; ch < NCHUNK; ch++) {
        size_t base = ((size_t)bd*NCHUNK + ch)*DSTATE + n;
        g_hin[base] = h;
        float sd = g_sumd[(size_t)bd*NCHUNK + ch];
        h = __expf(sd*A)*h + g_hend[base];
    }
}

// ---------------------------------------------------------------------------
// 8. scan pass 3: rescan with entry state; y=(h.C + u*Dp)*silu(z)
//    unroll 4 -> successive timesteps' shfl-reduction chains interleave
// ---------------------------------------------------------------------------
__global__ __launch_bounds__(128) void k_scan3(const float* __restrict__ A_log,
                                               const float* __restrict__ Dp)
{
    int lane = threadIdx.x & 31;
    int wgid = blockIdx.x*4 + (threadIdx.x >> 5);
    int ch = wgid & 63;
    int dp = (wgid >> 6) & 127;
    int b  = wgid >> 13;
    int dd = lane >> 4, n = lane & 15;
    int d  = dp*2 + dd;
    int bd = b*DINNER + d;

    float A = -__expf(A_log[d*DSTATE + n]);
    float Dd = Dp[d];
    int m0 = b*LSEQ + ch*LCHUNK;
    const float* drow = g_deltaT + (size_t)d*MTOT;
    const float* urow = g_uT     + (size_t)d*MTOT;
    const float* zrow = g_xzT    + (size_t)(DINNER + d)*MTOT;
    const float* dbc  = g_dbc;
    float*       yrow = g_yT     + (size_t)d*MTOT;

    float h = g_hin[((size_t)bd*NCHUNK + ch)*DSTATE + n];

#pragma unroll 4
    for (int l = 0; l < LCHUNK; l++) {
        int m = m0 + l;
        float dt = drow[m];
        float uu = urow[m];
        float Bn = dbc[(size_t)m*40 + 8 + n];
        float Cn = dbc[(size_t)m*40 + 24 + n];
        h = __expf(dt*A)*h + dt*Bn*uu;
        float y = h*Cn;
        y += __shfl_xor_sync(0xffffffffu, y, 8, 16);
        y += __shfl_xor_sync(0xffffffffu, y, 4, 16);
        y += __shfl_xor_sync(0xffffffffu, y, 2, 16);
        y += __shfl_xor_sync(0xffffffffu, y, 1, 16);
        if (n == 0) {
            float z = zrow[m];
            yrow[m] = (y + uu*Dd) * silu_f(z);
        }
    }
}

// ---------------------------------------------------------------------------
// 9. LayerNorm over 128 channels + silu ; write channel-major g_lnT
// ---------------------------------------------------------------------------
__global__ __launch_bounds__(256) void k_ln_silu(const float* __restrict__ gamma,
                                                 const float* __restrict__ beta)
{
    __shared__ float sT[128][36];
    int tid = threadIdx.x;
    int wid = tid >> 5, lane = tid & 31;
    int m_base = blockIdx.x*32;

    for (int r = 0; r < 4; r++) {
        int mloc = r*8 + wid;
        int m = m_base + mloc;
        float4 v = *reinterpret_cast<const float4*>(g_ym + (size_t)m*128 + lane*4);
        float s  = v.x + v.y + v.z + v.w;
        float s2 = v.x*v.x + v.y*v.y + v.z*v.z + v.w*v.w;
#pragma unroll
        for (int k = 16; k >= 1; k >>= 1) {
            s  += __shfl_xor_sync(0xffffffffu, s,  k);
            s2 += __shfl_xor_sync(0xffffffffu, s2, k);
        }
        float mean = s * (1.f/128.f);
        float var  = s2 * (1.f/128.f) - mean*mean;
        float rstd = rsqrtf(var + 1e-5f);
        float va[4] = {v.x, v.y, v.z, v.w};
#pragma unroll
        for (int i = 0; i < 4; i++) {
            int c = lane*4 + i;
            float t = (va[i] - mean)*rstd*gamma[c] + beta[c];
            sT[c][mloc] = silu_f(t);
        }
    }
    __syncthreads();

    int mq = tid & 7;
    int c0 = tid >> 3;
    for (int cc = c0; cc < 128; cc += 32) {
        float4 v = *reinterpret_cast<const float4*>(&sT[cc][mq*4]);
        *reinterpret_cast<float4*>(g_lnT + (size_t)cc*MTOT + m_base + mq*4) = v;
    }
}

// ---------------------------------------------------------------------------
extern "C" void kernel_launch(void* const* d_in, const int* in_sizes, int n_in,
                              void* d_out, int out_size)
{
    const float* x        = (const float*)d_in[0];
    const float* skip_x   = (const float*)d_in[1];
    const float* up_w     = (const float*)d_in[2];
    const float* up_b     = (const float*)d_in[3];
    const float* in_proj  = (const float*)d_in[4];
    const float* conv1d_w = (const float*)d_in[5];
    const float* conv1d_b = (const float*)d_in[6];
    const float* x_proj   = (const float*)d_in[7];
    const float* dt_proj_w= (const float*)d_in[8];
    const float* dt_proj_b= (const float*)d_in[9];
    const float* A_log    = (const float*)d_in[10];
    const float* Dp       = (const float*)d_in[11];
    const float* out_proj = (const float*)d_in[12];
    const float* ln_gamma = (const float*)d_in[13];
    const float* ln_beta  = (const float*)d_in[14];
    const float* convout_w= (const float*)d_in[15];
    const float* convout_b= (const float*)d_in[16];
    float* out = (float*)d_out;

    float *p_seqT, *p_xzT, *p_uT, *p_yT, *p_lnT, *p_dbc, *p_ym;
    cudaGetSymbolAddress((void**)&p_seqT, g_seqT);
    cudaGetSymbolAddress((void**)&p_xzT,  g_xzT);
    cudaGetSymbolAddress((void**)&p_uT,   g_uT);
    cudaGetSymbolAddress((void**)&p_yT,   g_yT);
    cudaGetSymbolAddress((void**)&p_lnT,  g_lnT);
    cudaGetSymbolAddress((void**)&p_dbc,  g_dbc);
    cudaGetSymbolAddress((void**)&p_ym,   g_ym);

    // 0-2: build seq (channel-major)
    k_transpose_upw<<<128, 256>>>(up_w);
    k_upsample<<<BATCH*64, 256>>>(x, up_b);
    k_copy_skip<<<(BATCH*64*4096)/256, 256>>>(skip_x);

    // 3: in_proj  (N=512, K=128) -> g_xzT channel-major
    k_sgemm4<<<dim3(MTOT/128, 8), 256>>>(in_proj, p_seqT, p_xzT, nullptr,
                                         512, 128, 0, 0);
    // 4: conv1d + silu -> g_uT
    k_conv1d_silu<<<dim3(MTOT/256, DINNER), 256>>>(conv1d_w, conv1d_b);

    // 5: x_proj (N=40, K=256) -> g_dbc row-major [m][40]
    k_sgemm4<<<dim3(MTOT/128, 1), 256>>>(x_proj, p_uT, p_dbc, nullptr,
                                         40, 256, 1, 40);
    // 6: delta
    k_delta<<<MTOT/64, 256>>>(dt_proj_w, dt_proj_b);

    // 7-9: chunked selective scan
    k_scan1<<<8192, 128>>>(A_log);
    k_scan2<<<64, 256>>>(A_log);
    k_scan3<<<8192, 128>>>(A_log, Dp);

    // 10: out_proj (N=128, K=256) -> g_ym row-major [m][128]
    k_sgemm4<<<dim3(MTOT/128, 2), 256>>>(out_proj, p_yT, p_ym, nullptr,
                                         128, 256, 1, 128);
    // 11: LayerNorm + silu -> g_lnT channel-major
    k_ln_silu<<<MTOT/32, 256>>>(ln_gamma, ln_beta);

    // 12: convout 1x1 (N=64, K=128) -> d_out NCHW + bias
    k_sgemm4<<<dim3(MTOT/128, 1), 256>>>(convout_w, p_lnT, out, convout_b,
                                         64, 128, 2, 0);
}

// round 6
// speedup vs baseline: 1.0595x; 1.0347x over previous
#include <cuda_runtime.h>
#include <math.h>

#define BATCH   4
#define LSEQ    4096
#define MTOT    16384          // BATCH*LSEQ
#define DMODEL  128
#define DINNER  256
#define DSTATE  16
#define NCHUNK  64
#define LCHUNK  64

// ---------------- static scratch (no cudaMalloc anywhere) -------------------
__device__ float g_seqT  [DMODEL  * MTOT];    // [c][m] concat(up,skip)
__device__ float g_xzT   [2*DINNER* MTOT];    // [n][m] rows 0..255 u_raw, 256..511 z
__device__ float g_uT    [DINNER  * MTOT];    // [d][m] conv1d+silu
__device__ float g_deltaT[DINNER  * MTOT];    // [d][m]
__device__ float g_dbc   [MTOT * 40];         // [m][40]  0..7 dt, 8..23 B, 24..39 C
__device__ float g_yT    [DINNER  * MTOT];    // [d][m] scan out * silu(z)
__device__ float g_ym    [MTOT * DMODEL];     // [m][128] out_proj out
__device__ float g_lnT   [DMODEL  * MTOT];    // [c][m] LN+silu out
__device__ float g_hend  [BATCH*DINNER*NCHUNK*DSTATE];
__device__ float g_hin   [BATCH*DINNER*NCHUNK*DSTATE];
__device__ float g_sumd  [BATCH*DINNER*NCHUNK];
__device__ float g_upwT  [256*128];           // [o*4+ij][cin]

__device__ __forceinline__ float silu_f(float x) {
    return x / (1.0f + __expf(-x));
}

// ---------------------------------------------------------------------------
// 0. transpose up_w (128,64,2,2) -> [n=o*4+ij][cin]
// ---------------------------------------------------------------------------
__global__ void k_transpose_upw(const float* __restrict__ upw)
{
    int cin = blockIdx.x;            // 128
    int n   = threadIdx.x;           // 256
    g_upwT[n*128 + cin] = upw[cin*256 + n];
}

// ---------------------------------------------------------------------------
// 1. ConvTranspose2d k=2 s=2 -> channels 0..63 of g_seqT
// ---------------------------------------------------------------------------
__global__ __launch_bounds__(256) void k_upsample(
    const float* __restrict__ x, const float* __restrict__ upb)
{
    __shared__ float xs[16][128];
    int t  = threadIdx.x;
    int b  = blockIdx.x >> 6;
    int p0 = (blockIdx.x & 63) << 4;

    for (int i = t; i < 16*128; i += 256) {
        int pix = i & 15, cin = i >> 4;
        xs[pix][cin] = x[(b*128 + cin)*1024 + p0 + pix];
    }
    __syncthreads();

    int o  = t >> 2;
    int ij = t & 3;
    int ii = ij >> 1, jj = ij & 1;

    float acc[16];
#pragma unroll
    for (int p = 0; p < 16; p++) acc[p] = 0.f;

    const float* wrow = g_upwT + t*128;
    for (int c4 = 0; c4 < 32; c4++) {
        float4 w4 = *reinterpret_cast<const float4*>(wrow + c4*4);
#pragma unroll
        for (int p = 0; p < 16; p++) {
            float4 x4 = *reinterpret_cast<const float4*>(&xs[p][c4*4]);
            acc[p] += x4.x*w4.x + x4.y*w4.y + x4.z*w4.z + x4.w*w4.w;
        }
    }
    float bias = upb[o];
#pragma unroll
    for (int p = 0; p < 16; p++) {
        int hp = (p0 + p) >> 5, wp = (p0 + p) & 31;
        int l  = (2*hp + ii)*64 + 2*wp + jj;
        g_seqT[o*MTOT + b*LSEQ + l] = acc[p] + bias;
    }
}

// ---------------------------------------------------------------------------
// 2. copy skip_x into g_seqT channels 64..127
// ---------------------------------------------------------------------------
__global__ void k_copy_skip(const float* __restrict__ skip)
{
    int idx = blockIdx.x*256 + threadIdx.x;
    int l = idx & 4095;
    int c = (idx >> 12) & 63;
    int b = idx >> 18;
    g_seqT[(64 + c)*MTOT + b*LSEQ + l] = skip[idx];
}

// ---------------------------------------------------------------------------
// 3a. SGEMM v5: 128(m) x 128(n) tile, 8x8 scalar microtile, pipelined.
//     Requires N % 128 == 0 for the launched grid.y tiles.
//     mode 0: channel-major [n][MTOT]
//     mode 1: row-major     [m][ldc]
// ---------------------------------------------------------------------------
__global__ __launch_bounds__(256) void k_sgemm5(
    const float* __restrict__ W, const float* __restrict__ Bm,
    float* __restrict__ C, int N, int K, int mode, int ldc)
{
    __shared__ float Bs[16][128];    // 8 KB
    __shared__ float Ws[16][132];    // 8.25 KB (pad 4 -> 2-way max on store)

    int tid = threadIdx.x;
    int tx = tid & 15;               // m: tx*4 and 64+tx*4
    int ty = tid >> 4;               // n: ty*4 and 64+ty*4
    int m0 = blockIdx.x * 128;
    int n0 = blockIdx.y * 128;

    float acc[8][8];                 // [n][m]
#pragma unroll
    for (int i = 0; i < 8; i++)
#pragma unroll
        for (int j = 0; j < 8; j++) acc[i][j] = 0.f;

    int lb_k = tid >> 5;             // rows lb_k, lb_k+8
    int lb_m = (tid & 31) * 4;
    int lw_k = tid & 15;
    int lw_n = tid >> 4;             // +16*j, j=0..7

    const float* pB0 = Bm + (size_t)lb_k*MTOT + m0 + lb_m;
    const float* pB1 = Bm + (size_t)(lb_k + 8)*MTOT + m0 + lb_m;

    // prologue prefetch
    float4 pb0 = *reinterpret_cast<const float4*>(pB0);
    float4 pb1 = *reinterpret_cast<const float4*>(pB1);
    float  pw[8];
#pragma unroll
    for (int j = 0; j < 8; j++)
        pw[j] = W[(size_t)(n0 + lw_n + j*16)*K + lw_k];

    for (int k0 = 0; k0 < K; k0 += 16) {
        *reinterpret_cast<float4*>(&Bs[lb_k][lb_m])     = pb0;
        *reinterpret_cast<float4*>(&Bs[lb_k + 8][lb_m]) = pb1;
#pragma unroll
        for (int j = 0; j < 8; j++)
            Ws[lw_k][lw_n + j*16] = pw[j];
        __syncthreads();

        if (k0 + 16 < K) {
            pb0 = *reinterpret_cast<const float4*>(pB0 + (size_t)(k0 + 16)*MTOT);
            pb1 = *reinterpret_cast<const float4*>(pB1 + (size_t)(k0 + 16)*MTOT);
#pragma unroll
            for (int j = 0; j < 8; j++)
                pw[j] = W[(size_t)(n0 + lw_n + j*16)*K + k0 + 16 + lw_k];
        }

#pragma unroll
        for (int k = 0; k < 16; k++) {
            float4 b0 = *reinterpret_cast<const float4*>(&Bs[k][tx*4]);
            float4 b1 = *reinterpret_cast<const float4*>(&Bs[k][64 + tx*4]);
            float4 w0 = *reinterpret_cast<const float4*>(&Ws[k][ty*4]);
            float4 w1 = *reinterpret_cast<const float4*>(&Ws[k][64 + ty*4]);
            float bm[8] = {b0.x, b0.y, b0.z, b0.w, b1.x, b1.y, b1.z, b1.w};
            float wn[8] = {w0.x, w0.y, w0.z, w0.w, w1.x, w1.y, w1.z, w1.w};
#pragma unroll
            for (int i = 0; i < 8; i++)
#pragma unroll
                for (int j = 0; j < 8; j++)
                    acc[i][j] += wn[i]*bm[j];
        }
        __syncthreads();
    }

    if (mode == 0) {
#pragma unroll
        for (int i = 0; i < 8; i++) {
            int n = n0 + ((i < 4) ? (ty*4 + i) : (64 + ty*4 + i - 4));
            *reinterpret_cast<float4*>(C + (size_t)n*MTOT + m0 + tx*4) =
                make_float4(acc[i][0], acc[i][1], acc[i][2], acc[i][3]);
            *reinterpret_cast<float4*>(C + (size_t)n*MTOT + m0 + 64 + tx*4) =
                make_float4(acc[i][4], acc[i][5], acc[i][6], acc[i][7]);
        }
    } else {
#pragma unroll
        for (int j = 0; j < 8; j++) {
            int m = m0 + ((j < 4) ? (tx*4 + j) : (64 + tx*4 + j - 4));
            *reinterpret_cast<float4*>(C + (size_t)m*ldc + n0 + ty*4) =
                make_float4(acc[0][j], acc[1][j], acc[2][j], acc[3][j]);
            *reinterpret_cast<float4*>(C + (size_t)m*ldc + n0 + 64 + ty*4) =
                make_float4(acc[4][j], acc[5][j], acc[6][j], acc[7][j]);
        }
    }
}

// ---------------------------------------------------------------------------
// 3b. SGEMM v4 (64-n tile) — kept for small-N GEMMs (x_proj N=40, convout N=64)
//     mode 1: row-major [m][ldc] ; mode 2: NCHW + bias
// ---------------------------------------------------------------------------
__global__ __launch_bounds__(256) void k_sgemm4(
    const float* __restrict__ W, const float* __restrict__ Bm,
    float* __restrict__ C, const float* __restrict__ bias,
    int N, int K, int mode, int ldc)
{
    __shared__ float Bs[16][128];
    __shared__ float Ws[16][68];

    int tid = threadIdx.x;
    int tx = tid & 15;
    int ty = tid >> 4;
    int m0 = blockIdx.x * 128;
    int n0 = blockIdx.y * 64;

    float acc[4][8];                 // [n][m]
#pragma unroll
    for (int i = 0; i < 4; i++)
#pragma unroll
        for (int j = 0; j < 8; j++) acc[i][j] = 0.f;

    int lb_k = tid >> 5;
    int lb_m = (tid & 31) * 4;
    int lw_k = tid & 15;
    int lw_n = tid >> 4;

    const float* pB0 = Bm + (size_t)lb_k*MTOT + m0 + lb_m;
    const float* pB1 = Bm + (size_t)(lb_k + 8)*MTOT + m0 + lb_m;

    float4 pb0 = *reinterpret_cast<const float4*>(pB0);
    float4 pb1 = *reinterpret_cast<const float4*>(pB1);
    float  pw[4];
#pragma unroll
    for (int j = 0; j < 4; j++) {
        int n = n0 + lw_n + j*16;
        pw[j] = (n < N) ? W[(size_t)n*K + lw_k] : 0.f;
    }

    for (int k0 = 0; k0 < K; k0 += 16) {
        *reinterpret_cast<float4*>(&Bs[lb_k][lb_m])     = pb0;
        *reinterpret_cast<float4*>(&Bs[lb_k + 8][lb_m]) = pb1;
#pragma unroll
        for (int j = 0; j < 4; j++)
            Ws[lw_k][lw_n + j*16] = pw[j];
        __syncthreads();

        if (k0 + 16 < K) {
            pb0 = *reinterpret_cast<const float4*>(pB0 + (size_t)(k0 + 16)*MTOT);
            pb1 = *reinterpret_cast<const float4*>(pB1 + (size_t)(k0 + 16)*MTOT);
#pragma unroll
            for (int j = 0; j < 4; j++) {
                int n = n0 + lw_n + j*16;
                pw[j] = (n < N) ? W[(size_t)n*K + k0 + 16 + lw_k] : 0.f;
            }
        }

#pragma unroll
        for (int k = 0; k < 16; k++) {
            float4 b0 = *reinterpret_cast<const float4*>(&Bs[k][tx*4]);
            float4 b1 = *reinterpret_cast<const float4*>(&Bs[k][64 + tx*4]);
            float4 w0 = *reinterpret_cast<const float4*>(&Ws[k][ty*4]);
            float bm[8] = {b0.x, b0.y, b0.z, b0.w, b1.x, b1.y, b1.z, b1.w};
            float wn[4] = {w0.x, w0.y, w0.z, w0.w};
#pragma unroll
            for (int i = 0; i < 4; i++)
#pragma unroll
                for (int j = 0; j < 8; j++)
                    acc[i][j] += wn[i]*bm[j];
        }
        __syncthreads();
    }

    if (mode == 2) {
#pragma unroll
        for (int i = 0; i < 4; i++) {
            int n = n0 + ty*4 + i;
            if (n >= N) continue;
            float bb = bias ? bias[n] : 0.f;
            int bidx = m0 >> 12;
            int l0   = (m0 & 4095) + tx*4;
            float* base = C + (size_t)bidx*N*4096 + (size_t)n*4096;
            *reinterpret_cast<float4*>(base + l0) =
                make_float4(acc[i][0]+bb, acc[i][1]+bb, acc[i][2]+bb, acc[i][3]+bb);
            *reinterpret_cast<float4*>(base + l0 + 64) =
                make_float4(acc[i][4]+bb, acc[i][5]+bb, acc[i][6]+bb, acc[i][7]+bb);
        }
    } else {
        // mode 1: row-major [m][ldc]
        bool ok = (n0 + ty*4) < N;
        if (ok) {
#pragma unroll
            for (int j = 0; j < 8; j++) {
                int m = m0 + ((j < 4) ? (tx*4 + j) : (64 + tx*4 + j - 4));
                *reinterpret_cast<float4*>(C + (size_t)m*ldc + n0 + ty*4) =
                    make_float4(acc[0][j], acc[1][j], acc[2][j], acc[3][j]);
            }
        }
    }
}

// ---------------------------------------------------------------------------
// 4. depthwise causal conv1d (D_CONV=4) + bias + silu
// ---------------------------------------------------------------------------
__global__ void k_conv1d_silu(const float* __restrict__ cw,
                              const float* __restrict__ cb)
{
    int d = blockIdx.y;
    int m = blockIdx.x*256 + threadIdx.x;
    int l = m & 4095;
    const float* row = g_xzT + (size_t)d*MTOT;
    float w0 = cw[d*4+0], w1 = cw[d*4+1], w2 = cw[d*4+2], w3 = cw[d*4+3];
    float acc = cb[d];
    if (l >= 3) acc += w0*row[m-3];
    if (l >= 2) acc += w1*row[m-2];
    if (l >= 1) acc += w2*row[m-1];
    acc += w3*row[m];
    g_uT[(size_t)d*MTOT + m] = silu_f(acc);
}

// ---------------------------------------------------------------------------
// 5. delta = softplus(dt @ dt_proj_w.T + dt_proj_b) -> g_deltaT [d][m]
// ---------------------------------------------------------------------------
__global__ void k_delta(const float* __restrict__ dtw,
                        const float* __restrict__ dtb)
{
    __shared__ float sdt[64][8];
    int tid = threadIdx.x;
    int m0 = blockIdx.x*64;
    for (int i = tid; i < 512; i += 256) {
        int ml = i >> 3, r = i & 7;
        sdt[ml][r] = g_dbc[(size_t)(m0 + ml)*40 + r];
    }
    __syncthreads();
    int ml = tid & 63;
    int dl = tid >> 6;   // 0..3
    for (int it = 0; it < 64; it++) {
        int d = it*4 + dl;
        const float* wr = dtw + d*8;
        float x = dtb[d];
#pragma unroll
        for (int r = 0; r < 8; r++) x += wr[r]*sdt[ml][r];
        float sp = (x > 20.f) ? x : log1pf(__expf(x));
        g_deltaT[(size_t)d*MTOT + m0 + ml] = sp;
    }
}

// ---------------------------------------------------------------------------
// 6. scan pass 1: per-chunk partial scan from h=0, record h_end & sum(delta)
// ---------------------------------------------------------------------------
__global__ __launch_bounds__(128) void k_scan1(const float* __restrict__ A_log)
{
    int lane = threadIdx.x & 31;
    int wgid = blockIdx.x*4 + (threadIdx.x >> 5);
    int ch = wgid & 63;
    int dp = (wgid >> 6) & 127;
    int b  = wgid >> 13;
    int dd = lane >> 4, n = lane & 15;
    int d  = dp*2 + dd;

    float A = -__expf(A_log[d*DSTATE + n]);
    int m0 = b*LSEQ + ch*LCHUNK;
    const float* drow = g_deltaT + (size_t)d*MTOT;
    const float* urow = g_uT     + (size_t)d*MTOT;
    const float* dbc  = g_dbc;

    float h = 0.f, sumd = 0.f;
#pragma unroll 8
    for (int l = 0; l < LCHUNK; l++) {
        int m = m0 + l;
        float dt = drow[m];
        float uu = urow[m];
        float Bn = dbc[(size_t)m*40 + 8 + n];
        h = __expf(dt*A)*h + dt*Bn*uu;
        sumd += dt;
    }
    int bd = b*DINNER + d;
    g_hend[((size_t)bd*NCHUNK + ch)*DSTATE + n] = h;
    if (n == 0) g_sumd[(size_t)bd*NCHUNK + ch] = sumd;
}

// ---------------------------------------------------------------------------
// 7. scan pass 2: serial carry over 64 chunks per (b,d)
// ---------------------------------------------------------------------------
__global__ void k_scan2(const float* __restrict__ A_log)
{
    int gt = blockIdx.x*256 + threadIdx.x;
    int w  = gt >> 5;
    int lane = gt & 31;
    int dd = lane >> 4, n = lane & 15;
    int bd = w*2 + dd;
    int d  = bd & 255;

    float A = -__expf(A_log[d*DSTATE + n]);
    float h = 0.f;
    for (int ch = 0; ch < NCHUNK; ch++) {
        size_t base = ((size_t)bd*NCHUNK + ch)*DSTATE + n;
        g_hin[base] = h;
        float sd = g_sumd[(size_t)bd*NCHUNK + ch];
        h = __expf(sd*A)*h + g_hend[base];
    }
}

// ---------------------------------------------------------------------------
// 8. scan pass 3: rescan with entry state; y=(h.C + u*Dp)*silu(z)
// ---------------------------------------------------------------------------
__global__ __launch_bounds__(128) void k_scan3(const float* __restrict__ A_log,
                                               const float* __restrict__ Dp)
{
    int lane = threadIdx.x & 31;
    int wgid = blockIdx.x*4 + (threadIdx.x >> 5);
    int ch = wgid & 63;
    int dp = (wgid >> 6) & 127;
    int b  = wgid >> 13;
    int dd = lane >> 4, n = lane & 15;
    int d  = dp*2 + dd;
    int bd = b*DINNER + d;

    float A = -__expf(A_log[d*DSTATE + n]);
    float Dd = Dp[d];
    int m0 = b*LSEQ + ch*LCHUNK;
    const float* drow = g_deltaT + (size_t)d*MTOT;
    const float* urow = g_uT     + (size_t)d*MTOT;
    const float* zrow = g_xzT    + (size_t)(DINNER + d)*MTOT;
    const float* dbc  = g_dbc;
    float*       yrow = g_yT     + (size_t)d*MTOT;

    float h = g_hin[((size_t)bd*NCHUNK + ch)*DSTATE + n];

#pragma unroll 4
    for (int l = 0; l < LCHUNK; l++) {
        int m = m0 + l;
        float dt = drow[m];
        float uu = urow[m];
        float Bn = dbc[(size_t)m*40 + 8 + n];
        float Cn = dbc[(size_t)m*40 + 24 + n];
        h = __expf(dt*A)*h + dt*Bn*uu;
        float y = h*Cn;
        y += __shfl_xor_sync(0xffffffffu, y, 8, 16);
        y += __shfl_xor_sync(0xffffffffu, y, 4, 16);
        y += __shfl_xor_sync(0xffffffffu, y, 2, 16);
        y += __shfl_xor_sync(0xffffffffu, y, 1, 16);
        if (n == 0) {
            float z = zrow[m];
            yrow[m] = (y + uu*Dd) * silu_f(z);
        }
    }
}

// ---------------------------------------------------------------------------
// 9. LayerNorm over 128 channels + silu ; write channel-major g_lnT
// ---------------------------------------------------------------------------
__global__ __launch_bounds__(256) void k_ln_silu(const float* __restrict__ gamma,
                                                 const float* __restrict__ beta)
{
    __shared__ float sT[128][36];
    int tid = threadIdx.x;
    int wid = tid >> 5, lane = tid & 31;
    int m_base = blockIdx.x*32;

    for (int r = 0; r < 4; r++) {
        int mloc = r*8 + wid;
        int m = m_base + mloc;
        float4 v = *reinterpret_cast<const float4*>(g_ym + (size_t)m*128 + lane*4);
        float s  = v.x + v.y + v.z + v.w;
        float s2 = v.x*v.x + v.y*v.y + v.z*v.z + v.w*v.w;
#pragma unroll
        for (int k = 16; k >= 1; k >>= 1) {
            s  += __shfl_xor_sync(0xffffffffu, s,  k);
            s2 += __shfl_xor_sync(0xffffffffu, s2, k);
        }
        float mean = s * (1.f/128.f);
        float var  = s2 * (1.f/128.f) - mean*mean;
        float rstd = rsqrtf(var + 1e-5f);
        float va[4] = {v.x, v.y, v.z, v.w};
#pragma unroll
        for (int i = 0; i < 4; i++) {
            int c = lane*4 + i;
            float t = (va[i] - mean)*rstd*gamma[c] + beta[c];
            sT[c][mloc] = silu_f(t);
        }
    }
    __syncthreads();

    int mq = tid & 7;
    int c0 = tid >> 3;
    for (int cc = c0; cc < 128; cc += 32) {
        float4 v = *reinterpret_cast<const float4*>(&sT[cc][mq*4]);
        *reinterpret_cast<float4*>(g_lnT + (size_t)cc*MTOT + m_base + mq*4) = v;
    }
}

// ---------------------------------------------------------------------------
extern "C" void kernel_launch(void* const* d_in, const int* in_sizes, int n_in,
                              void* d_out, int out_size)
{
    const float* x        = (const float*)d_in[0];
    const float* skip_x   = (const float*)d_in[1];
    const float* up_w     = (const float*)d_in[2];
    const float* up_b     = (const float*)d_in[3];
    const float* in_proj  = (const float*)d_in[4];
    const float* conv1d_w = (const float*)d_in[5];
    const float* conv1d_b = (const float*)d_in[6];
    const float* x_proj   = (const float*)d_in[7];
    const float* dt_proj_w= (const float*)d_in[8];
    const float* dt_proj_b= (const float*)d_in[9];
    const float* A_log    = (const float*)d_in[10];
    const float* Dp       = (const float*)d_in[11];
    const float* out_proj = (const float*)d_in[12];
    const float* ln_gamma = (const float*)d_in[13];
    const float* ln_beta  = (const float*)d_in[14];
    const float* convout_w= (const float*)d_in[15];
    const float* convout_b= (const float*)d_in[16];
    float* out = (float*)d_out;

    float *p_seqT, *p_xzT, *p_uT, *p_yT, *p_lnT, *p_dbc, *p_ym;
    cudaGetSymbolAddress((void**)&p_seqT, g_seqT);
    cudaGetSymbolAddress((void**)&p_xzT,  g_xzT);
    cudaGetSymbolAddress((void**)&p_uT,   g_uT);
    cudaGetSymbolAddress((void**)&p_yT,   g_yT);
    cudaGetSymbolAddress((void**)&p_lnT,  g_lnT);
    cudaGetSymbolAddress((void**)&p_dbc,  g_dbc);
    cudaGetSymbolAddress((void**)&p_ym,   g_ym);

    // 0-2: build seq (channel-major)
    k_transpose_upw<<<128, 256>>>(up_w);
    k_upsample<<<BATCH*64, 256>>>(x, up_b);
    k_copy_skip<<<(BATCH*64*4096)/256, 256>>>(skip_x);

    // 3: in_proj  (N=512, K=128) -> g_xzT channel-major [v5]
    k_sgemm5<<<dim3(MTOT/128, 4), 256>>>(in_proj, p_seqT, p_xzT, 512, 128, 0, 0);

    // 4: conv1d + silu -> g_uT
    k_conv1d_silu<<<dim3(MTOT/256, DINNER), 256>>>(conv1d_w, conv1d_b);

    // 5: x_proj (N=40, K=256) -> g_dbc row-major [m][40]  [v4]
    k_sgemm4<<<dim3(MTOT/128, 1), 256>>>(x_proj, p_uT, p_dbc, nullptr,
                                         40, 256, 1, 40);
    // 6: delta
    k_delta<<<MTOT/64, 256>>>(dt_proj_w, dt_proj_b);

    // 7-9: chunked selective scan
    k_scan1<<<8192, 128>>>(A_log);
    k_scan2<<<64, 256>>>(A_log);
    k_scan3<<<8192, 128>>>(A_log, Dp);

    // 10: out_proj (N=128, K=256) -> g_ym row-major [m][128]  [v5]
    k_sgemm5<<<dim3(MTOT/128, 1), 256>>>(out_proj, p_yT, p_ym, 128, 256, 1, 128);

    // 11: LayerNorm + silu -> g_lnT channel-major
    k_ln_silu<<<MTOT/32, 256>>>(ln_gamma, ln_beta);

    // 12: convout 1x1 (N=64, K=128) -> d_out NCHW + bias  [v4]
    k_sgemm4<<<dim3(MTOT/128, 1), 256>>>(convout_w, p_lnT, out, convout_b,
                                         64, 128, 2, 0);
}

// round 8
// speedup vs baseline: 1.0806x; 1.0199x over previous
#include <cuda_runtime.h>
#include <stdint.h>
#include <math.h>

#define BATCH   4
#define LSEQ    4096
#define MTOT    16384          // BATCH*LSEQ
#define DMODEL  128
#define DINNER  256
#define DSTATE  16
#define NCHUNK  64
#define LCHUNK  64

// ---------------- static scratch (no cudaMalloc anywhere) -------------------
__device__ float g_seqT  [DMODEL  * MTOT];    // [c][m] concat(up,skip)
__device__ float g_xzT   [2*DINNER* MTOT];    // [n][m] rows 0..255 u_raw, 256..511 z
__device__ float g_uT    [DINNER  * MTOT];    // [d][m] conv1d+silu
__device__ float g_deltaT[DINNER  * MTOT];    // [d][m]
__device__ float g_dbc   [MTOT * 40];         // [m][40]  0..7 dt, 8..23 B, 24..39 C
__device__ float g_yT    [DINNER  * MTOT];    // [d][m] scan out * silu(z)
__device__ float g_ym    [MTOT * DMODEL];     // [m][128] out_proj out
__device__ float g_lnT   [DMODEL  * MTOT];    // [c][m] LN+silu out
__device__ float g_hend  [BATCH*DINNER*NCHUNK*DSTATE];
__device__ float g_hin   [BATCH*DINNER*NCHUNK*DSTATE];
__device__ float g_sumd  [BATCH*DINNER*NCHUNK];
__device__ float g_upwT  [256*128];           // [o*4+ij][cin]

__device__ __forceinline__ float silu_f(float x) {
    return x / (1.0f + __expf(-x));
}

__device__ __forceinline__ void cp_async16(unsigned int s, const void* g) {
    asm volatile("cp.async.cg.shared.global [%0], [%1], 16;" :: "r"(s), "l"(g));
}
__device__ __forceinline__ void cp_async4(unsigned int s, const void* g) {
    asm volatile("cp.async.ca.shared.global [%0], [%1], 4;" :: "r"(s), "l"(g));
}
__device__ __forceinline__ void cp_commit() {
    asm volatile("cp.async.commit_group;" ::: "memory");
}
__device__ __forceinline__ void cp_wait0() {
    asm volatile("cp.async.wait_group 0;" ::: "memory");
}

// ---------------------------------------------------------------------------
// 0. transpose up_w (128,64,2,2) -> [n=o*4+ij][cin]
// ---------------------------------------------------------------------------
__global__ void k_transpose_upw(const float* __restrict__ upw)
{
    int cin = blockIdx.x;            // 128
    int n   = threadIdx.x;           // 256
    g_upwT[n*128 + cin] = upw[cin*256 + n];
}

// ---------------------------------------------------------------------------
// 1. ConvTranspose2d k=2 s=2 -> channels 0..63 of g_seqT
// ---------------------------------------------------------------------------
__global__ __launch_bounds__(256) void k_upsample(
    const float* __restrict__ x, const float* __restrict__ upb)
{
    __shared__ float xs[16][128];
    int t  = threadIdx.x;
    int b  = blockIdx.x >> 6;
    int p0 = (blockIdx.x & 63) << 4;

    for (int i = t; i < 16*128; i += 256) {
        int pix = i & 15, cin = i >> 4;
        xs[pix][cin] = x[(b*128 + cin)*1024 + p0 + pix];
    }
    __syncthreads();

    int o  = t >> 2;
    int ij = t & 3;
    int ii = ij >> 1, jj = ij & 1;

    float acc[16];
#pragma unroll
    for (int p = 0; p < 16; p++) acc[p] = 0.f;

    const float* wrow = g_upwT + t*128;
    for (int c4 = 0; c4 < 32; c4++) {
        float4 w4 = *reinterpret_cast<const float4*>(wrow + c4*4);
#pragma unroll
        for (int p = 0; p < 16; p++) {
            float4 x4 = *reinterpret_cast<const float4*>(&xs[p][c4*4]);
            acc[p] += x4.x*w4.x + x4.y*w4.y + x4.z*w4.z + x4.w*w4.w;
        }
    }
    float bias = upb[o];
#pragma unroll
    for (int p = 0; p < 16; p++) {
        int hp = (p0 + p) >> 5, wp = (p0 + p) & 31;
        int l  = (2*hp + ii)*64 + 2*wp + jj;
        g_seqT[o*MTOT + b*LSEQ + l] = acc[p] + bias;
    }
}

// ---------------------------------------------------------------------------
// 2. copy skip_x into g_seqT channels 64..127
// ---------------------------------------------------------------------------
__global__ void k_copy_skip(const float* __restrict__ skip)
{
    int idx = blockIdx.x*256 + threadIdx.x;
    int l = idx & 4095;
    int c = (idx >> 12) & 63;
    int b = idx >> 18;
    g_seqT[(64 + c)*MTOT + b*LSEQ + l] = skip[idx];
}

// ---------------------------------------------------------------------------
// 3a. SGEMM v6: 128x128 tile, 8x8 microtile, cp.async double-buffered smem,
//     2 CTAs/SM. Requires N % 128 == 0.
//     mode 0: channel-major [n][MTOT] ; mode 1: row-major [m][ldc]
// ---------------------------------------------------------------------------
__global__ __launch_bounds__(256, 2) void k_sgemm6(
    const float* __restrict__ W, const float* __restrict__ Bm,
    float* __restrict__ C, int N, int K, int mode, int ldc)
{
    __shared__ float Bs[2][16][128];     // 16 KB
    __shared__ float Ws[2][16][132];     // 16.5 KB

    int tid = threadIdx.x;
    int tx = tid & 15;               // m: tx*4 and 64+tx*4
    int ty = tid >> 4;               // n: ty*4 and 64+ty*4
    int m0 = blockIdx.x * 128;
    int n0 = blockIdx.y * 128;

    float acc[8][8];                 // [n][m]
#pragma unroll
    for (int i = 0; i < 8; i++)
#pragma unroll
        for (int j = 0; j < 8; j++) acc[i][j] = 0.f;

    int lb_k = tid >> 5;             // rows lb_k, lb_k+8
    int lb_m = (tid & 31) * 4;
    int lw_k = tid & 15;
    int lw_n = tid >> 4;             // +16*j, j=0..7

    unsigned int sB0 = (unsigned int)__cvta_generic_to_shared(&Bs[0][lb_k][lb_m]);
    unsigned int sB1 = (unsigned int)__cvta_generic_to_shared(&Bs[0][lb_k + 8][lb_m]);
    unsigned int sW  = (unsigned int)__cvta_generic_to_shared(&Ws[0][lw_k][lw_n]);
    const unsigned int bufB = 16*128*4;      // bytes between Bs buffers
    const unsigned int bufW = 16*132*4;

    const float* gB0 = Bm + (size_t)lb_k*MTOT + m0 + lb_m;
    const float* gB1 = Bm + (size_t)(lb_k + 8)*MTOT + m0 + lb_m;
    const float* gW  = W + (size_t)n0*K + lw_k;

    // issue tile k0 into buffer buf
    auto issue = [&](int buf, int k0) {
        cp_async16(sB0 + buf*bufB, gB0 + (size_t)k0*MTOT);
        cp_async16(sB1 + buf*bufB, gB1 + (size_t)k0*MTOT);
#pragma unroll
        for (int j = 0; j < 8; j++)
            cp_async4(sW + buf*bufW + j*16*4,
                      gW + (size_t)(lw_n + j*16)*K + k0);
        cp_commit();
    };

    issue(0, 0);
    cp_wait0();
    __syncthreads();

    int p = 0;
    for (int k0 = 0; k0 < K; k0 += 16) {
        if (k0 + 16 < K) issue(p ^ 1, k0 + 16);

#pragma unroll
        for (int k = 0; k < 16; k++) {
            float4 b0 = *reinterpret_cast<const float4*>(&Bs[p][k][tx*4]);
            float4 b1 = *reinterpret_cast<const float4*>(&Bs[p][k][64 + tx*4]);
            float4 w0 = *reinterpret_cast<const float4*>(&Ws[p][k][ty*4]);
            float4 w1 = *reinterpret_cast<const float4*>(&Ws[p][k][64 + ty*4]);
            float bm[8] = {b0.x, b0.y, b0.z, b0.w, b1.x, b1.y, b1.z, b1.w};
            float wn[8] = {w0.x, w0.y, w0.z, w0.w, w1.x, w1.y, w1.z, w1.w};
#pragma unroll
            for (int i = 0; i < 8; i++)
#pragma unroll
                for (int j = 0; j < 8; j++)
                    acc[i][j] += wn[i]*bm[j];
        }
        cp_wait0();
        __syncthreads();
        p ^= 1;
    }

    if (mode == 0) {
#pragma unroll
        for (int i = 0; i < 8; i++) {
            int n = n0 + ((i < 4) ? (ty*4 + i) : (64 + ty*4 + i - 4));
            *reinterpret_cast<float4*>(C + (size_t)n*MTOT + m0 + tx*4) =
                make_float4(acc[i][0], acc[i][1], acc[i][2], acc[i][3]);
            *reinterpret_cast<float4*>(C + (size_t)n*MTOT + m0 + 64 + tx*4) =
                make_float4(acc[i][4], acc[i][5], acc[i][6], acc[i][7]);
        }
    } else {
#pragma unroll
        for (int j = 0; j < 8; j++) {
            int m = m0 + ((j < 4) ? (tx*4 + j) : (64 + tx*4 + j - 4));
            *reinterpret_cast<float4*>(C + (size_t)m*ldc + n0 + ty*4) =
                make_float4(acc[0][j], acc[1][j], acc[2][j], acc[3][j]);
            *reinterpret_cast<float4*>(C + (size_t)m*ldc + n0 + 64 + ty*4) =
                make_float4(acc[4][j], acc[5][j], acc[6][j], acc[7][j]);
        }
    }
}

// ---------------------------------------------------------------------------
// 3b. SGEMM v4 (64-n tile) — small-N GEMMs (x_proj N=40, convout N=64)
//     mode 1: row-major [m][ldc] ; mode 2: NCHW + bias
// ---------------------------------------------------------------------------
__global__ __launch_bounds__(256) void k_sgemm4(
    const float* __restrict__ W, const float* __restrict__ Bm,
    float* __restrict__ C, const float* __restrict__ bias,
    int N, int K, int mode, int ldc)
{
    __shared__ float Bs[16][128];
    __shared__ float Ws[16][68];

    int tid = threadIdx.x;
    int tx = tid & 15;
    int ty = tid >> 4;
    int m0 = blockIdx.x * 128;
    int n0 = blockIdx.y * 64;

    float acc[4][8];                 // [n][m]
#pragma unroll
    for (int i = 0; i < 4; i++)
#pragma unroll
        for (int j = 0; j < 8; j++) acc[i][j] = 0.f;

    int lb_k = tid >> 5;
    int lb_m = (tid & 31) * 4;
    int lw_k = tid & 15;
    int lw_n = tid >> 4;

    const float* pB0 = Bm + (size_t)lb_k*MTOT + m0 + lb_m;
    const float* pB1 = Bm + (size_t)(lb_k + 8)*MTOT + m0 + lb_m;

    float4 pb0 = *reinterpret_cast<const float4*>(pB0);
    float4 pb1 = *reinterpret_cast<const float4*>(pB1);
    float  pw[4];
#pragma unroll
    for (int j = 0; j < 4; j++) {
        int n = n0 + lw_n + j*16;
        pw[j] = (n < N) ? W[(size_t)n*K + lw_k] : 0.f;
    }

    for (int k0 = 0; k0 < K; k0 += 16) {
        *reinterpret_cast<float4*>(&Bs[lb_k][lb_m])     = pb0;
        *reinterpret_cast<float4*>(&Bs[lb_k + 8][lb_m]) = pb1;
#pragma unroll
        for (int j = 0; j < 4; j++)
            Ws[lw_k][lw_n + j*16] = pw[j];
        __syncthreads();

        if (k0 + 16 < K) {
            pb0 = *reinterpret_cast<const float4*>(pB0 + (size_t)(k0 + 16)*MTOT);
            pb1 = *reinterpret_cast<const float4*>(pB1 + (size_t)(k0 + 16)*MTOT);
#pragma unroll
            for (int j = 0; j < 4; j++) {
                int n = n0 + lw_n + j*16;
                pw[j] = (n < N) ? W[(size_t)n*K + k0 + 16 + lw_k] : 0.f;
            }
        }

#pragma unroll
        for (int k = 0; k < 16; k++) {
            float4 b0 = *reinterpret_cast<const float4*>(&Bs[k][tx*4]);
            float4 b1 = *reinterpret_cast<const float4*>(&Bs[k][64 + tx*4]);
            float4 w0 = *reinterpret_cast<const float4*>(&Ws[k][ty*4]);
            float bm[8] = {b0.x, b0.y, b0.z, b0.w, b1.x, b1.y, b1.z, b1.w};
            float wn[4] = {w0.x, w0.y, w0.z, w0.w};
#pragma unroll
            for (int i = 0; i < 4; i++)
#pragma unroll
                for (int j = 0; j < 8; j++)
                    acc[i][j] += wn[i]*bm[j];
        }
        __syncthreads();
    }

    if (mode == 2) {
#pragma unroll
        for (int i = 0; i < 4; i++) {
            int n = n0 + ty*4 + i;
            if (n >= N) continue;
            float bb = bias ? bias[n] : 0.f;
            int bidx = m0 >> 12;
            int l0   = (m0 & 4095) + tx*4;
            float* base = C + (size_t)bidx*N*4096 + (size_t)n*4096;
            *reinterpret_cast<float4*>(base + l0) =
                make_float4(acc[i][0]+bb, acc[i][1]+bb, acc[i][2]+bb, acc[i][3]+bb);
            *reinterpret_cast<float4*>(base + l0 + 64) =
                make_float4(acc[i][4]+bb, acc[i][5]+bb, acc[i][6]+bb, acc[i][7]+bb);
        }
    } else {
        bool ok = (n0 + ty*4) < N;
        if (ok) {
#pragma unroll
            for (int j = 0; j < 8; j++) {
                int m = m0 + ((j < 4) ? (tx*4 + j) : (64 + tx*4 + j - 4));
                *reinterpret_cast<float4*>(C + (size_t)m*ldc + n0 + ty*4) =
                    make_float4(acc[0][j], acc[1][j], acc[2][j], acc[3][j]);
            }
        }
    }
}

// ---------------------------------------------------------------------------
// 4. depthwise causal conv1d (D_CONV=4) + bias + silu
// ---------------------------------------------------------------------------
__global__ void k_conv1d_silu(const float* __restrict__ cw,
                              const float* __restrict__ cb)
{
    int d = blockIdx.y;
    int m = blockIdx.x*256 + threadIdx.x;
    int l = m & 4095;
    const float* row = g_xzT + (size_t)d*MTOT;
    float w0 = cw[d*4+0], w1 = cw[d*4+1], w2 = cw[d*4+2], w3 = cw[d*4+3];
    float acc = cb[d];
    if (l >= 3) acc += w0*row[m-3];
    if (l >= 2) acc += w1*row[m-2];
    if (l >= 1) acc += w2*row[m-1];
    acc += w3*row[m];
    g_uT[(size_t)d*MTOT + m] = silu_f(acc);
}

// ---------------------------------------------------------------------------
// 5. delta = softplus(dt @ dt_proj_w.T + dt_proj_b) -> g_deltaT [d][m]
// ---------------------------------------------------------------------------
__global__ void k_delta(const float* __restrict__ dtw,
                        const float* __restrict__ dtb)
{
    __shared__ float sdt[64][8];
    int tid = threadIdx.x;
    int m0 = blockIdx.x*64;
    for (int i = tid; i < 512; i += 256) {
        int ml = i >> 3, r = i & 7;
        sdt[ml][r] = g_dbc[(size_t)(m0 + ml)*40 + r];
    }
    __syncthreads();
    int ml = tid & 63;
    int dl = tid >> 6;   // 0..3
    for (int it = 0; it < 64; it++) {
        int d = it*4 + dl;
        const float* wr = dtw + d*8;
        float x = dtb[d];
#pragma unroll
        for (int r = 0; r < 8; r++) x += wr[r]*sdt[ml][r];
        float sp = (x > 20.f) ? x : log1pf(__expf(x));
        g_deltaT[(size_t)d*MTOT + m0 + ml] = sp;
    }
}

// ---------------------------------------------------------------------------
// 6. scan pass 1: per-chunk partial scan from h=0, record h_end & sum(delta)
// ---------------------------------------------------------------------------
__global__ __launch_bounds__(128) void k_scan1(const float* __restrict__ A_log)
{
    int lane = threadIdx.x & 31;
    int wgid = blockIdx.x*4 + (threadIdx.x >> 5);
    int ch = wgid & 63;
    int dp = (wgid >> 6) & 127;
    int b  = wgid >> 13;
    int dd = lane >> 4, n = lane & 15;
    int d  = dp*2 + dd;

    float A = -__expf(A_log[d*DSTATE + n]);
    int m0 = b*LSEQ + ch*LCHUNK;
    const float* drow = g_deltaT + (size_t)d*MTOT;
    const float* urow = g_uT     + (size_t)d*MTOT;
    const float* dbc  = g_dbc;

    float h = 0.f, sumd = 0.f;
#pragma unroll 8
    for (int l = 0; l < LCHUNK; l++) {
        int m = m0 + l;
        float dt = drow[m];
        float uu = urow[m];
        float Bn = dbc[(size_t)m*40 + 8 + n];
        h = __expf(dt*A)*h + dt*Bn*uu;
        sumd += dt;
    }
    int bd = b*DINNER + d;
    g_hend[((size_t)bd*NCHUNK + ch)*DSTATE + n] = h;
    if (n == 0) g_sumd[(size_t)bd*NCHUNK + ch] = sumd;
}

// ---------------------------------------------------------------------------
// 7. scan pass 2: serial carry over 64 chunks per (b,d)
// ---------------------------------------------------------------------------
__global__ void k_scan2(const float* __restrict__ A_log)
{
    int gt = blockIdx.x*256 + threadIdx.x;
    int w  = gt >> 5;
    int lane = gt & 31;
    int dd = lane >> 4, n = lane & 15;
    int bd = w*2 + dd;
    int d  = bd & 255;

    float A = -__expf(A_log[d*DSTATE + n]);
    float h = 0.f;
    for (int ch = 0; ch < NCHUNK; ch++) {
        size_t base = ((size_t)bd*NCHUNK + ch)*DSTATE + n;
        g_hin[base] = h;
        float sd = g_sumd[(size_t)bd*NCHUNK + ch];
        h = __expf(sd*A)*h + g_hend[base];
    }
}

// ---------------------------------------------------------------------------
// 8. scan pass 3: rescan with entry state; y=(h.C + u*Dp)*silu(z)
// ---------------------------------------------------------------------------
__global__ __launch_bounds__(128) void k_scan3(const float* __restrict__ A_log,
                                               const float* __restrict__ Dp)
{
    int lane = threadIdx.x & 31;
    int wgid = blockIdx.x*4 + (threadIdx.x >> 5);
    int ch = wgid & 63;
    int dp = (wgid >> 6) & 127;
    int b  = wgid >> 13;
    int dd = lane >> 4, n = lane & 15;
    int d  = dp*2 + dd;
    int bd = b*DINNER + d;

    float A = -__expf(A_log[d*DSTATE + n]);
    float Dd = Dp[d];
    int m0 = b*LSEQ + ch*LCHUNK;
    const float* drow = g_deltaT + (size_t)d*MTOT;
    const float* urow = g_uT     + (size_t)d*MTOT;
    const float* zrow = g_xzT    + (size_t)(DINNER + d)*MTOT;
    const float* dbc  = g_dbc;
    float*       yrow = g_yT     + (size_t)d*MTOT;

    float h = g_hin[((size_t)bd*NCHUNK + ch)*DSTATE + n];

#pragma unroll 4
    for (int l = 0; l < LCHUNK; l++) {
        int m = m0 + l;
        float dt = drow[m];
        float uu = urow[m];
        float Bn = dbc[(size_t)m*40 + 8 + n];
        float Cn = dbc[(size_t)m*40 + 24 + n];
        h = __expf(dt*A)*h + dt*Bn*uu;
        float y = h*Cn;
        y += __shfl_xor_sync(0xffffffffu, y, 8, 16);
        y += __shfl_xor_sync(0xffffffffu, y, 4, 16);
        y += __shfl_xor_sync(0xffffffffu, y, 2, 16);
        y += __shfl_xor_sync(0xffffffffu, y, 1, 16);
        if (n == 0) {
            float z = zrow[m];
            yrow[m] = (y + uu*Dd) * silu_f(z);
        }
    }
}

// ---------------------------------------------------------------------------
// 9. LayerNorm over 128 channels + silu ; write channel-major g_lnT
// ---------------------------------------------------------------------------
__global__ __launch_bounds__(256) void k_ln_silu(const float* __restrict__ gamma,
                                                 const float* __restrict__ beta)
{
    __shared__ float sT[128][36];
    int tid = threadIdx.x;
    int wid = tid >> 5, lane = tid & 31;
    int m_base = blockIdx.x*32;

    for (int r = 0; r < 4; r++) {
        int mloc = r*8 + wid;
        int m = m_base + mloc;
        float4 v = *reinterpret_cast<const float4*>(g_ym + (size_t)m*128 + lane*4);
        float s  = v.x + v.y + v.z + v.w;
        float s2 = v.x*v.x + v.y*v.y + v.z*v.z + v.w*v.w;
#pragma unroll
        for (int k = 16; k >= 1; k >>= 1) {
            s  += __shfl_xor_sync(0xffffffffu, s,  k);
            s2 += __shfl_xor_sync(0xffffffffu, s2, k);
        }
        float mean = s * (1.f/128.f);
        float var  = s2 * (1.f/128.f) - mean*mean;
        float rstd = rsqrtf(var + 1e-5f);
        float va[4] = {v.x, v.y, v.z, v.w};
#pragma unroll
        for (int i = 0; i < 4; i++) {
            int c = lane*4 + i;
            float t = (va[i] - mean)*rstd*gamma[c] + beta[c];
            sT[c][mloc] = silu_f(t);
        }
    }
    __syncthreads();

    int mq = tid & 7;
    int c0 = tid >> 3;
    for (int cc = c0; cc < 128; cc += 32) {
        float4 v = *reinterpret_cast<const float4*>(&sT[cc][mq*4]);
        *reinterpret_cast<float4*>(g_lnT + (size_t)cc*MTOT + m_base + mq*4) = v;
    }
}

// ---------------------------------------------------------------------------
extern "C" void kernel_launch(void* const* d_in, const int* in_sizes, int n_in,
                              void* d_out, int out_size)
{
    const float* x        = (const float*)d_in[0];
    const float* skip_x   = (const float*)d_in[1];
    const float* up_w     = (const float*)d_in[2];
    const float* up_b     = (const float*)d_in[3];
    const float* in_proj  = (const float*)d_in[4];
    const float* conv1d_w = (const float*)d_in[5];
    const float* conv1d_b = (const float*)d_in[6];
    const float* x_proj   = (const float*)d_in[7];
    const float* dt_proj_w= (const float*)d_in[8];
    const float* dt_proj_b= (const float*)d_in[9];
    const float* A_log    = (const float*)d_in[10];
    const float* Dp       = (const float*)d_in[11];
    const float* out_proj = (const float*)d_in[12];
    const float* ln_gamma = (const float*)d_in[13];
    const float* ln_beta  = (const float*)d_in[14];
    const float* convout_w= (const float*)d_in[15];
    const float* convout_b= (const float*)d_in[16];
    float* out = (float*)d_out;

    float *p_seqT, *p_xzT, *p_uT, *p_yT, *p_lnT, *p_dbc, *p_ym;
    cudaGetSymbolAddress((void**)&p_seqT, g_seqT);
    cudaGetSymbolAddress((void**)&p_xzT,  g_xzT);
    cudaGetSymbolAddress((void**)&p_uT,   g_uT);
    cudaGetSymbolAddress((void**)&p_yT,   g_yT);
    cudaGetSymbolAddress((void**)&p_lnT,  g_lnT);
    cudaGetSymbolAddress((void**)&p_dbc,  g_dbc);
    cudaGetSymbolAddress((void**)&p_ym,   g_ym);

    // 0-2: build seq (channel-major)
    k_transpose_upw<<<128, 256>>>(up_w);
    k_upsample<<<BATCH*64, 256>>>(x, up_b);
    k_copy_skip<<<(BATCH*64*4096)/256, 256>>>(skip_x);

    // 3: in_proj  (N=512, K=128) -> g_xzT channel-major [v6]
    k_sgemm6<<<dim3(MTOT/128, 4), 256>>>(in_proj, p_seqT, p_xzT, 512, 128, 0, 0);

    // 4: conv1d + silu -> g_uT
    k_conv1d_silu<<<dim3(MTOT/256, DINNER), 256>>>(conv1d_w, conv1d_b);

    // 5: x_proj (N=40, K=256) -> g_dbc row-major [m][40]  [v4]
    k_sgemm4<<<dim3(MTOT/128, 1), 256>>>(x_proj, p_uT, p_dbc, nullptr,
                                         40, 256, 1, 40);
    // 6: delta
    k_delta<<<MTOT/64, 256>>>(dt_proj_w, dt_proj_b);

    // 7-9: chunked selective scan
    k_scan1<<<8192, 128>>>(A_log);
    k_scan2<<<64, 256>>>(A_log);
    k_scan3<<<8192, 128>>>(A_log, Dp);

    // 10: out_proj (N=128, K=256) -> g_ym row-major [m][128]  [v6]
    k_sgemm6<<<dim3(MTOT/128, 1), 256>>>(out_proj, p_yT, p_ym, 128, 256, 1, 128);

    // 11: LayerNorm + silu -> g_lnT channel-major
    k_ln_silu<<<MTOT/32, 256>>>(ln_gamma, ln_beta);

    // 12: convout 1x1 (N=64, K=128) -> d_out NCHW + bias  [v4]
    k_sgemm4<<<dim3(MTOT/128, 1), 256>>>(convout_w, p_lnT, out, convout_b,
                                         64, 128, 2, 0);
}

// round 9
// speedup vs baseline: 1.1693x; 1.0821x over previous
#include <cuda_runtime.h>
#include <stdint.h>
#include <math.h>

#define BATCH   4
#define LSEQ    4096
#define MTOT    16384          // BATCH*LSEQ
#define DMODEL  128
#define DINNER  256
#define DSTATE  16
#define NCHUNK  64
#define LCHUNK  64

// ---------------- static scratch (no cudaMalloc anywhere) -------------------
__device__ float g_seqT  [DMODEL  * MTOT];    // [c][m] concat(up,skip) (tf32-rounded)
__device__ float g_xzT   [2*DINNER* MTOT];    // [n][m] rows 0..255 u_raw, 256..511 z
__device__ float g_uT    [DINNER  * MTOT];    // [d][m] conv1d+silu
__device__ float g_deltaT[DINNER  * MTOT];    // [d][m]
__device__ float g_dbc   [MTOT * 40];         // [m][40]  0..7 dt, 8..23 B, 24..39 C
__device__ float g_yT    [DINNER  * MTOT];    // [d][m] scan out * silu(z)
__device__ float g_ym    [MTOT * DMODEL];     // [m][128] out_proj out
__device__ float g_lnT   [DMODEL  * MTOT];    // [c][m] LN+silu out
__device__ float g_hend  [BATCH*DINNER*NCHUNK*DSTATE];
__device__ float g_hin   [BATCH*DINNER*NCHUNK*DSTATE];
__device__ float g_sumd  [BATCH*DINNER*NCHUNK];
__device__ float g_upwT  [256*128];           // [o*4+ij][cin]
__device__ float g_wrnd  [512*128];           // tf32-rounded in_proj weights

__device__ __forceinline__ float silu_f(float x) {
    return x / (1.0f + __expf(-x));
}
__device__ __forceinline__ float tf32r(float x) {
    unsigned int u;
    asm("cvt.rna.tf32.f32 %0, %1;" : "=r"(u) : "f"(x));
    return __uint_as_float(u);
}

__device__ __forceinline__ void cp_async16(unsigned int s, const void* g) {
    asm volatile("cp.async.cg.shared.global [%0], [%1], 16;" :: "r"(s), "l"(g));
}
__device__ __forceinline__ void cp_async4(unsigned int s, const void* g) {
    asm volatile("cp.async.ca.shared.global [%0], [%1], 4;" :: "r"(s), "l"(g));
}
__device__ __forceinline__ void cp_commit() {
    asm volatile("cp.async.commit_group;" ::: "memory");
}
__device__ __forceinline__ void cp_wait0() {
    asm volatile("cp.async.wait_group 0;" ::: "memory");
}

__device__ __forceinline__ void mma_tf32(float& d0, float& d1, float& d2, float& d3,
                                         unsigned a0, unsigned a1, unsigned a2, unsigned a3,
                                         unsigned b0, unsigned b1)
{
    asm volatile(
        "mma.sync.aligned.m16n8k8.row.col.f32.tf32.tf32.f32 "
        "{%0,%1,%2,%3}, {%4,%5,%6,%7}, {%8,%9}, {%0,%1,%2,%3};"
        : "+f"(d0), "+f"(d1), "+f"(d2), "+f"(d3)
        : "r"(a0), "r"(a1), "r"(a2), "r"(a3), "r"(b0), "r"(b1));
}

// ---------------------------------------------------------------------------
// 0a. transpose up_w (128,64,2,2) -> [n=o*4+ij][cin]
// ---------------------------------------------------------------------------
__global__ void k_transpose_upw(const float* __restrict__ upw)
{
    int cin = blockIdx.x;            // 128
    int n   = threadIdx.x;           // 256
    g_upwT[n*128 + cin] = upw[cin*256 + n];
}

// 0b. round in_proj weights to tf32 -> g_wrnd
__global__ void k_round_w(const float* __restrict__ w)
{
    int i = blockIdx.x*256 + threadIdx.x;
    g_wrnd[i] = tf32r(w[i]);
}

// ---------------------------------------------------------------------------
// 1. ConvTranspose2d k=2 s=2 -> channels 0..63 of g_seqT (tf32-rounded)
// ---------------------------------------------------------------------------
__global__ __launch_bounds__(256) void k_upsample(
    const float* __restrict__ x, const float* __restrict__ upb)
{
    __shared__ float xs[16][128];
    int t  = threadIdx.x;
    int b  = blockIdx.x >> 6;
    int p0 = (blockIdx.x & 63) << 4;

    for (int i = t; i < 16*128; i += 256) {
        int pix = i & 15, cin = i >> 4;
        xs[pix][cin] = x[(b*128 + cin)*1024 + p0 + pix];
    }
    __syncthreads();

    int o  = t >> 2;
    int ij = t & 3;
    int ii = ij >> 1, jj = ij & 1;

    float acc[16];
#pragma unroll
    for (int p = 0; p < 16; p++) acc[p] = 0.f;

    const float* wrow = g_upwT + t*128;
    for (int c4 = 0; c4 < 32; c4++) {
        float4 w4 = *reinterpret_cast<const float4*>(wrow + c4*4);
#pragma unroll
        for (int p = 0; p < 16; p++) {
            float4 x4 = *reinterpret_cast<const float4*>(&xs[p][c4*4]);
            acc[p] += x4.x*w4.x + x4.y*w4.y + x4.z*w4.z + x4.w*w4.w;
        }
    }
    float bias = upb[o];
#pragma unroll
    for (int p = 0; p < 16; p++) {
        int hp = (p0 + p) >> 5, wp = (p0 + p) & 31;
        int l  = (2*hp + ii)*64 + 2*wp + jj;
        g_seqT[o*MTOT + b*LSEQ + l] = tf32r(acc[p] + bias);
    }
}

// ---------------------------------------------------------------------------
// 2. copy skip_x into g_seqT channels 64..127 (tf32-rounded)
// ---------------------------------------------------------------------------
__global__ void k_copy_skip(const float* __restrict__ skip)
{
    int idx = blockIdx.x*256 + threadIdx.x;
    int l = idx & 4095;
    int c = (idx >> 12) & 63;
    int b = idx >> 18;
    g_seqT[(64 + c)*MTOT + b*LSEQ + l] = tf32r(skip[idx]);
}

// ---------------------------------------------------------------------------
// 3a. k_mma0: tf32 tensor-core GEMM, C[n][m] = W[n][k]*Bm[k][m], mode 0 out.
//     CTA 128n x 128m, 8 warps (4n x 2m), warp tile 32n x 64m (2x8 mma tiles),
//     k-chunk 16, cp.async double buffer. N%128==0, K%16==0.
// ---------------------------------------------------------------------------
__global__ __launch_bounds__(256, 2) void k_mma0(
    const float* __restrict__ W, const float* __restrict__ Bm,
    float* __restrict__ C, int N, int K)
{
    __shared__ float Ws[2][128][20];     // [n][k] pad 20 -> conflict-free frags
    __shared__ float Bs[2][16][136];     // [k][m] pad 136 -> conflict-free frags

    int tid  = threadIdx.x;
    int lane = tid & 31;
    int g    = lane >> 2;       // 0..7
    int tg   = lane & 3;        // 0..3
    int wid  = tid >> 5;
    int wm   = wid & 3;         // n-warp 0..3
    int wn   = wid >> 2;        // m-warp 0..1
    int nb   = wm * 32;
    int mb   = wn * 64;

    int m0 = blockIdx.x * 128;
    int n0 = blockIdx.y * 128;

    float d[2][8][4];
#pragma unroll
    for (int mt = 0; mt < 2; mt++)
#pragma unroll
        for (int nt = 0; nt < 8; nt++)
#pragma unroll
            for (int q = 0; q < 4; q++) d[mt][nt][q] = 0.f;

    // load indices
    int lb_k = tid >> 5;                 // Bs rows lb_k, lb_k+8
    int lb_m = (tid & 31) * 4;
    int lw_n = tid >> 1;                 // Ws row
    int lw_k = (tid & 1) * 8;            // Ws k segments lw_k, lw_k+4

    unsigned int sB = (unsigned int)__cvta_generic_to_shared(&Bs[0][lb_k][lb_m]);
    unsigned int sW = (unsigned int)__cvta_generic_to_shared(&Ws[0][lw_n][lw_k]);
    const unsigned int bufB = 16*136*4;
    const unsigned int bufW = 128*20*4;
    const unsigned int rowB = 8*136*4;   // 8 rows down

    const float* gB = Bm + (size_t)lb_k*MTOT + m0 + lb_m;
    const float* gW = W + (size_t)(n0 + lw_n)*K + lw_k;

    auto issue = [&](int buf, int k0) {
        cp_async16(sB + buf*bufB,        gB + (size_t)k0*MTOT);
        cp_async16(sB + buf*bufB + rowB, gB + (size_t)(k0 + 8)*MTOT);
        cp_async16(sW + buf*bufW,        gW + k0);
        cp_async16(sW + buf*bufW + 16,   gW + k0 + 4);
        cp_commit();
    };

    issue(0, 0);
    cp_wait0();
    __syncthreads();

    int p = 0;
    for (int k0 = 0; k0 < K; k0 += 16) {
        if (k0 + 16 < K) issue(p ^ 1, k0 + 16);

#pragma unroll
        for (int ks = 0; ks < 16; ks += 8) {
            unsigned a[2][4];
#pragma unroll
            for (int mt = 0; mt < 2; mt++) {
                int nr = nb + mt*16 + g;
                a[mt][0] = __float_as_uint(Ws[p][nr    ][ks + tg]);
                a[mt][1] = __float_as_uint(Ws[p][nr + 8][ks + tg]);
                a[mt][2] = __float_as_uint(Ws[p][nr    ][ks + tg + 4]);
                a[mt][3] = __float_as_uint(Ws[p][nr + 8][ks + tg + 4]);
            }
            unsigned bf[8][2];
#pragma unroll
            for (int nt = 0; nt < 8; nt++) {
                int mc = mb + nt*8 + g;
                bf[nt][0] = __float_as_uint(Bs[p][ks + tg    ][mc]);
                bf[nt][1] = __float_as_uint(Bs[p][ks + tg + 4][mc]);
            }
#pragma unroll
            for (int mt = 0; mt < 2; mt++)
#pragma unroll
                for (int nt = 0; nt < 8; nt++)
                    mma_tf32(d[mt][nt][0], d[mt][nt][1], d[mt][nt][2], d[mt][nt][3],
                             a[mt][0], a[mt][1], a[mt][2], a[mt][3],
                             bf[nt][0], bf[nt][1]);
        }
        cp_wait0();
        __syncthreads();
        p ^= 1;
    }

    // epilogue: channel-major [n][MTOT]
#pragma unroll
    for (int mt = 0; mt < 2; mt++) {
        int n_lo = n0 + nb + mt*16 + g;
        int n_hi = n_lo + 8;
#pragma unroll
        for (int nt = 0; nt < 8; nt++) {
            int m = m0 + mb + nt*8 + 2*tg;
            *reinterpret_cast<float2*>(C + (size_t)n_lo*MTOT + m) =
                make_float2(d[mt][nt][0], d[mt][nt][1]);
            *reinterpret_cast<float2*>(C + (size_t)n_hi*MTOT + m) =
                make_float2(d[mt][nt][2], d[mt][nt][3]);
        }
    }
}

// ---------------------------------------------------------------------------
// 3b. SGEMM v6 (fp32, cp.async): used for out_proj.
// ---------------------------------------------------------------------------
__global__ __launch_bounds__(256, 2) void k_sgemm6(
    const float* __restrict__ W, const float* __restrict__ Bm,
    float* __restrict__ C, int N, int K, int mode, int ldc)
{
    __shared__ float Bs[2][16][128];
    __shared__ float Ws[2][16][132];

    int tid = threadIdx.x;
    int tx = tid & 15;
    int ty = tid >> 4;
    int m0 = blockIdx.x * 128;
    int n0 = blockIdx.y * 128;

    float acc[8][8];
#pragma unroll
    for (int i = 0; i < 8; i++)
#pragma unroll
        for (int j = 0; j < 8; j++) acc[i][j] = 0.f;

    int lb_k = tid >> 5;
    int lb_m = (tid & 31) * 4;
    int lw_k = tid & 15;
    int lw_n = tid >> 4;

    unsigned int sB0 = (unsigned int)__cvta_generic_to_shared(&Bs[0][lb_k][lb_m]);
    unsigned int sB1 = (unsigned int)__cvta_generic_to_shared(&Bs[0][lb_k + 8][lb_m]);
    unsigned int sW  = (unsigned int)__cvta_generic_to_shared(&Ws[0][lw_k][lw_n]);
    const unsigned int bufB = 16*128*4;
    const unsigned int bufW = 16*132*4;

    const float* gB0 = Bm + (size_t)lb_k*MTOT + m0 + lb_m;
    const float* gB1 = Bm + (size_t)(lb_k + 8)*MTOT + m0 + lb_m;
    const float* gW  = W + (size_t)n0*K + lw_k;

    auto issue = [&](int buf, int k0) {
        cp_async16(sB0 + buf*bufB, gB0 + (size_t)k0*MTOT);
        cp_async16(sB1 + buf*bufB, gB1 + (size_t)k0*MTOT);
#pragma unroll
        for (int j = 0; j < 8; j++)
            cp_async4(sW + buf*bufW + j*16*4,
                      gW + (size_t)(lw_n + j*16)*K + k0);
        cp_commit();
    };

    issue(0, 0);
    cp_wait0();
    __syncthreads();

    int p = 0;
    for (int k0 = 0; k0 < K; k0 += 16) {
        if (k0 + 16 < K) issue(p ^ 1, k0 + 16);

#pragma unroll
        for (int k = 0; k < 16; k++) {
            float4 b0 = *reinterpret_cast<const float4*>(&Bs[p][k][tx*4]);
            float4 b1 = *reinterpret_cast<const float4*>(&Bs[p][k][64 + tx*4]);
            float4 w0 = *reinterpret_cast<const float4*>(&Ws[p][k][ty*4]);
            float4 w1 = *reinterpret_cast<const float4*>(&Ws[p][k][64 + ty*4]);
            float bm[8] = {b0.x, b0.y, b0.z, b0.w, b1.x, b1.y, b1.z, b1.w};
            float wn[8] = {w0.x, w0.y, w0.z, w0.w, w1.x, w1.y, w1.z, w1.w};
#pragma unroll
            for (int i = 0; i < 8; i++)
#pragma unroll
                for (int j = 0; j < 8; j++)
                    acc[i][j] += wn[i]*bm[j];
        }
        cp_wait0();
        __syncthreads();
        p ^= 1;
    }

    if (mode == 0) {
#pragma unroll
        for (int i = 0; i < 8; i++) {
            int n = n0 + ((i < 4) ? (ty*4 + i) : (64 + ty*4 + i - 4));
            *reinterpret_cast<float4*>(C + (size_t)n*MTOT + m0 + tx*4) =
                make_float4(acc[i][0], acc[i][1], acc[i][2], acc[i][3]);
            *reinterpret_cast<float4*>(C + (size_t)n*MTOT + m0 + 64 + tx*4) =
                make_float4(acc[i][4], acc[i][5], acc[i][6], acc[i][7]);
        }
    } else {
#pragma unroll
        for (int j = 0; j < 8; j++) {
            int m = m0 + ((j < 4) ? (tx*4 + j) : (64 + tx*4 + j - 4));
            *reinterpret_cast<float4*>(C + (size_t)m*ldc + n0 + ty*4) =
                make_float4(acc[0][j], acc[1][j], acc[2][j], acc[3][j]);
            *reinterpret_cast<float4*>(C + (size_t)m*ldc + n0 + 64 + ty*4) =
                make_float4(acc[4][j], acc[5][j], acc[6][j], acc[7][j]);
        }
    }
}

// ---------------------------------------------------------------------------
// 3c. SGEMM v4 (64-n tile) — small-N GEMMs (x_proj N=40, convout N=64)
// ---------------------------------------------------------------------------
__global__ __launch_bounds__(256) void k_sgemm4(
    const float* __restrict__ W, const float* __restrict__ Bm,
    float* __restrict__ C, const float* __restrict__ bias,
    int N, int K, int mode, int ldc)
{
    __shared__ float Bs[16][128];
    __shared__ float Ws[16][68];

    int tid = threadIdx.x;
    int tx = tid & 15;
    int ty = tid >> 4;
    int m0 = blockIdx.x * 128;
    int n0 = blockIdx.y * 64;

    float acc[4][8];
#pragma unroll
    for (int i = 0; i < 4; i++)
#pragma unroll
        for (int j = 0; j < 8; j++) acc[i][j] = 0.f;

    int lb_k = tid >> 5;
    int lb_m = (tid & 31) * 4;
    int lw_k = tid & 15;
    int lw_n = tid >> 4;

    const float* pB0 = Bm + (size_t)lb_k*MTOT + m0 + lb_m;
    const float* pB1 = Bm + (size_t)(lb_k + 8)*MTOT + m0 + lb_m;

    float4 pb0 = *reinterpret_cast<const float4*>(pB0);
    float4 pb1 = *reinterpret_cast<const float4*>(pB1);
    float  pw[4];
#pragma unroll
    for (int j = 0; j < 4; j++) {
        int n = n0 + lw_n + j*16;
        pw[j] = (n < N) ? W[(size_t)n*K + lw_k] : 0.f;
    }

    for (int k0 = 0; k0 < K; k0 += 16) {
        *reinterpret_cast<float4*>(&Bs[lb_k][lb_m])     = pb0;
        *reinterpret_cast<float4*>(&Bs[lb_k + 8][lb_m]) = pb1;
#pragma unroll
        for (int j = 0; j < 4; j++)
            Ws[lw_k][lw_n + j*16] = pw[j];
        __syncthreads();

        if (k0 + 16 < K) {
            pb0 = *reinterpret_cast<const float4*>(pB0 + (size_t)(k0 + 16)*MTOT);
            pb1 = *reinterpret_cast<const float4*>(pB1 + (size_t)(k0 + 16)*MTOT);
#pragma unroll
            for (int j = 0; j < 4; j++) {
                int n = n0 + lw_n + j*16;
                pw[j] = (n < N) ? W[(size_t)n*K + k0 + 16 + lw_k] : 0.f;
            }
        }

#pragma unroll
        for (int k = 0; k < 16; k++) {
            float4 b0 = *reinterpret_cast<const float4*>(&Bs[k][tx*4]);
            float4 b1 = *reinterpret_cast<const float4*>(&Bs[k][64 + tx*4]);
            float4 w0 = *reinterpret_cast<const float4*>(&Ws[k][ty*4]);
            float bm[8] = {b0.x, b0.y, b0.z, b0.w, b1.x, b1.y, b1.z, b1.w};
            float wn[4] = {w0.x, w0.y, w0.z, w0.w};
#pragma unroll
            for (int i = 0; i < 4; i++)
#pragma unroll
                for (int j = 0; j < 8; j++)
                    acc[i][j] += wn[i]*bm[j];
        }
        __syncthreads();
    }

    if (mode == 2) {
#pragma unroll
        for (int i = 0; i < 4; i++) {
            int n = n0 + ty*4 + i;
            if (n >= N) continue;
            float bb = bias ? bias[n] : 0.f;
            int bidx = m0 >> 12;
            int l0   = (m0 & 4095) + tx*4;
            float* base = C + (size_t)bidx*N*4096 + (size_t)n*4096;
            *reinterpret_cast<float4*>(base + l0) =
                make_float4(acc[i][0]+bb, acc[i][1]+bb, acc[i][2]+bb, acc[i][3]+bb);
            *reinterpret_cast<float4*>(base + l0 + 64) =
                make_float4(acc[i][4]+bb, acc[i][5]+bb, acc[i][6]+bb, acc[i][7]+bb);
        }
    } else {
        bool ok = (n0 + ty*4) < N;
        if (ok) {
#pragma unroll
            for (int j = 0; j < 8; j++) {
                int m = m0 + ((j < 4) ? (tx*4 + j) : (64 + tx*4 + j - 4));
                *reinterpret_cast<float4*>(C + (size_t)m*ldc + n0 + ty*4) =
                    make_float4(acc[0][j], acc[1][j], acc[2][j], acc[3][j]);
            }
        }
    }
}

// ---------------------------------------------------------------------------
// 4. depthwise causal conv1d (D_CONV=4) + bias + silu
// ---------------------------------------------------------------------------
__global__ void k_conv1d_silu(const float* __restrict__ cw,
                              const float* __restrict__ cb)
{
    int d = blockIdx.y;
    int m = blockIdx.x*256 + threadIdx.x;
    int l = m & 4095;
    const float* row = g_xzT + (size_t)d*MTOT;
    float w0 = cw[d*4+0], w1 = cw[d*4+1], w2 = cw[d*4+2], w3 = cw[d*4+3];
    float acc = cb[d];
    if (l >= 3) acc += w0*row[m-3];
    if (l >= 2) acc += w1*row[m-2];
    if (l >= 1) acc += w2*row[m-1];
    acc += w3*row[m];
    g_uT[(size_t)d*MTOT + m] = silu_f(acc);
}

// ---------------------------------------------------------------------------
// 5. delta = softplus(dt @ dt_proj_w.T + dt_proj_b) -> g_deltaT [d][m]
// ---------------------------------------------------------------------------
__global__ void k_delta(const float* __restrict__ dtw,
                        const float* __restrict__ dtb)
{
    __shared__ float sdt[64][8];
    int tid = threadIdx.x;
    int m0 = blockIdx.x*64;
    for (int i = tid; i < 512; i += 256) {
        int ml = i >> 3, r = i & 7;
        sdt[ml][r] = g_dbc[(size_t)(m0 + ml)*40 + r];
    }
    __syncthreads();
    int ml = tid & 63;
    int dl = tid >> 6;
    for (int it = 0; it < 64; it++) {
        int d = it*4 + dl;
        const float* wr = dtw + d*8;
        float x = dtb[d];
#pragma unroll
        for (int r = 0; r < 8; r++) x += wr[r]*sdt[ml][r];
        float sp = (x > 20.f) ? x : log1pf(__expf(x));
        g_deltaT[(size_t)d*MTOT + m0 + ml] = sp;
    }
}

// ---------------------------------------------------------------------------
// 6. scan pass 1: per-chunk partial scan from h=0, record h_end & sum(delta)
// ---------------------------------------------------------------------------
__global__ __launch_bounds__(128) void k_scan1(const float* __restrict__ A_log)
{
    int lane = threadIdx.x & 31;
    int wgid = blockIdx.x*4 + (threadIdx.x >> 5);
    int ch = wgid & 63;
    int dp = (wgid >> 6) & 127;
    int b  = wgid >> 13;
    int dd = lane >> 4, n = lane & 15;
    int d  = dp*2 + dd;

    float A = -__expf(A_log[d*DSTATE + n]);
    int m0 = b*LSEQ + ch*LCHUNK;
    const float* drow = g_deltaT + (size_t)d*MTOT;
    const float* urow = g_uT     + (size_t)d*MTOT;
    const float* dbc  = g_dbc;

    float h = 0.f, sumd = 0.f;
#pragma unroll 8
    for (int l = 0; l < LCHUNK; l++) {
        int m = m0 + l;
        float dt = drow[m];
        float uu = urow[m];
        float Bn = dbc[(size_t)m*40 + 8 + n];
        h = __expf(dt*A)*h + dt*Bn*uu;
        sumd += dt;
    }
    int bd = b*DINNER + d;
    g_hend[((size_t)bd*NCHUNK + ch)*DSTATE + n] = h;
    if (n == 0) g_sumd[(size_t)bd*NCHUNK + ch] = sumd;
}

// ---------------------------------------------------------------------------
// 7. scan pass 2: serial carry over 64 chunks per (b,d)
// ---------------------------------------------------------------------------
__global__ void k_scan2(const float* __restrict__ A_log)
{
    int gt = blockIdx.x*256 + threadIdx.x;
    int w  = gt >> 5;
    int lane = gt & 31;
    int dd = lane >> 4, n = lane & 15;
    int bd = w*2 + dd;
    int d  = bd & 255;

    float A = -__expf(A_log[d*DSTATE + n]);
    float h = 0.f;
    for (int ch = 0; ch < NCHUNK; ch++) {
        size_t base = ((size_t)bd*NCHUNK + ch)*DSTATE + n;
        g_hin[base] = h;
        float sd = g_sumd[(size_t)bd*NCHUNK + ch];
        h = __expf(sd*A)*h + g_hend[base];
    }
}

// ---------------------------------------------------------------------------
// 8. scan pass 3: rescan with entry state; y=(h.C + u*Dp)*silu(z)
// ---------------------------------------------------------------------------
__global__ __launch_bounds__(128) void k_scan3(const float* __restrict__ A_log,
                                               const float* __restrict__ Dp)
{
    int lane = threadIdx.x & 31;
    int wgid = blockIdx.x*4 + (threadIdx.x >> 5);
    int ch = wgid & 63;
    int dp = (wgid >> 6) & 127;
    int b  = wgid >> 13;
    int dd = lane >> 4, n = lane & 15;
    int d  = dp*2 + dd;
    int bd = b*DINNER + d;

    float A = -__expf(A_log[d*DSTATE + n]);
    float Dd = Dp[d];
    int m0 = b*LSEQ + ch*LCHUNK;
    const float* drow = g_deltaT + (size_t)d*MTOT;
    const float* urow = g_uT     + (size_t)d*MTOT;
    const float* zrow = g_xzT    + (size_t)(DINNER + d)*MTOT;
    const float* dbc  = g_dbc;
    float*       yrow = g_yT     + (size_t)d*MTOT;

    float h = g_hin[((size_t)bd*NCHUNK + ch)*DSTATE + n];

#pragma unroll 4
    for (int l = 0; l < LCHUNK; l++) {
        int m = m0 + l;
        float dt = drow[m];
        float uu = urow[m];
        float Bn = dbc[(size_t)m*40 + 8 + n];
        float Cn = dbc[(size_t)m*40 + 24 + n];
        h = __expf(dt*A)*h + dt*Bn*uu;
        float y = h*Cn;
        y += __shfl_xor_sync(0xffffffffu, y, 8, 16);
        y += __shfl_xor_sync(0xffffffffu, y, 4, 16);
        y += __shfl_xor_sync(0xffffffffu, y, 2, 16);
        y += __shfl_xor_sync(0xffffffffu, y, 1, 16);
        if (n == 0) {
            float z = zrow[m];
            yrow[m] = (y + uu*Dd) * silu_f(z);
        }
    }
}

// ---------------------------------------------------------------------------
// 9. LayerNorm over 128 channels + silu ; write channel-major g_lnT
// ---------------------------------------------------------------------------
__global__ __launch_bounds__(256) void k_ln_silu(const float* __restrict__ gamma,
                                                 const float* __restrict__ beta)
{
    __shared__ float sT[128][36];
    int tid = threadIdx.x;
    int wid = tid >> 5, lane = tid & 31;
    int m_base = blockIdx.x*32;

    for (int r = 0; r < 4; r++) {
        int mloc = r*8 + wid;
        int m = m_base + mloc;
        float4 v = *reinterpret_cast<const float4*>(g_ym + (size_t)m*128 + lane*4);
        float s  = v.x + v.y + v.z + v.w;
        float s2 = v.x*v.x + v.y*v.y + v.z*v.z + v.w*v.w;
#pragma unroll
        for (int k = 16; k >= 1; k >>= 1) {
            s  += __shfl_xor_sync(0xffffffffu, s,  k);
            s2 += __shfl_xor_sync(0xffffffffu, s2, k);
        }
        float mean = s * (1.f/128.f);
        float var  = s2 * (1.f/128.f) - mean*mean;
        float rstd = rsqrtf(var + 1e-5f);
        float va[4] = {v.x, v.y, v.z, v.w};
#pragma unroll
        for (int i = 0; i < 4; i++) {
            int c = lane*4 + i;
            float t = (va[i] - mean)*rstd*gamma[c] + beta[c];
            sT[c][mloc] = silu_f(t);
        }
    }
    __syncthreads();

    int mq = tid & 7;
    int c0 = tid >> 3;
    for (int cc = c0; cc < 128; cc += 32) {
        float4 v = *reinterpret_cast<const float4*>(&sT[cc][mq*4]);
        *reinterpret_cast<float4*>(g_lnT + (size_t)cc*MTOT + m_base + mq*4) = v;
    }
}

// ---------------------------------------------------------------------------
extern "C" void kernel_launch(void* const* d_in, const int* in_sizes, int n_in,
                              void* d_out, int out_size)
{
    const float* x        = (const float*)d_in[0];
    const float* skip_x   = (const float*)d_in[1];
    const float* up_w     = (const float*)d_in[2];
    const float* up_b     = (const float*)d_in[3];
    const float* in_proj  = (const float*)d_in[4];
    const float* conv1d_w = (const float*)d_in[5];
    const float* conv1d_b = (const float*)d_in[6];
    const float* x_proj   = (const float*)d_in[7];
    const float* dt_proj_w= (const float*)d_in[8];
    const float* dt_proj_b= (const float*)d_in[9];
    const float* A_log    = (const float*)d_in[10];
    const float* Dp       = (const float*)d_in[11];
    const float* out_proj = (const float*)d_in[12];
    const float* ln_gamma = (const float*)d_in[13];
    const float* ln_beta  = (const float*)d_in[14];
    const float* convout_w= (const float*)d_in[15];
    const float* convout_b= (const float*)d_in[16];
    float* out = (float*)d_out;

    float *p_seqT, *p_xzT, *p_uT, *p_yT, *p_lnT, *p_dbc, *p_ym, *p_wrnd;
    cudaGetSymbolAddress((void**)&p_seqT, g_seqT);
    cudaGetSymbolAddress((void**)&p_xzT,  g_xzT);
    cudaGetSymbolAddress((void**)&p_uT,   g_uT);
    cudaGetSymbolAddress((void**)&p_yT,   g_yT);
    cudaGetSymbolAddress((void**)&p_lnT,  g_lnT);
    cudaGetSymbolAddress((void**)&p_dbc,  g_dbc);
    cudaGetSymbolAddress((void**)&p_ym,   g_ym);
    cudaGetSymbolAddress((void**)&p_wrnd, g_wrnd);

    // 0-2: build seq (channel-major, tf32-rounded) + round weights
    k_transpose_upw<<<128, 256>>>(up_w);
    k_round_w<<<256, 256>>>(in_proj);
    k_upsample<<<BATCH*64, 256>>>(x, up_b);
    k_copy_skip<<<(BATCH*64*4096)/256, 256>>>(skip_x);

    // 3: in_proj (N=512, K=128) -> g_xzT channel-major [tf32 tensor core]
    k_mma0<<<dim3(MTOT/128, 4), 256>>>(p_wrnd, p_seqT, p_xzT, 512, 128);

    // 4: conv1d + silu -> g_uT
    k_conv1d_silu<<<dim3(MTOT/256, DINNER), 256>>>(conv1d_w, conv1d_b);

    // 5: x_proj (N=40, K=256) -> g_dbc row-major [m][40]  [v4]
    k_sgemm4<<<dim3(MTOT/128, 1), 256>>>(x_proj, p_uT, p_dbc, nullptr,
                                         40, 256, 1, 40);
    // 6: delta
    k_delta<<<MTOT/64, 256>>>(dt_proj_w, dt_proj_b);

    // 7-9: chunked selective scan
    k_scan1<<<8192, 128>>>(A_log);
    k_scan2<<<64, 256>>>(A_log);
    k_scan3<<<8192, 128>>>(A_log, Dp);

    // 10: out_proj (N=128, K=256) -> g_ym row-major [m][128]  [v6]
    k_sgemm6<<<dim3(MTOT/128, 1), 256>>>(out_proj, p_yT, p_ym, 128, 256, 1, 128);

    // 11: LayerNorm + silu -> g_lnT channel-major
    k_ln_silu<<<MTOT/32, 256>>>(ln_gamma, ln_beta);

    // 12: convout 1x1 (N=64, K=128) -> d_out NCHW + bias  [v4]
    k_sgemm4<<<dim3(MTOT/128, 1), 256>>>(convout_w, p_lnT, out, convout_b,
                                         64, 128, 2, 0);
}

// round 10
// speedup vs baseline: 1.1950x; 1.0220x over previous
#include <cuda_runtime.h>
#include <stdint.h>
#include <math.h>

#define BATCH   4
#define LSEQ    4096
#define MTOT    16384          // BATCH*LSEQ
#define DMODEL  128
#define DINNER  256
#define DSTATE  16
#define NCHUNK  64
#define LCHUNK  64

// ---------------- static scratch (no cudaMalloc anywhere) -------------------
__device__ float g_seqT  [DMODEL  * MTOT];    // [c][m] concat(up,skip) (tf32-rounded)
__device__ float g_xzT   [2*DINNER* MTOT];    // [n][m] rows 0..255 u_raw, 256..511 z
__device__ float g_uT    [DINNER  * MTOT];    // [d][m] conv1d+silu
__device__ float g_deltaT[DINNER  * MTOT];    // [d][m]
__device__ float g_dbc   [MTOT * 40];         // [m][40]  0..7 dt, 8..23 B, 24..39 C
__device__ float g_yT    [DINNER  * MTOT];    // [d][m] scan out * silu(z) (tf32)
__device__ float g_ym    [MTOT * DMODEL];     // [m][128] out_proj out
__device__ float g_lnT   [DMODEL  * MTOT];    // [c][m] LN+silu out (tf32)
__device__ float g_hend  [BATCH*DINNER*NCHUNK*DSTATE];
__device__ float g_hin   [BATCH*DINNER*NCHUNK*DSTATE];
__device__ float g_sumd  [BATCH*DINNER*NCHUNK];
__device__ float g_upwT  [256*128];           // [o*4+ij][cin]
__device__ float g_wrnd  [512*128];           // tf32 in_proj weights
__device__ float g_wrnd2 [128*256];           // tf32 out_proj weights
__device__ float g_wrnd3 [64*128];            // tf32 convout weights

__device__ __forceinline__ float silu_f(float x) {
    return x / (1.0f + __expf(-x));
}
__device__ __forceinline__ float tf32r(float x) {
    unsigned int u;
    asm("cvt.rna.tf32.f32 %0, %1;" : "=r"(u) : "f"(x));
    return __uint_as_float(u);
}

__device__ __forceinline__ void cp_async16(unsigned int s, const void* g) {
    asm volatile("cp.async.cg.shared.global [%0], [%1], 16;" :: "r"(s), "l"(g));
}
__device__ __forceinline__ void cp_async4(unsigned int s, const void* g) {
    asm volatile("cp.async.ca.shared.global [%0], [%1], 4;" :: "r"(s), "l"(g));
}
__device__ __forceinline__ void cp_commit() {
    asm volatile("cp.async.commit_group;" ::: "memory");
}
__device__ __forceinline__ void cp_wait0() {
    asm volatile("cp.async.wait_group 0;" ::: "memory");
}

__device__ __forceinline__ void mma_tf32(float& d0, float& d1, float& d2, float& d3,
                                         unsigned a0, unsigned a1, unsigned a2, unsigned a3,
                                         unsigned b0, unsigned b1)
{
    asm volatile(
        "mma.sync.aligned.m16n8k8.row.col.f32.tf32.tf32.f32 "
        "{%0,%1,%2,%3}, {%4,%5,%6,%7}, {%8,%9}, {%0,%1,%2,%3};"
        : "+f"(d0), "+f"(d1), "+f"(d2), "+f"(d3)
        : "r"(a0), "r"(a1), "r"(a2), "r"(a3), "r"(b0), "r"(b1));
}

// ---------------------------------------------------------------------------
// 0a. transpose up_w (128,64,2,2) -> [n=o*4+ij][cin]
// ---------------------------------------------------------------------------
__global__ void k_transpose_upw(const float* __restrict__ upw)
{
    int cin = blockIdx.x;            // 128
    int n   = threadIdx.x;           // 256
    g_upwT[n*128 + cin] = upw[cin*256 + n];
}

// 0b. round weights to tf32
__global__ void k_round_gen(float* __restrict__ dst, const float* __restrict__ src)
{
    int i = blockIdx.x*256 + threadIdx.x;
    dst[i] = tf32r(src[i]);
}

// ---------------------------------------------------------------------------
// 1. ConvTranspose2d k=2 s=2 -> channels 0..63 of g_seqT (tf32-rounded)
// ---------------------------------------------------------------------------
__global__ __launch_bounds__(256) void k_upsample(
    const float* __restrict__ x, const float* __restrict__ upb)
{
    __shared__ float xs[16][128];
    int t  = threadIdx.x;
    int b  = blockIdx.x >> 6;
    int p0 = (blockIdx.x & 63) << 4;

    for (int i = t; i < 16*128; i += 256) {
        int pix = i & 15, cin = i >> 4;
        xs[pix][cin] = x[(b*128 + cin)*1024 + p0 + pix];
    }
    __syncthreads();

    int o  = t >> 2;
    int ij = t & 3;
    int ii = ij >> 1, jj = ij & 1;

    float acc[16];
#pragma unroll
    for (int p = 0; p < 16; p++) acc[p] = 0.f;

    const float* wrow = g_upwT + t*128;
    for (int c4 = 0; c4 < 32; c4++) {
        float4 w4 = *reinterpret_cast<const float4*>(wrow + c4*4);
#pragma unroll
        for (int p = 0; p < 16; p++) {
            float4 x4 = *reinterpret_cast<const float4*>(&xs[p][c4*4]);
            acc[p] += x4.x*w4.x + x4.y*w4.y + x4.z*w4.z + x4.w*w4.w;
        }
    }
    float bias = upb[o];
#pragma unroll
    for (int p = 0; p < 16; p++) {
        int hp = (p0 + p) >> 5, wp = (p0 + p) & 31;
        int l  = (2*hp + ii)*64 + 2*wp + jj;
        g_seqT[o*MTOT + b*LSEQ + l] = tf32r(acc[p] + bias);
    }
}

// ---------------------------------------------------------------------------
// 2. copy skip_x into g_seqT channels 64..127 (tf32-rounded)
// ---------------------------------------------------------------------------
__global__ void k_copy_skip(const float* __restrict__ skip)
{
    int idx = blockIdx.x*256 + threadIdx.x;
    int l = idx & 4095;
    int c = (idx >> 12) & 63;
    int b = idx >> 18;
    g_seqT[(64 + c)*MTOT + b*LSEQ + l] = tf32r(skip[idx]);
}

// ---------------------------------------------------------------------------
// 3a. k_mma0: tf32 GEMM, C[n][m] = W[n][k]*Bm[k][m], channel-major out.
//     CTA 128n x 128m, 8 warps (4n x 2m). N%128==0, K%16==0.
// ---------------------------------------------------------------------------
__global__ __launch_bounds__(256, 2) void k_mma0(
    const float* __restrict__ W, const float* __restrict__ Bm,
    float* __restrict__ C, int N, int K)
{
    __shared__ float Ws[2][128][20];
    __shared__ float Bs[2][16][136];

    int tid  = threadIdx.x;
    int lane = tid & 31;
    int g    = lane >> 2;
    int tg   = lane & 3;
    int wid  = tid >> 5;
    int wm   = wid & 3;
    int wn   = wid >> 2;
    int nb   = wm * 32;
    int mb   = wn * 64;

    int m0 = blockIdx.x * 128;
    int n0 = blockIdx.y * 128;

    float d[2][8][4];
#pragma unroll
    for (int mt = 0; mt < 2; mt++)
#pragma unroll
        for (int nt = 0; nt < 8; nt++)
#pragma unroll
            for (int q = 0; q < 4; q++) d[mt][nt][q] = 0.f;

    int lb_k = tid >> 5;
    int lb_m = (tid & 31) * 4;
    int lw_n = tid >> 1;
    int lw_k = (tid & 1) * 8;

    unsigned int sB = (unsigned int)__cvta_generic_to_shared(&Bs[0][lb_k][lb_m]);
    unsigned int sW = (unsigned int)__cvta_generic_to_shared(&Ws[0][lw_n][lw_k]);
    const unsigned int bufB = 16*136*4;
    const unsigned int bufW = 128*20*4;
    const unsigned int rowB = 8*136*4;

    const float* gB = Bm + (size_t)lb_k*MTOT + m0 + lb_m;
    const float* gW = W + (size_t)(n0 + lw_n)*K + lw_k;

    auto issue = [&](int buf, int k0) {
        cp_async16(sB + buf*bufB,        gB + (size_t)k0*MTOT);
        cp_async16(sB + buf*bufB + rowB, gB + (size_t)(k0 + 8)*MTOT);
        cp_async16(sW + buf*bufW,        gW + k0);
        cp_async16(sW + buf*bufW + 16,   gW + k0 + 4);
        cp_commit();
    };

    issue(0, 0);
    cp_wait0();
    __syncthreads();

    int p = 0;
    for (int k0 = 0; k0 < K; k0 += 16) {
        if (k0 + 16 < K) issue(p ^ 1, k0 + 16);

#pragma unroll
        for (int ks = 0; ks < 16; ks += 8) {
            unsigned a[2][4];
#pragma unroll
            for (int mt = 0; mt < 2; mt++) {
                int nr = nb + mt*16 + g;
                a[mt][0] = __float_as_uint(Ws[p][nr    ][ks + tg]);
                a[mt][1] = __float_as_uint(Ws[p][nr + 8][ks + tg]);
                a[mt][2] = __float_as_uint(Ws[p][nr    ][ks + tg + 4]);
                a[mt][3] = __float_as_uint(Ws[p][nr + 8][ks + tg + 4]);
            }
            unsigned bf[8][2];
#pragma unroll
            for (int nt = 0; nt < 8; nt++) {
                int mc = mb + nt*8 + g;
                bf[nt][0] = __float_as_uint(Bs[p][ks + tg    ][mc]);
                bf[nt][1] = __float_as_uint(Bs[p][ks + tg + 4][mc]);
            }
#pragma unroll
            for (int mt = 0; mt < 2; mt++)
#pragma unroll
                for (int nt = 0; nt < 8; nt++)
                    mma_tf32(d[mt][nt][0], d[mt][nt][1], d[mt][nt][2], d[mt][nt][3],
                             a[mt][0], a[mt][1], a[mt][2], a[mt][3],
                             bf[nt][0], bf[nt][1]);
        }
        cp_wait0();
        __syncthreads();
        p ^= 1;
    }

#pragma unroll
    for (int mt = 0; mt < 2; mt++) {
        int n_lo = n0 + nb + mt*16 + g;
        int n_hi = n_lo + 8;
#pragma unroll
        for (int nt = 0; nt < 8; nt++) {
            int m = m0 + mb + nt*8 + 2*tg;
            *reinterpret_cast<float2*>(C + (size_t)n_lo*MTOT + m) =
                make_float2(d[mt][nt][0], d[mt][nt][1]);
            *reinterpret_cast<float2*>(C + (size_t)n_hi*MTOT + m) =
                make_float2(d[mt][nt][2], d[mt][nt][3]);
        }
    }
}

// ---------------------------------------------------------------------------
// 3b. k_mma1: same mainloop as k_mma0, row-major [m][ldc] epilogue (out_proj).
// ---------------------------------------------------------------------------
__global__ __launch_bounds__(256, 2) void k_mma1(
    const float* __restrict__ W, const float* __restrict__ Bm,
    float* __restrict__ C, int N, int K, int ldc)
{
    __shared__ float Ws[2][128][20];
    __shared__ float Bs[2][16][136];

    int tid  = threadIdx.x;
    int lane = tid & 31;
    int g    = lane >> 2;
    int tg   = lane & 3;
    int wid  = tid >> 5;
    int wm   = wid & 3;
    int wn   = wid >> 2;
    int nb   = wm * 32;
    int mb   = wn * 64;

    int m0 = blockIdx.x * 128;
    int n0 = blockIdx.y * 128;

    float d[2][8][4];
#pragma unroll
    for (int mt = 0; mt < 2; mt++)
#pragma unroll
        for (int nt = 0; nt < 8; nt++)
#pragma unroll
            for (int q = 0; q < 4; q++) d[mt][nt][q] = 0.f;

    int lb_k = tid >> 5;
    int lb_m = (tid & 31) * 4;
    int lw_n = tid >> 1;
    int lw_k = (tid & 1) * 8;

    unsigned int sB = (unsigned int)__cvta_generic_to_shared(&Bs[0][lb_k][lb_m]);
    unsigned int sW = (unsigned int)__cvta_generic_to_shared(&Ws[0][lw_n][lw_k]);
    const unsigned int bufB = 16*136*4;
    const unsigned int bufW = 128*20*4;
    const unsigned int rowB = 8*136*4;

    const float* gB = Bm + (size_t)lb_k*MTOT + m0 + lb_m;
    const float* gW = W + (size_t)(n0 + lw_n)*K + lw_k;

    auto issue = [&](int buf, int k0) {
        cp_async16(sB + buf*bufB,        gB + (size_t)k0*MTOT);
        cp_async16(sB + buf*bufB + rowB, gB + (size_t)(k0 + 8)*MTOT);
        cp_async16(sW + buf*bufW,        gW + k0);
        cp_async16(sW + buf*bufW + 16,   gW + k0 + 4);
        cp_commit();
    };

    issue(0, 0);
    cp_wait0();
    __syncthreads();

    int p = 0;
    for (int k0 = 0; k0 < K; k0 += 16) {
        if (k0 + 16 < K) issue(p ^ 1, k0 + 16);

#pragma unroll
        for (int ks = 0; ks < 16; ks += 8) {
            unsigned a[2][4];
#pragma unroll
            for (int mt = 0; mt < 2; mt++) {
                int nr = nb + mt*16 + g;
                a[mt][0] = __float_as_uint(Ws[p][nr    ][ks + tg]);
                a[mt][1] = __float_as_uint(Ws[p][nr + 8][ks + tg]);
                a[mt][2] = __float_as_uint(Ws[p][nr    ][ks + tg + 4]);
                a[mt][3] = __float_as_uint(Ws[p][nr + 8][ks + tg + 4]);
            }
            unsigned bf[8][2];
#pragma unroll
            for (int nt = 0; nt < 8; nt++) {
                int mc = mb + nt*8 + g;
                bf[nt][0] = __float_as_uint(Bs[p][ks + tg    ][mc]);
                bf[nt][1] = __float_as_uint(Bs[p][ks + tg + 4][mc]);
            }
#pragma unroll
            for (int mt = 0; mt < 2; mt++)
#pragma unroll
                for (int nt = 0; nt < 8; nt++)
                    mma_tf32(d[mt][nt][0], d[mt][nt][1], d[mt][nt][2], d[mt][nt][3],
                             a[mt][0], a[mt][1], a[mt][2], a[mt][3],
                             bf[nt][0], bf[nt][1]);
        }
        cp_wait0();
        __syncthreads();
        p ^= 1;
    }

    // row-major epilogue: C[m][n]
#pragma unroll
    for (int mt = 0; mt < 2; mt++) {
        int n_lo = n0 + nb + mt*16 + g;
        int n_hi = n_lo + 8;
#pragma unroll
        for (int nt = 0; nt < 8; nt++) {
            int m = m0 + mb + nt*8 + 2*tg;
            C[(size_t)m*ldc + n_lo]       = d[mt][nt][0];
            C[(size_t)(m+1)*ldc + n_lo]   = d[mt][nt][1];
            C[(size_t)m*ldc + n_hi]       = d[mt][nt][2];
            C[(size_t)(m+1)*ldc + n_hi]   = d[mt][nt][3];
        }
    }
}

// ---------------------------------------------------------------------------
// 3c. k_mma2: tf32 GEMM for convout. N=64 per block (2n x 4m warps),
//     NCHW + bias epilogue. K%16==0.
// ---------------------------------------------------------------------------
__global__ __launch_bounds__(256, 2) void k_mma2(
    const float* __restrict__ W, const float* __restrict__ Bm,
    float* __restrict__ C, const float* __restrict__ bias, int N, int K)
{
    __shared__ float Ws[2][64][20];
    __shared__ float Bs[2][16][136];

    int tid  = threadIdx.x;
    int lane = tid & 31;
    int g    = lane >> 2;
    int tg   = lane & 3;
    int wid  = tid >> 5;
    int wm   = wid & 1;         // n-warp 0..1
    int wn   = wid >> 1;        // m-warp 0..3
    int nb   = wm * 32;
    int mb   = wn * 32;

    int m0 = blockIdx.x * 128;

    float d[2][4][4];
#pragma unroll
    for (int mt = 0; mt < 2; mt++)
#pragma unroll
        for (int nt = 0; nt < 4; nt++)
#pragma unroll
            for (int q = 0; q < 4; q++) d[mt][nt][q] = 0.f;

    int lb_k = tid >> 5;
    int lb_m = (tid & 31) * 4;
    int lw_n = tid >> 2;        // 0..63
    int lw_k = (tid & 3) * 4;

    unsigned int sB = (unsigned int)__cvta_generic_to_shared(&Bs[0][lb_k][lb_m]);
    unsigned int sW = (unsigned int)__cvta_generic_to_shared(&Ws[0][lw_n][lw_k]);
    const unsigned int bufB = 16*136*4;
    const unsigned int bufW = 64*20*4;
    const unsigned int rowB = 8*136*4;

    const float* gB = Bm + (size_t)lb_k*MTOT + m0 + lb_m;
    const float* gW = W + (size_t)lw_n*K + lw_k;

    auto issue = [&](int buf, int k0) {
        cp_async16(sB + buf*bufB,        gB + (size_t)k0*MTOT);
        cp_async16(sB + buf*bufB + rowB, gB + (size_t)(k0 + 8)*MTOT);
        cp_async16(sW + buf*bufW,        gW + k0);
        cp_commit();
    };

    issue(0, 0);
    cp_wait0();
    __syncthreads();

    int p = 0;
    for (int k0 = 0; k0 < K; k0 += 16) {
        if (k0 + 16 < K) issue(p ^ 1, k0 + 16);

#pragma unroll
        for (int ks = 0; ks < 16; ks += 8) {
            unsigned a[2][4];
#pragma unroll
            for (int mt = 0; mt < 2; mt++) {
                int nr = nb + mt*16 + g;
                a[mt][0] = __float_as_uint(Ws[p][nr    ][ks + tg]);
                a[mt][1] = __float_as_uint(Ws[p][nr + 8][ks + tg]);
                a[mt][2] = __float_as_uint(Ws[p][nr    ][ks + tg + 4]);
                a[mt][3] = __float_as_uint(Ws[p][nr + 8][ks + tg + 4]);
            }
            unsigned bf[4][2];
#pragma unroll
            for (int nt = 0; nt < 4; nt++) {
                int mc = mb + nt*8 + g;
                bf[nt][0] = __float_as_uint(Bs[p][ks + tg    ][mc]);
                bf[nt][1] = __float_as_uint(Bs[p][ks + tg + 4][mc]);
            }
#pragma unroll
            for (int mt = 0; mt < 2; mt++)
#pragma unroll
                for (int nt = 0; nt < 4; nt++)
                    mma_tf32(d[mt][nt][0], d[mt][nt][1], d[mt][nt][2], d[mt][nt][3],
                             a[mt][0], a[mt][1], a[mt][2], a[mt][3],
                             bf[nt][0], bf[nt][1]);
        }
        cp_wait0();
        __syncthreads();
        p ^= 1;
    }

    // NCHW epilogue: C[bidx][n][l] + bias
    int bidx = m0 >> 12;
    int lbase = (m0 & 4095);
#pragma unroll
    for (int mt = 0; mt < 2; mt++) {
        int n_lo = nb + mt*16 + g;
        int n_hi = n_lo + 8;
        float bl = bias[n_lo], bh = bias[n_hi];
#pragma unroll
        for (int nt = 0; nt < 4; nt++) {
            int l = lbase + mb + nt*8 + 2*tg;
            *reinterpret_cast<float2*>(C + (size_t)bidx*N*4096 + (size_t)n_lo*4096 + l) =
                make_float2(d[mt][nt][0] + bl, d[mt][nt][1] + bl);
            *reinterpret_cast<float2*>(C + (size_t)bidx*N*4096 + (size_t)n_hi*4096 + l) =
                make_float2(d[mt][nt][2] + bh, d[mt][nt][3] + bh);
        }
    }
}

// ---------------------------------------------------------------------------
// 3d. SGEMM v4 (64-n tile) — x_proj (N=40, fp32, feeds scan)
// ---------------------------------------------------------------------------
__global__ __launch_bounds__(256) void k_sgemm4(
    const float* __restrict__ W, const float* __restrict__ Bm,
    float* __restrict__ C, const float* __restrict__ bias,
    int N, int K, int mode, int ldc)
{
    __shared__ float Bs[16][128];
    __shared__ float Ws[16][68];

    int tid = threadIdx.x;
    int tx = tid & 15;
    int ty = tid >> 4;
    int m0 = blockIdx.x * 128;
    int n0 = blockIdx.y * 64;

    float acc[4][8];
#pragma unroll
    for (int i = 0; i < 4; i++)
#pragma unroll
        for (int j = 0; j < 8; j++) acc[i][j] = 0.f;

    int lb_k = tid >> 5;
    int lb_m = (tid & 31) * 4;
    int lw_k = tid & 15;
    int lw_n = tid >> 4;

    const float* pB0 = Bm + (size_t)lb_k*MTOT + m0 + lb_m;
    const float* pB1 = Bm + (size_t)(lb_k + 8)*MTOT + m0 + lb_m;

    float4 pb0 = *reinterpret_cast<const float4*>(pB0);
    float4 pb1 = *reinterpret_cast<const float4*>(pB1);
    float  pw[4];
#pragma unroll
    for (int j = 0; j < 4; j++) {
        int n = n0 + lw_n + j*16;
        pw[j] = (n < N) ? W[(size_t)n*K + lw_k] : 0.f;
    }

    for (int k0 = 0; k0 < K; k0 += 16) {
        *reinterpret_cast<float4*>(&Bs[lb_k][lb_m])     = pb0;
        *reinterpret_cast<float4*>(&Bs[lb_k + 8][lb_m]) = pb1;
#pragma unroll
        for (int j = 0; j < 4; j++)
            Ws[lw_k][lw_n + j*16] = pw[j];
        __syncthreads();

        if (k0 + 16 < K) {
            pb0 = *reinterpret_cast<const float4*>(pB0 + (size_t)(k0 + 16)*MTOT);
            pb1 = *reinterpret_cast<const float4*>(pB1 + (size_t)(k0 + 16)*MTOT);
#pragma unroll
            for (int j = 0; j < 4; j++) {
                int n = n0 + lw_n + j*16;
                pw[j] = (n < N) ? W[(size_t)n*K + k0 + 16 + lw_k] : 0.f;
            }
        }

#pragma unroll
        for (int k = 0; k < 16; k++) {
            float4 b0 = *reinterpret_cast<const float4*>(&Bs[k][tx*4]);
            float4 b1 = *reinterpret_cast<const float4*>(&Bs[k][64 + tx*4]);
            float4 w0 = *reinterpret_cast<const float4*>(&Ws[k][ty*4]);
            float bm[8] = {b0.x, b0.y, b0.z, b0.w, b1.x, b1.y, b1.z, b1.w};
            float wn[4] = {w0.x, w0.y, w0.z, w0.w};
#pragma unroll
            for (int i = 0; i < 4; i++)
#pragma unroll
                for (int j = 0; j < 8; j++)
                    acc[i][j] += wn[i]*bm[j];
        }
        __syncthreads();
    }

    // mode 1: row-major [m][ldc]
    bool ok = (n0 + ty*4) < N;
    if (ok) {
#pragma unroll
        for (int j = 0; j < 8; j++) {
            int m = m0 + ((j < 4) ? (tx*4 + j) : (64 + tx*4 + j - 4));
            *reinterpret_cast<float4*>(C + (size_t)m*ldc + n0 + ty*4) =
                make_float4(acc[0][j], acc[1][j], acc[2][j], acc[3][j]);
        }
    }
}

// ---------------------------------------------------------------------------
// 4. depthwise causal conv1d (D_CONV=4) + bias + silu
// ---------------------------------------------------------------------------
__global__ void k_conv1d_silu(const float* __restrict__ cw,
                              const float* __restrict__ cb)
{
    int d = blockIdx.y;
    int m = blockIdx.x*256 + threadIdx.x;
    int l = m & 4095;
    const float* row = g_xzT + (size_t)d*MTOT;
    float w0 = cw[d*4+0], w1 = cw[d*4+1], w2 = cw[d*4+2], w3 = cw[d*4+3];
    float acc = cb[d];
    if (l >= 3) acc += w0*row[m-3];
    if (l >= 2) acc += w1*row[m-2];
    if (l >= 1) acc += w2*row[m-1];
    acc += w3*row[m];
    g_uT[(size_t)d*MTOT + m] = silu_f(acc);
}

// ---------------------------------------------------------------------------
// 5. delta = softplus(dt @ dt_proj_w.T + dt_proj_b) -> g_deltaT [d][m]
// ---------------------------------------------------------------------------
__global__ void k_delta(const float* __restrict__ dtw,
                        const float* __restrict__ dtb)
{
    __shared__ float sdt[64][8];
    int tid = threadIdx.x;
    int m0 = blockIdx.x*64;
    for (int i = tid; i < 512; i += 256) {
        int ml = i >> 3, r = i & 7;
        sdt[ml][r] = g_dbc[(size_t)(m0 + ml)*40 + r];
    }
    __syncthreads();
    int ml = tid & 63;
    int dl = tid >> 6;
    for (int it = 0; it < 64; it++) {
        int d = it*4 + dl;
        const float* wr = dtw + d*8;
        float x = dtb[d];
#pragma unroll
        for (int r = 0; r < 8; r++) x += wr[r]*sdt[ml][r];
        float sp = (x > 20.f) ? x : log1pf(__expf(x));
        g_deltaT[(size_t)d*MTOT + m0 + ml] = sp;
    }
}

// ---------------------------------------------------------------------------
// 6. scan pass 1
// ---------------------------------------------------------------------------
__global__ __launch_bounds__(128) void k_scan1(const float* __restrict__ A_log)
{
    int lane = threadIdx.x & 31;
    int wgid = blockIdx.x*4 + (threadIdx.x >> 5);
    int ch = wgid & 63;
    int dp = (wgid >> 6) & 127;
    int b  = wgid >> 13;
    int dd = lane >> 4, n = lane & 15;
    int d  = dp*2 + dd;

    float A = -__expf(A_log[d*DSTATE + n]);
    int m0 = b*LSEQ + ch*LCHUNK;
    const float* drow = g_deltaT + (size_t)d*MTOT;
    const float* urow = g_uT     + (size_t)d*MTOT;
    const float* dbc  = g_dbc;

    float h = 0.f, sumd = 0.f;
#pragma unroll 8
    for (int l = 0; l < LCHUNK; l++) {
        int m = m0 + l;
        float dt = drow[m];
        float uu = urow[m];
        float Bn = dbc[(size_t)m*40 + 8 + n];
        h = __expf(dt*A)*h + dt*Bn*uu;
        sumd += dt;
    }
    int bd = b*DINNER + d;
    g_hend[((size_t)bd*NCHUNK + ch)*DSTATE + n] = h;
    if (n == 0) g_sumd[(size_t)bd*NCHUNK + ch] = sumd;
}

// ---------------------------------------------------------------------------
// 7. scan pass 2
// ---------------------------------------------------------------------------
__global__ void k_scan2(const float* __restrict__ A_log)
{
    int gt = blockIdx.x*256 + threadIdx.x;
    int w  = gt >> 5;
    int lane = gt & 31;
    int dd = lane >> 4, n = lane & 15;
    int bd = w*2 + dd;
    int d  = bd & 255;

    float A = -__expf(A_log[d*DSTATE + n]);
    float h = 0.f;
    for (int ch = 0; ch < NCHUNK; ch++) {
        size_t base = ((size_t)bd*NCHUNK + ch)*DSTATE + n;
        g_hin[base] = h;
        float sd = g_sumd[(size_t)bd*NCHUNK + ch];
        h = __expf(sd*A)*h + g_hend[base];
    }
}

// ---------------------------------------------------------------------------
// 8. scan pass 3: rescan; y=(h.C + u*Dp)*silu(z), tf32-rounded for out_proj
// ---------------------------------------------------------------------------
__global__ __launch_bounds__(128) void k_scan3(const float* __restrict__ A_log,
                                               const float* __restrict__ Dp)
{
    int lane = threadIdx.x & 31;
    int wgid = blockIdx.x*4 + (threadIdx.x >> 5);
    int ch = wgid & 63;
    int dp = (wgid >> 6) & 127;
    int b  = wgid >> 13;
    int dd = lane >> 4, n = lane & 15;
    int d  = dp*2 + dd;
    int bd = b*DINNER + d;

    float A = -__expf(A_log[d*DSTATE + n]);
    float Dd = Dp[d];
    int m0 = b*LSEQ + ch*LCHUNK;
    const float* drow = g_deltaT + (size_t)d*MTOT;
    const float* urow = g_uT     + (size_t)d*MTOT;
    const float* zrow = g_xzT    + (size_t)(DINNER + d)*MTOT;
    const float* dbc  = g_dbc;
    float*       yrow = g_yT     + (size_t)d*MTOT;

    float h = g_hin[((size_t)bd*NCHUNK + ch)*DSTATE + n];

#pragma unroll 4
    for (int l = 0; l < LCHUNK; l++) {
        int m = m0 + l;
        float dt = drow[m];
        float uu = urow[m];
        float Bn = dbc[(size_t)m*40 + 8 + n];
        float Cn = dbc[(size_t)m*40 + 24 + n];
        h = __expf(dt*A)*h + dt*Bn*uu;
        float y = h*Cn;
        y += __shfl_xor_sync(0xffffffffu, y, 8, 16);
        y += __shfl_xor_sync(0xffffffffu, y, 4, 16);
        y += __shfl_xor_sync(0xffffffffu, y, 2, 16);
        y += __shfl_xor_sync(0xffffffffu, y, 1, 16);
        if (n == 0) {
            float z = zrow[m];
            yrow[m] = tf32r((y + uu*Dd) * silu_f(z));
        }
    }
}

// ---------------------------------------------------------------------------
// 9. LayerNorm over 128 channels + silu ; channel-major tf32 out
// ---------------------------------------------------------------------------
__global__ __launch_bounds__(256) void k_ln_silu(const float* __restrict__ gamma,
                                                 const float* __restrict__ beta)
{
    __shared__ float sT[128][36];
    int tid = threadIdx.x;
    int wid = tid >> 5, lane = tid & 31;
    int m_base = blockIdx.x*32;

    for (int r = 0; r < 4; r++) {
        int mloc = r*8 + wid;
        int m = m_base + mloc;
        float4 v = *reinterpret_cast<const float4*>(g_ym + (size_t)m*128 + lane*4);
        float s  = v.x + v.y + v.z + v.w;
        float s2 = v.x*v.x + v.y*v.y + v.z*v.z + v.w*v.w;
#pragma unroll
        for (int k = 16; k >= 1; k >>= 1) {
            s  += __shfl_xor_sync(0xffffffffu, s,  k);
            s2 += __shfl_xor_sync(0xffffffffu, s2, k);
        }
        float mean = s * (1.f/128.f);
        float var  = s2 * (1.f/128.f) - mean*mean;
        float rstd = rsqrtf(var + 1e-5f);
        float va[4] = {v.x, v.y, v.z, v.w};
#pragma unroll
        for (int i = 0; i < 4; i++) {
            int c = lane*4 + i;
            float t = (va[i] - mean)*rstd*gamma[c] + beta[c];
            sT[c][mloc] = tf32r(silu_f(t));
        }
    }
    __syncthreads();

    int mq = tid & 7;
    int c0 = tid >> 3;
    for (int cc = c0; cc < 128; cc += 32) {
        float4 v = *reinterpret_cast<const float4*>(&sT[cc][mq*4]);
        *reinterpret_cast<float4*>(g_lnT + (size_t)cc*MTOT + m_base + mq*4) = v;
    }
}

// ---------------------------------------------------------------------------
extern "C" void kernel_launch(void* const* d_in, const int* in_sizes, int n_in,
                              void* d_out, int out_size)
{
    const float* x        = (const float*)d_in[0];
    const float* skip_x   = (const float*)d_in[1];
    const float* up_w     = (const float*)d_in[2];
    const float* up_b     = (const float*)d_in[3];
    const float* in_proj  = (const float*)d_in[4];
    const float* conv1d_w = (const float*)d_in[5];
    const float* conv1d_b = (const float*)d_in[6];
    const float* x_proj   = (const float*)d_in[7];
    const float* dt_proj_w= (const float*)d_in[8];
    const float* dt_proj_b= (const float*)d_in[9];
    const float* A_log    = (const float*)d_in[10];
    const float* Dp       = (const float*)d_in[11];
    const float* out_proj = (const float*)d_in[12];
    const float* ln_gamma = (const float*)d_in[13];
    const float* ln_beta  = (const float*)d_in[14];
    const float* convout_w= (const float*)d_in[15];
    const float* convout_b= (const float*)d_in[16];
    float* out = (float*)d_out;

    float *p_seqT, *p_xzT, *p_uT, *p_yT, *p_lnT, *p_dbc, *p_ym;
    float *p_wrnd, *p_wrnd2, *p_wrnd3;
    cudaGetSymbolAddress((void**)&p_seqT, g_seqT);
    cudaGetSymbolAddress((void**)&p_xzT,  g_xzT);
    cudaGetSymbolAddress((void**)&p_uT,   g_uT);
    cudaGetSymbolAddress((void**)&p_yT,   g_yT);
    cudaGetSymbolAddress((void**)&p_lnT,  g_lnT);
    cudaGetSymbolAddress((void**)&p_dbc,  g_dbc);
    cudaGetSymbolAddress((void**)&p_ym,   g_ym);
    cudaGetSymbolAddress((void**)&p_wrnd, g_wrnd);
    cudaGetSymbolAddress((void**)&p_wrnd2, g_wrnd2);
    cudaGetSymbolAddress((void**)&p_wrnd3, g_wrnd3);

    // 0-2: prep (tf32 rounding of weights + seq build)
    k_transpose_upw<<<128, 256>>>(up_w);
    k_round_gen<<<(512*128)/256, 256>>>(p_wrnd, in_proj);
    k_round_gen<<<(128*256)/256, 256>>>(p_wrnd2, out_proj);
    k_round_gen<<<(64*128)/256, 256>>>(p_wrnd3, convout_w);
    k_upsample<<<BATCH*64, 256>>>(x, up_b);
    k_copy_skip<<<(BATCH*64*4096)/256, 256>>>(skip_x);

    // 3: in_proj (N=512, K=128) -> g_xzT channel-major [tf32]
    k_mma0<<<dim3(MTOT/128, 4), 256>>>(p_wrnd, p_seqT, p_xzT, 512, 128);

    // 4: conv1d + silu -> g_uT
    k_conv1d_silu<<<dim3(MTOT/256, DINNER), 256>>>(conv1d_w, conv1d_b);

    // 5: x_proj (N=40, K=256) -> g_dbc row-major [m][40]  [fp32]
    k_sgemm4<<<dim3(MTOT/128, 1), 256>>>(x_proj, p_uT, p_dbc, nullptr,
                                         40, 256, 1, 40);
    // 6: delta
    k_delta<<<MTOT/64, 256>>>(dt_proj_w, dt_proj_b);

    // 7-9: chunked selective scan (fp32)
    k_scan1<<<8192, 128>>>(A_log);
    k_scan2<<<64, 256>>>(A_log);
    k_scan3<<<8192, 128>>>(A_log, Dp);

    // 10: out_proj (N=128, K=256) -> g_ym row-major [m][128]  [tf32]
    k_mma1<<<dim3(MTOT/128, 1), 256>>>(p_wrnd2, p_yT, p_ym, 128, 256, 128);

    // 11: LayerNorm + silu -> g_lnT channel-major (tf32)
    k_ln_silu<<<MTOT/32, 256>>>(ln_gamma, ln_beta);

    // 12: convout 1x1 (N=64, K=128) -> d_out NCHW + bias  [tf32]
    k_mma2<<<dim3(MTOT/128, 1), 256>>>(p_wrnd3, p_lnT, out, convout_b, 64, 128);
}

// round 11
// speedup vs baseline: 1.2646x; 1.0583x over previous
#include <cuda_runtime.h>
#include <stdint.h>
#include <math.h>

#define BATCH   4
#define LSEQ    4096
#define MTOT    16384          // BATCH*LSEQ
#define DMODEL  128
#define DINNER  256
#define DSTATE  16
#define NCHUNK  64
#define LCHUNK  64

// ---------------- static scratch (no cudaMalloc anywhere) -------------------
__device__ float g_seqT  [DMODEL  * MTOT];    // [c][m] concat(up,skip) (tf32)
__device__ float g_xzT   [2*DINNER* MTOT];    // [n][m] rows 0..255 u_raw, 256..511 z
__device__ float g_uT    [DINNER  * MTOT];    // [d][m] conv1d+silu (fp32)
__device__ float g_deltaT[DINNER  * MTOT];    // [d][m]
__device__ float g_dbc   [MTOT * 40];         // [m][40]  0..7 dt, 8..23 B, 24..39 C
__device__ float g_yT    [DINNER  * MTOT];    // [d][m] scan out * silu(z) (tf32)
__device__ float g_ym    [MTOT * DMODEL];     // [m][128] out_proj out
__device__ float g_lnT   [DMODEL  * MTOT];    // [c][m] LN+silu out (tf32)
__device__ float g_hend  [BATCH*DINNER*NCHUNK*DSTATE];
__device__ float g_hin   [BATCH*DINNER*NCHUNK*DSTATE];
__device__ float g_sumd  [BATCH*DINNER*NCHUNK];
__device__ float g_upwT  [256*128];           // [o*4+ij][cin]
__device__ float g_wrnd  [512*128];           // tf32 in_proj weights
__device__ float g_wrnd2 [128*256];           // tf32 out_proj weights
__device__ float g_wrnd3 [64*128];            // tf32 convout weights
__device__ float g_wrnd4 [64*256];            // tf32 x_proj weights (rows 40..63 zero)

__device__ __forceinline__ float silu_f(float x) {
    return x / (1.0f + __expf(-x));
}
__device__ __forceinline__ float tf32r(float x) {
    unsigned int u;
    asm("cvt.rna.tf32.f32 %0, %1;" : "=r"(u) : "f"(x));
    return __uint_as_float(u);
}

__device__ __forceinline__ void cp_async16(unsigned int s, const void* g) {
    asm volatile("cp.async.cg.shared.global [%0], [%1], 16;" :: "r"(s), "l"(g));
}
__device__ __forceinline__ void cp_commit() {
    asm volatile("cp.async.commit_group;" ::: "memory");
}
__device__ __forceinline__ void cp_wait0() {
    asm volatile("cp.async.wait_group 0;" ::: "memory");
}

__device__ __forceinline__ void mma_tf32(float& d0, float& d1, float& d2, float& d3,
                                         unsigned a0, unsigned a1, unsigned a2, unsigned a3,
                                         unsigned b0, unsigned b1)
{
    asm volatile(
        "mma.sync.aligned.m16n8k8.row.col.f32.tf32.tf32.f32 "
        "{%0,%1,%2,%3}, {%4,%5,%6,%7}, {%8,%9}, {%0,%1,%2,%3};"
        : "+f"(d0), "+f"(d1), "+f"(d2), "+f"(d3)
        : "r"(a0), "r"(a1), "r"(a2), "r"(a3), "r"(b0), "r"(b1));
}

// ---------------------------------------------------------------------------
// 0. merged prep: transpose up_w + tf32-round all mma weights (one launch)
//    segments by blockIdx.x:
//    [0,128)    transpose_upw
//    [128,384)  round in_proj   (65536)
//    [384,512)  round out_proj  (32768)
//    [512,544)  round convout   (8192)
//    [544,608)  round+pad x_proj (64x256, rows>=40 zero)
// ---------------------------------------------------------------------------
__global__ void k_prep(const float* __restrict__ upw,
                       const float* __restrict__ w_in,
                       const float* __restrict__ w_out,
                       const float* __restrict__ w_co,
                       const float* __restrict__ w_xp)
{
    int bx = blockIdx.x, t = threadIdx.x;
    if (bx < 128) {
        g_upwT[t*128 + bx] = upw[bx*256 + t];
    } else if (bx < 384) {
        int i = (bx - 128)*256 + t;
        g_wrnd[i] = tf32r(w_in[i]);
    } else if (bx < 512) {
        int i = (bx - 384)*256 + t;
        g_wrnd2[i] = tf32r(w_out[i]);
    } else if (bx < 544) {
        int i = (bx - 512)*256 + t;
        g_wrnd3[i] = tf32r(w_co[i]);
    } else {
        int i = (bx - 544)*256 + t;
        int row = i >> 8;            // /256
        g_wrnd4[i] = (row < 40) ? tf32r(w_xp[row*256 + (i & 255)]) : 0.f;
    }
}

// ---------------------------------------------------------------------------
// 1. ConvTranspose2d k=2 s=2 -> channels 0..63 of g_seqT (tf32)
// ---------------------------------------------------------------------------
__global__ __launch_bounds__(256) void k_upsample(
    const float* __restrict__ x, const float* __restrict__ upb)
{
    __shared__ float xs[16][128];
    int t  = threadIdx.x;
    int b  = blockIdx.x >> 6;
    int p0 = (blockIdx.x & 63) << 4;

    for (int i = t; i < 16*128; i += 256) {
        int pix = i & 15, cin = i >> 4;
        xs[pix][cin] = x[(b*128 + cin)*1024 + p0 + pix];
    }
    __syncthreads();

    int o  = t >> 2;
    int ij = t & 3;
    int ii = ij >> 1, jj = ij & 1;

    float acc[16];
#pragma unroll
    for (int p = 0; p < 16; p++) acc[p] = 0.f;

    const float* wrow = g_upwT + t*128;
    for (int c4 = 0; c4 < 32; c4++) {
        float4 w4 = *reinterpret_cast<const float4*>(wrow + c4*4);
#pragma unroll
        for (int p = 0; p < 16; p++) {
            float4 x4 = *reinterpret_cast<const float4*>(&xs[p][c4*4]);
            acc[p] += x4.x*w4.x + x4.y*w4.y + x4.z*w4.z + x4.w*w4.w;
        }
    }
    float bias = upb[o];
#pragma unroll
    for (int p = 0; p < 16; p++) {
        int hp = (p0 + p) >> 5, wp = (p0 + p) & 31;
        int l  = (2*hp + ii)*64 + 2*wp + jj;
        g_seqT[o*MTOT + b*LSEQ + l] = tf32r(acc[p] + bias);
    }
}

// ---------------------------------------------------------------------------
// 2. copy skip_x into g_seqT channels 64..127 (tf32)
// ---------------------------------------------------------------------------
__global__ void k_copy_skip(const float* __restrict__ skip)
{
    int idx = blockIdx.x*256 + threadIdx.x;
    int l = idx & 4095;
    int c = (idx >> 12) & 63;
    int b = idx >> 18;
    g_seqT[(64 + c)*MTOT + b*LSEQ + l] = tf32r(skip[idx]);
}

// ---------------------------------------------------------------------------
// 3a. k_mma0: tf32 GEMM, channel-major out. CTA 128n x 128m, 8 warps (4n x 2m).
// ---------------------------------------------------------------------------
__global__ __launch_bounds__(256, 2) void k_mma0(
    const float* __restrict__ W, const float* __restrict__ Bm,
    float* __restrict__ C, int N, int K)
{
    __shared__ float Ws[2][128][20];
    __shared__ float Bs[2][16][136];

    int tid  = threadIdx.x;
    int lane = tid & 31;
    int g    = lane >> 2;
    int tg   = lane & 3;
    int wid  = tid >> 5;
    int wm   = wid & 3;
    int wn   = wid >> 2;
    int nb   = wm * 32;
    int mb   = wn * 64;

    int m0 = blockIdx.x * 128;
    int n0 = blockIdx.y * 128;

    float d[2][8][4];
#pragma unroll
    for (int mt = 0; mt < 2; mt++)
#pragma unroll
        for (int nt = 0; nt < 8; nt++)
#pragma unroll
            for (int q = 0; q < 4; q++) d[mt][nt][q] = 0.f;

    int lb_k = tid >> 5;
    int lb_m = (tid & 31) * 4;
    int lw_n = tid >> 1;
    int lw_k = (tid & 1) * 8;

    unsigned int sB = (unsigned int)__cvta_generic_to_shared(&Bs[0][lb_k][lb_m]);
    unsigned int sW = (unsigned int)__cvta_generic_to_shared(&Ws[0][lw_n][lw_k]);
    const unsigned int bufB = 16*136*4;
    const unsigned int bufW = 128*20*4;
    const unsigned int rowB = 8*136*4;

    const float* gB = Bm + (size_t)lb_k*MTOT + m0 + lb_m;
    const float* gW = W + (size_t)(n0 + lw_n)*K + lw_k;

    auto issue = [&](int buf, int k0) {
        cp_async16(sB + buf*bufB,        gB + (size_t)k0*MTOT);
        cp_async16(sB + buf*bufB + rowB, gB + (size_t)(k0 + 8)*MTOT);
        cp_async16(sW + buf*bufW,        gW + k0);
        cp_async16(sW + buf*bufW + 16,   gW + k0 + 4);
        cp_commit();
    };

    issue(0, 0);
    cp_wait0();
    __syncthreads();

    int p = 0;
    for (int k0 = 0; k0 < K; k0 += 16) {
        if (k0 + 16 < K) issue(p ^ 1, k0 + 16);

#pragma unroll
        for (int ks = 0; ks < 16; ks += 8) {
            unsigned a[2][4];
#pragma unroll
            for (int mt = 0; mt < 2; mt++) {
                int nr = nb + mt*16 + g;
                a[mt][0] = __float_as_uint(Ws[p][nr    ][ks + tg]);
                a[mt][1] = __float_as_uint(Ws[p][nr + 8][ks + tg]);
                a[mt][2] = __float_as_uint(Ws[p][nr    ][ks + tg + 4]);
                a[mt][3] = __float_as_uint(Ws[p][nr + 8][ks + tg + 4]);
            }
            unsigned bf[8][2];
#pragma unroll
            for (int nt = 0; nt < 8; nt++) {
                int mc = mb + nt*8 + g;
                bf[nt][0] = __float_as_uint(Bs[p][ks + tg    ][mc]);
                bf[nt][1] = __float_as_uint(Bs[p][ks + tg + 4][mc]);
            }
#pragma unroll
            for (int mt = 0; mt < 2; mt++)
#pragma unroll
                for (int nt = 0; nt < 8; nt++)
                    mma_tf32(d[mt][nt][0], d[mt][nt][1], d[mt][nt][2], d[mt][nt][3],
                             a[mt][0], a[mt][1], a[mt][2], a[mt][3],
                             bf[nt][0], bf[nt][1]);
        }
        cp_wait0();
        __syncthreads();
        p ^= 1;
    }

#pragma unroll
    for (int mt = 0; mt < 2; mt++) {
        int n_lo = n0 + nb + mt*16 + g;
        int n_hi = n_lo + 8;
#pragma unroll
        for (int nt = 0; nt < 8; nt++) {
            int m = m0 + mb + nt*8 + 2*tg;
            *reinterpret_cast<float2*>(C + (size_t)n_lo*MTOT + m) =
                make_float2(d[mt][nt][0], d[mt][nt][1]);
            *reinterpret_cast<float2*>(C + (size_t)n_hi*MTOT + m) =
                make_float2(d[mt][nt][2], d[mt][nt][3]);
        }
    }
}

// ---------------------------------------------------------------------------
// 3b. k_mma1: row-major [m][ldc] epilogue (out_proj).
// ---------------------------------------------------------------------------
__global__ __launch_bounds__(256, 2) void k_mma1(
    const float* __restrict__ W, const float* __restrict__ Bm,
    float* __restrict__ C, int N, int K, int ldc)
{
    __shared__ float Ws[2][128][20];
    __shared__ float Bs[2][16][136];

    int tid  = threadIdx.x;
    int lane = tid & 31;
    int g    = lane >> 2;
    int tg   = lane & 3;
    int wid  = tid >> 5;
    int wm   = wid & 3;
    int wn   = wid >> 2;
    int nb   = wm * 32;
    int mb   = wn * 64;

    int m0 = blockIdx.x * 128;
    int n0 = blockIdx.y * 128;

    float d[2][8][4];
#pragma unroll
    for (int mt = 0; mt < 2; mt++)
#pragma unroll
        for (int nt = 0; nt < 8; nt++)
#pragma unroll
            for (int q = 0; q < 4; q++) d[mt][nt][q] = 0.f;

    int lb_k = tid >> 5;
    int lb_m = (tid & 31) * 4;
    int lw_n = tid >> 1;
    int lw_k = (tid & 1) * 8;

    unsigned int sB = (unsigned int)__cvta_generic_to_shared(&Bs[0][lb_k][lb_m]);
    unsigned int sW = (unsigned int)__cvta_generic_to_shared(&Ws[0][lw_n][lw_k]);
    const unsigned int bufB = 16*136*4;
    const unsigned int bufW = 128*20*4;
    const unsigned int rowB = 8*136*4;

    const float* gB = Bm + (size_t)lb_k*MTOT + m0 + lb_m;
    const float* gW = W + (size_t)(n0 + lw_n)*K + lw_k;

    auto issue = [&](int buf, int k0) {
        cp_async16(sB + buf*bufB,        gB + (size_t)k0*MTOT);
        cp_async16(sB + buf*bufB + rowB, gB + (size_t)(k0 + 8)*MTOT);
        cp_async16(sW + buf*bufW,        gW + k0);
        cp_async16(sW + buf*bufW + 16,   gW + k0 + 4);
        cp_commit();
    };

    issue(0, 0);
    cp_wait0();
    __syncthreads();

    int p = 0;
    for (int k0 = 0; k0 < K; k0 += 16) {
        if (k0 + 16 < K) issue(p ^ 1, k0 + 16);

#pragma unroll
        for (int ks = 0; ks < 16; ks += 8) {
            unsigned a[2][4];
#pragma unroll
            for (int mt = 0; mt < 2; mt++) {
                int nr = nb + mt*16 + g;
                a[mt][0] = __float_as_uint(Ws[p][nr    ][ks + tg]);
                a[mt][1] = __float_as_uint(Ws[p][nr + 8][ks + tg]);
                a[mt][2] = __float_as_uint(Ws[p][nr    ][ks + tg + 4]);
                a[mt][3] = __float_as_uint(Ws[p][nr + 8][ks + tg + 4]);
            }
            unsigned bf[8][2];
#pragma unroll
            for (int nt = 0; nt < 8; nt++) {
                int mc = mb + nt*8 + g;
                bf[nt][0] = __float_as_uint(Bs[p][ks + tg    ][mc]);
                bf[nt][1] = __float_as_uint(Bs[p][ks + tg + 4][mc]);
            }
#pragma unroll
            for (int mt = 0; mt < 2; mt++)
#pragma unroll
                for (int nt = 0; nt < 8; nt++)
                    mma_tf32(d[mt][nt][0], d[mt][nt][1], d[mt][nt][2], d[mt][nt][3],
                             a[mt][0], a[mt][1], a[mt][2], a[mt][3],
                             bf[nt][0], bf[nt][1]);
        }
        cp_wait0();
        __syncthreads();
        p ^= 1;
    }

#pragma unroll
    for (int mt = 0; mt < 2; mt++) {
        int n_lo = n0 + nb + mt*16 + g;
        int n_hi = n_lo + 8;
#pragma unroll
        for (int nt = 0; nt < 8; nt++) {
            int m = m0 + mb + nt*8 + 2*tg;
            C[(size_t)m*ldc + n_lo]       = d[mt][nt][0];
            C[(size_t)(m+1)*ldc + n_lo]   = d[mt][nt][1];
            C[(size_t)m*ldc + n_hi]       = d[mt][nt][2];
            C[(size_t)(m+1)*ldc + n_hi]   = d[mt][nt][3];
        }
    }
}

// ---------------------------------------------------------------------------
// 3c. k_mma2: tf32 GEMM for convout. 64-n block (2n x 4m warps), NCHW + bias.
// ---------------------------------------------------------------------------
__global__ __launch_bounds__(256, 2) void k_mma2(
    const float* __restrict__ W, const float* __restrict__ Bm,
    float* __restrict__ C, const float* __restrict__ bias, int N, int K)
{
    __shared__ float Ws[2][64][20];
    __shared__ float Bs[2][16][136];

    int tid  = threadIdx.x;
    int lane = tid & 31;
    int g    = lane >> 2;
    int tg   = lane & 3;
    int wid  = tid >> 5;
    int wm   = wid & 1;
    int wn   = wid >> 1;
    int nb   = wm * 32;
    int mb   = wn * 32;

    int m0 = blockIdx.x * 128;

    float d[2][4][4];
#pragma unroll
    for (int mt = 0; mt < 2; mt++)
#pragma unroll
        for (int nt = 0; nt < 4; nt++)
#pragma unroll
            for (int q = 0; q < 4; q++) d[mt][nt][q] = 0.f;

    int lb_k = tid >> 5;
    int lb_m = (tid & 31) * 4;
    int lw_n = tid >> 2;
    int lw_k = (tid & 3) * 4;

    unsigned int sB = (unsigned int)__cvta_generic_to_shared(&Bs[0][lb_k][lb_m]);
    unsigned int sW = (unsigned int)__cvta_generic_to_shared(&Ws[0][lw_n][lw_k]);
    const unsigned int bufB = 16*136*4;
    const unsigned int bufW = 64*20*4;
    const unsigned int rowB = 8*136*4;

    const float* gB = Bm + (size_t)lb_k*MTOT + m0 + lb_m;
    const float* gW = W + (size_t)lw_n*K + lw_k;

    auto issue = [&](int buf, int k0) {
        cp_async16(sB + buf*bufB,        gB + (size_t)k0*MTOT);
        cp_async16(sB + buf*bufB + rowB, gB + (size_t)(k0 + 8)*MTOT);
        cp_async16(sW + buf*bufW,        gW + k0);
        cp_commit();
    };

    issue(0, 0);
    cp_wait0();
    __syncthreads();

    int p = 0;
    for (int k0 = 0; k0 < K; k0 += 16) {
        if (k0 + 16 < K) issue(p ^ 1, k0 + 16);

#pragma unroll
        for (int ks = 0; ks < 16; ks += 8) {
            unsigned a[2][4];
#pragma unroll
            for (int mt = 0; mt < 2; mt++) {
                int nr = nb + mt*16 + g;
                a[mt][0] = __float_as_uint(Ws[p][nr    ][ks + tg]);
                a[mt][1] = __float_as_uint(Ws[p][nr + 8][ks + tg]);
                a[mt][2] = __float_as_uint(Ws[p][nr    ][ks + tg + 4]);
                a[mt][3] = __float_as_uint(Ws[p][nr + 8][ks + tg + 4]);
            }
            unsigned bf[4][2];
#pragma unroll
            for (int nt = 0; nt < 4; nt++) {
                int mc = mb + nt*8 + g;
                bf[nt][0] = __float_as_uint(Bs[p][ks + tg    ][mc]);
                bf[nt][1] = __float_as_uint(Bs[p][ks + tg + 4][mc]);
            }
#pragma unroll
            for (int mt = 0; mt < 2; mt++)
#pragma unroll
                for (int nt = 0; nt < 4; nt++)
                    mma_tf32(d[mt][nt][0], d[mt][nt][1], d[mt][nt][2], d[mt][nt][3],
                             a[mt][0], a[mt][1], a[mt][2], a[mt][3],
                             bf[nt][0], bf[nt][1]);
        }
        cp_wait0();
        __syncthreads();
        p ^= 1;
    }

    int bidx = m0 >> 12;
    int lbase = (m0 & 4095);
#pragma unroll
    for (int mt = 0; mt < 2; mt++) {
        int n_lo = nb + mt*16 + g;
        int n_hi = n_lo + 8;
        float bl = bias[n_lo], bh = bias[n_hi];
#pragma unroll
        for (int nt = 0; nt < 4; nt++) {
            int l = lbase + mb + nt*8 + 2*tg;
            *reinterpret_cast<float2*>(C + (size_t)bidx*N*4096 + (size_t)n_lo*4096 + l) =
                make_float2(d[mt][nt][0] + bl, d[mt][nt][1] + bl);
            *reinterpret_cast<float2*>(C + (size_t)bidx*N*4096 + (size_t)n_hi*4096 + l) =
                make_float2(d[mt][nt][2] + bh, d[mt][nt][3] + bh);
        }
    }
}

// ---------------------------------------------------------------------------
// 3d. k_mma3: tf32 GEMM for x_proj. W = g_wrnd4 (64x256, rows>=40 zero).
//     64-n block (2n x 4m warps). Row-major [m][40] epilogue, n<40 guard.
// ---------------------------------------------------------------------------
__global__ __launch_bounds__(256, 2) void k_mma3(
    const float* __restrict__ W, const float* __restrict__ Bm,
    float* __restrict__ C, int K)
{
    __shared__ float Ws[2][64][20];
    __shared__ float Bs[2][16][136];

    int tid  = threadIdx.x;
    int lane = tid & 31;
    int g    = lane >> 2;
    int tg   = lane & 3;
    int wid  = tid >> 5;
    int wm   = wid & 1;
    int wn   = wid >> 1;
    int nb   = wm * 32;
    int mb   = wn * 32;

    int m0 = blockIdx.x * 128;

    float d[2][4][4];
#pragma unroll
    for (int mt = 0; mt < 2; mt++)
#pragma unroll
        for (int nt = 0; nt < 4; nt++)
#pragma unroll
            for (int q = 0; q < 4; q++) d[mt][nt][q] = 0.f;

    int lb_k = tid >> 5;
    int lb_m = (tid & 31) * 4;
    int lw_n = tid >> 2;
    int lw_k = (tid & 3) * 4;

    unsigned int sB = (unsigned int)__cvta_generic_to_shared(&Bs[0][lb_k][lb_m]);
    unsigned int sW = (unsigned int)__cvta_generic_to_shared(&Ws[0][lw_n][lw_k]);
    const unsigned int bufB = 16*136*4;
    const unsigned int bufW = 64*20*4;
    const unsigned int rowB = 8*136*4;

    const float* gB = Bm + (size_t)lb_k*MTOT + m0 + lb_m;
    const float* gW = W + (size_t)lw_n*K + lw_k;

    auto issue = [&](int buf, int k0) {
        cp_async16(sB + buf*bufB,        gB + (size_t)k0*MTOT);
        cp_async16(sB + buf*bufB + rowB, gB + (size_t)(k0 + 8)*MTOT);
        cp_async16(sW + buf*bufW,        gW + k0);
        cp_commit();
    };

    issue(0, 0);
    cp_wait0();
    __syncthreads();

    int p = 0;
    for (int k0 = 0; k0 < K; k0 += 16) {
        if (k0 + 16 < K) issue(p ^ 1, k0 + 16);

#pragma unroll
        for (int ks = 0; ks < 16; ks += 8) {
            unsigned a[2][4];
#pragma unroll
            for (int mt = 0; mt < 2; mt++) {
                int nr = nb + mt*16 + g;
                a[mt][0] = __float_as_uint(Ws[p][nr    ][ks + tg]);
                a[mt][1] = __float_as_uint(Ws[p][nr + 8][ks + tg]);
                a[mt][2] = __float_as_uint(Ws[p][nr    ][ks + tg + 4]);
                a[mt][3] = __float_as_uint(Ws[p][nr + 8][ks + tg + 4]);
            }
            unsigned bf[4][2];
#pragma unroll
            for (int nt = 0; nt < 4; nt++) {
                int mc = mb + nt*8 + g;
                bf[nt][0] = __float_as_uint(Bs[p][ks + tg    ][mc]);
                bf[nt][1] = __float_as_uint(Bs[p][ks + tg + 4][mc]);
            }
#pragma unroll
            for (int mt = 0; mt < 2; mt++)
#pragma unroll
                for (int nt = 0; nt < 4; nt++)
                    mma_tf32(d[mt][nt][0], d[mt][nt][1], d[mt][nt][2], d[mt][nt][3],
                             a[mt][0], a[mt][1], a[mt][2], a[mt][3],
                             bf[nt][0], bf[nt][1]);
        }
        cp_wait0();
        __syncthreads();
        p ^= 1;
    }

    // row-major epilogue C[m][40], guard n < 40
#pragma unroll
    for (int mt = 0; mt < 2; mt++) {
        int n_lo = nb + mt*16 + g;
        int n_hi = n_lo + 8;
#pragma unroll
        for (int nt = 0; nt < 4; nt++) {
            int m = m0 + mb + nt*8 + 2*tg;
            if (n_lo < 40) {
                C[(size_t)m*40 + n_lo]     = d[mt][nt][0];
                C[(size_t)(m+1)*40 + n_lo] = d[mt][nt][1];
            }
            if (n_hi < 40) {
                C[(size_t)m*40 + n_hi]     = d[mt][nt][2];
                C[(size_t)(m+1)*40 + n_hi] = d[mt][nt][3];
            }
        }
    }
}

// ---------------------------------------------------------------------------
// 4. depthwise causal conv1d (D_CONV=4) + bias + silu — float4 vectorized
//    thread handles 4 consecutive m. grid (16, 256)
// ---------------------------------------------------------------------------
__global__ __launch_bounds__(256) void k_conv1d_silu(const float* __restrict__ cw,
                                                     const float* __restrict__ cb)
{
    int d = blockIdx.y;
    int m4 = (blockIdx.x*256 + threadIdx.x) * 4;
    int l = m4 & 4095;
    const float* row = g_xzT + (size_t)d*MTOT;

    float w0 = cw[d*4+0], w1 = cw[d*4+1], w2 = cw[d*4+2], w3 = cw[d*4+3];
    float bb = cb[d];

    float4 cur = *reinterpret_cast<const float4*>(row + m4);
    float4 prv = make_float4(0.f, 0.f, 0.f, 0.f);
    if (l >= 4) prv = *reinterpret_cast<const float4*>(row + m4 - 4);

    float x0 = prv.y, x1 = prv.z, x2 = prv.w;   // m-3, m-2, m-1
    float r0 = bb + w0*x0 + w1*x1 + w2*x2 + w3*cur.x;
    float r1 = bb + w0*x1 + w1*x2 + w2*cur.x + w3*cur.y;
    float r2 = bb + w0*x2 + w1*cur.x + w2*cur.y + w3*cur.z;
    float r3 = bb + w0*cur.x + w1*cur.y + w2*cur.z + w3*cur.w;

    *reinterpret_cast<float4*>(g_uT + (size_t)d*MTOT + m4) =
        make_float4(silu_f(r0), silu_f(r1), silu_f(r2), silu_f(r3));
}

// ---------------------------------------------------------------------------
// 5. delta = softplus(dt @ dt_proj_w.T + dt_proj_b) -> g_deltaT [d][m]
// ---------------------------------------------------------------------------
__global__ void k_delta(const float* __restrict__ dtw,
                        const float* __restrict__ dtb)
{
    __shared__ float sdt[64][8];
    int tid = threadIdx.x;
    int m0 = blockIdx.x*64;
    for (int i = tid; i < 512; i += 256) {
        int ml = i >> 3, r = i & 7;
        sdt[ml][r] = g_dbc[(size_t)(m0 + ml)*40 + r];
    }
    __syncthreads();
    int ml = tid & 63;
    int dl = tid >> 6;
    for (int it = 0; it < 64; it++) {
        int d = it*4 + dl;
        const float* wr = dtw + d*8;
        float x = dtb[d];
#pragma unroll
        for (int r = 0; r < 8; r++) x += wr[r]*sdt[ml][r];
        float sp = (x > 20.f) ? x : log1pf(__expf(x));
        g_deltaT[(size_t)d*MTOT + m0 + ml] = sp;
    }
}

// ---------------------------------------------------------------------------
// 6. scan pass 1
// ---------------------------------------------------------------------------
__global__ __launch_bounds__(128) void k_scan1(const float* __restrict__ A_log)
{
    int lane = threadIdx.x & 31;
    int wgid = blockIdx.x*4 + (threadIdx.x >> 5);
    int ch = wgid & 63;
    int dp = (wgid >> 6) & 127;
    int b  = wgid >> 13;
    int dd = lane >> 4, n = lane & 15;
    int d  = dp*2 + dd;

    float A = -__expf(A_log[d*DSTATE + n]);
    int m0 = b*LSEQ + ch*LCHUNK;
    const float* drow = g_deltaT + (size_t)d*MTOT;
    const float* urow = g_uT     + (size_t)d*MTOT;
    const float* dbc  = g_dbc;

    float h = 0.f, sumd = 0.f;
#pragma unroll 8
    for (int l = 0; l < LCHUNK; l++) {
        int m = m0 + l;
        float dt = drow[m];
        float uu = urow[m];
        float Bn = dbc[(size_t)m*40 + 8 + n];
        h = __expf(dt*A)*h + dt*Bn*uu;
        sumd += dt;
    }
    int bd = b*DINNER + d;
    g_hend[((size_t)bd*NCHUNK + ch)*DSTATE + n] = h;
    if (n == 0) g_sumd[(size_t)bd*NCHUNK + ch] = sumd;
}

// ---------------------------------------------------------------------------
// 7. scan pass 2
// ---------------------------------------------------------------------------
__global__ void k_scan2(const float* __restrict__ A_log)
{
    int gt = blockIdx.x*256 + threadIdx.x;
    int w  = gt >> 5;
    int lane = gt & 31;
    int dd = lane >> 4, n = lane & 15;
    int bd = w*2 + dd;
    int d  = bd & 255;

    float A = -__expf(A_log[d*DSTATE + n]);
    float h = 0.f;
    for (int ch = 0; ch < NCHUNK; ch++) {
        size_t base = ((size_t)bd*NCHUNK + ch)*DSTATE + n;
        g_hin[base] = h;
        float sd = g_sumd[(size_t)bd*NCHUNK + ch];
        h = __expf(sd*A)*h + g_hend[base];
    }
}

// ---------------------------------------------------------------------------
// 8. scan pass 3: rescan; y=(h.C + u*Dp)*silu(z), tf32-rounded
// ---------------------------------------------------------------------------
__global__ __launch_bounds__(128) void k_scan3(const float* __restrict__ A_log,
                                               const float* __restrict__ Dp)
{
    int lane = threadIdx.x & 31;
    int wgid = blockIdx.x*4 + (threadIdx.x >> 5);
    int ch = wgid & 63;
    int dp = (wgid >> 6) & 127;
    int b  = wgid >> 13;
    int dd = lane >> 4, n = lane & 15;
    int d  = dp*2 + dd;
    int bd = b*DINNER + d;

    float A = -__expf(A_log[d*DSTATE + n]);
    float Dd = Dp[d];
    int m0 = b*LSEQ + ch*LCHUNK;
    const float* drow = g_deltaT + (size_t)d*MTOT;
    const float* urow = g_uT     + (size_t)d*MTOT;
    const float* zrow = g_xzT    + (size_t)(DINNER + d)*MTOT;
    const float* dbc  = g_dbc;
    float*       yrow = g_yT     + (size_t)d*MTOT;

    float h = g_hin[((size_t)bd*NCHUNK + ch)*DSTATE + n];

#pragma unroll 4
    for (int l = 0; l < LCHUNK; l++) {
        int m = m0 + l;
        float dt = drow[m];
        float uu = urow[m];
        float Bn = dbc[(size_t)m*40 + 8 + n];
        float Cn = dbc[(size_t)m*40 + 24 + n];
        h = __expf(dt*A)*h + dt*Bn*uu;
        float y = h*Cn;
        y += __shfl_xor_sync(0xffffffffu, y, 8, 16);
        y += __shfl_xor_sync(0xffffffffu, y, 4, 16);
        y += __shfl_xor_sync(0xffffffffu, y, 2, 16);
        y += __shfl_xor_sync(0xffffffffu, y, 1, 16);
        if (n == 0) {
            float z = zrow[m];
            yrow[m] = tf32r((y + uu*Dd) * silu_f(z));
        }
    }
}

// ---------------------------------------------------------------------------
// 9. LayerNorm over 128 channels + silu ; channel-major tf32 out
// ---------------------------------------------------------------------------
__global__ __launch_bounds__(256) void k_ln_silu(const float* __restrict__ gamma,
                                                 const float* __restrict__ beta)
{
    __shared__ float sT[128][36];
    int tid = threadIdx.x;
    int wid = tid >> 5, lane = tid & 31;
    int m_base = blockIdx.x*32;

    for (int r = 0; r < 4; r++) {
        int mloc = r*8 + wid;
        int m = m_base + mloc;
        float4 v = *reinterpret_cast<const float4*>(g_ym + (size_t)m*128 + lane*4);
        float s  = v.x + v.y + v.z + v.w;
        float s2 = v.x*v.x + v.y*v.y + v.z*v.z + v.w*v.w;
#pragma unroll
        for (int k = 16; k >= 1; k >>= 1) {
            s  += __shfl_xor_sync(0xffffffffu, s,  k);
            s2 += __shfl_xor_sync(0xffffffffu, s2, k);
        }
        float mean = s * (1.f/128.f);
        float var  = s2 * (1.f/128.f) - mean*mean;
        float rstd = rsqrtf(var + 1e-5f);
        float va[4] = {v.x, v.y, v.z, v.w};
#pragma unroll
        for (int i = 0; i < 4; i++) {
            int c = lane*4 + i;
            float t = (va[i] - mean)*rstd*gamma[c] + beta[c];
            sT[c][mloc] = tf32r(silu_f(t));
        }
    }
    __syncthreads();

    int mq = tid & 7;
    int c0 = tid >> 3;
    for (int cc = c0; cc < 128; cc += 32) {
        float4 v = *reinterpret_cast<const float4*>(&sT[cc][mq*4]);
        *reinterpret_cast<float4*>(g_lnT + (size_t)cc*MTOT + m_base + mq*4) = v;
    }
}

// ---------------------------------------------------------------------------
extern "C" void kernel_launch(void* const* d_in, const int* in_sizes, int n_in,
                              void* d_out, int out_size)
{
    const float* x        = (const float*)d_in[0];
    const float* skip_x   = (const float*)d_in[1];
    const float* up_w     = (const float*)d_in[2];
    const float* up_b     = (const float*)d_in[3];
    const float* in_proj  = (const float*)d_in[4];
    const float* conv1d_w = (const float*)d_in[5];
    const float* conv1d_b = (const float*)d_in[6];
    const float* x_proj   = (const float*)d_in[7];
    const float* dt_proj_w= (const float*)d_in[8];
    const float* dt_proj_b= (const float*)d_in[9];
    const float* A_log    = (const float*)d_in[10];
    const float* Dp       = (const float*)d_in[11];
    const float* out_proj = (const float*)d_in[12];
    const float* ln_gamma = (const float*)d_in[13];
    const float* ln_beta  = (const float*)d_in[14];
    const float* convout_w= (const float*)d_in[15];
    const float* convout_b= (const float*)d_in[16];
    float* out = (float*)d_out;

    float *p_seqT, *p_xzT, *p_uT, *p_yT, *p_lnT, *p_dbc, *p_ym;
    float *p_wrnd, *p_wrnd2, *p_wrnd3, *p_wrnd4;
    cudaGetSymbolAddress((void**)&p_seqT, g_seqT);
    cudaGetSymbolAddress((void**)&p_xzT,  g_xzT);
    cudaGetSymbolAddress((void**)&p_uT,   g_uT);
    cudaGetSymbolAddress((void**)&p_yT,   g_yT);
    cudaGetSymbolAddress((void**)&p_lnT,  g_lnT);
    cudaGetSymbolAddress((void**)&p_dbc,  g_dbc);
    cudaGetSymbolAddress((void**)&p_ym,   g_ym);
    cudaGetSymbolAddress((void**)&p_wrnd,  g_wrnd);
    cudaGetSymbolAddress((void**)&p_wrnd2, g_wrnd2);
    cudaGetSymbolAddress((void**)&p_wrnd3, g_wrnd3);
    cudaGetSymbolAddress((void**)&p_wrnd4, g_wrnd4);

    // 0: merged prep (1 launch)
    k_prep<<<608, 256>>>(up_w, in_proj, out_proj, convout_w, x_proj);
    // 1-2: build seq
    k_upsample<<<BATCH*64, 256>>>(x, up_b);
    k_copy_skip<<<(BATCH*64*4096)/256, 256>>>(skip_x);

    // 3: in_proj (N=512, K=128) -> g_xzT channel-major [tf32]
    k_mma0<<<dim3(MTOT/128, 4), 256>>>(p_wrnd, p_seqT, p_xzT, 512, 128);

    // 4: conv1d + silu -> g_uT (fp32)
    k_conv1d_silu<<<dim3(16, DINNER), 256>>>(conv1d_w, conv1d_b);

    // 5: x_proj (N=40 padded to 64, K=256) -> g_dbc row-major [m][40]  [tf32]
    k_mma3<<<MTOT/128, 256>>>(p_wrnd4, p_uT, p_dbc, 256);

    // 6: delta
    k_delta<<<MTOT/64, 256>>>(dt_proj_w, dt_proj_b);

    // 7-9: chunked selective scan (fp32)
    k_scan1<<<8192, 128>>>(A_log);
    k_scan2<<<64, 256>>>(A_log);
    k_scan3<<<8192, 128>>>(A_log, Dp);

    // 10: out_proj (N=128, K=256) -> g_ym row-major [m][128]  [tf32]
    k_mma1<<<dim3(MTOT/128, 1), 256>>>(p_wrnd2, p_yT, p_ym, 128, 256, 128);

    // 11: LayerNorm + silu -> g_lnT channel-major (tf32)
    k_ln_silu<<<MTOT/32, 256>>>(ln_gamma, ln_beta);

    // 12: convout 1x1 (N=64, K=128) -> d_out NCHW + bias  [tf32]
    k_mma2<<<dim3(MTOT/128, 1), 256>>>(p_wrnd3, p_lnT, out, convout_b, 64, 128);
}

// round 13
// speedup vs baseline: 1.3296x; 1.0514x over previous
#include <cuda_runtime.h>
#include <stdint.h>
#include <math.h>

#define BATCH   4
#define LSEQ    4096
#define MTOT    16384          // BATCH*LSEQ
#define DMODEL  128
#define DINNER  256
#define DSTATE  16
#define NCHUNK  64
#define LCHUNK  64

// ---------------- static scratch (no cudaMalloc anywhere) -------------------
__device__ float g_seqT  [DMODEL  * MTOT];    // [c][m] concat(up,skip) (tf32)
__device__ float g_xzT   [2*DINNER* MTOT];    // [n][m] rows 0..255 u_raw, 256..511 z
__device__ float g_uT    [DINNER  * MTOT];    // [d][m] conv1d+silu (fp32)
__device__ float g_deltaT[DINNER  * MTOT];    // [d][m]
__device__ float g_dbc   [MTOT * 40];         // [m][40]  0..7 dt, 8..23 B, 24..39 C
__device__ float g_yT    [DINNER  * MTOT];    // [d][m] scan out * silu(z) (tf32)
__device__ float g_ym    [MTOT * DMODEL];     // [m][128] out_proj out
__device__ float g_lnT   [DMODEL  * MTOT];    // [c][m] LN+silu out (tf32)
__device__ float g_hend  [BATCH*DINNER*NCHUNK*DSTATE];
__device__ float g_hin   [BATCH*DINNER*NCHUNK*DSTATE];
__device__ float g_sumd  [BATCH*DINNER*NCHUNK];
__device__ float g_upwT  [256*128];           // [o*4+ij][cin]
__device__ float g_wrnd  [512*128];           // tf32 in_proj weights
__device__ float g_wrnd2 [128*256];           // tf32 out_proj weights
__device__ float g_wrnd3 [64*128];            // tf32 convout weights
__device__ float g_wrnd4 [64*256];            // tf32 x_proj weights (rows 40..63 zero)

__device__ __forceinline__ float silu_f(float x) {
    return x / (1.0f + __expf(-x));
}
__device__ __forceinline__ float tf32r(float x) {
    unsigned int u;
    asm("cvt.rna.tf32.f32 %0, %1;" : "=r"(u) : "f"(x));
    return __uint_as_float(u);
}

__device__ __forceinline__ void cp_async16(unsigned int s, const void* g) {
    asm volatile("cp.async.cg.shared.global [%0], [%1], 16;" :: "r"(s), "l"(g));
}
__device__ __forceinline__ void cp_commit() {
    asm volatile("cp.async.commit_group;" ::: "memory");
}
__device__ __forceinline__ void cp_wait0() {
    asm volatile("cp.async.wait_group 0;" ::: "memory");
}

__device__ __forceinline__ void mma_tf32(float& d0, float& d1, float& d2, float& d3,
                                         unsigned a0, unsigned a1, unsigned a2, unsigned a3,
                                         unsigned b0, unsigned b1)
{
    asm volatile(
        "mma.sync.aligned.m16n8k8.row.col.f32.tf32.tf32.f32 "
        "{%0,%1,%2,%3}, {%4,%5,%6,%7}, {%8,%9}, {%0,%1,%2,%3};"
        : "+f"(d0), "+f"(d1), "+f"(d2), "+f"(d3)
        : "r"(a0), "r"(a1), "r"(a2), "r"(a3), "r"(b0), "r"(b1));
}

// ---------------------------------------------------------------------------
// 0. merged front-end: upsample + copy_skip + weight prep in one launch.
//    bx in [0,256)     : upsample
//    bx in [256,4352)  : copy skip
//    bx in [4352,4960) : weight rounding (g_upwT written by k_transpose_upw first)
// ---------------------------------------------------------------------------
__global__ __launch_bounds__(256) void k_front(
    const float* __restrict__ x, const float* __restrict__ upb,
    const float* __restrict__ skip,
    const float* __restrict__ w_in,
    const float* __restrict__ w_out,
    const float* __restrict__ w_co,
    const float* __restrict__ w_xp)
{
    int bx = blockIdx.x;
    int t  = threadIdx.x;

    if (bx < 256) {
        __shared__ float xs[16][128];
        int b  = bx >> 6;
        int p0 = (bx & 63) << 4;

        for (int i = t; i < 16*128; i += 256) {
            int pix = i & 15, cin = i >> 4;
            xs[pix][cin] = x[(b*128 + cin)*1024 + p0 + pix];
        }
        __syncthreads();

        int o  = t >> 2;
        int ij = t & 3;
        int ii = ij >> 1, jj = ij & 1;

        float acc[16];
#pragma unroll
        for (int p = 0; p < 16; p++) acc[p] = 0.f;

        const float* wrow = g_upwT + t*128;
        for (int c4 = 0; c4 < 32; c4++) {
            float4 w4 = *reinterpret_cast<const float4*>(wrow + c4*4);
#pragma unroll
            for (int p = 0; p < 16; p++) {
                float4 x4 = *reinterpret_cast<const float4*>(&xs[p][c4*4]);
                acc[p] += x4.x*w4.x + x4.y*w4.y + x4.z*w4.z + x4.w*w4.w;
            }
        }
        float bias = upb[o];
#pragma unroll
        for (int p = 0; p < 16; p++) {
            int hp = (p0 + p) >> 5, wp = (p0 + p) & 31;
            int l  = (2*hp + ii)*64 + 2*wp + jj;
            g_seqT[o*MTOT + b*LSEQ + l] = tf32r(acc[p] + bias);
        }
    } else if (bx < 4352) {
        int idx = (bx - 256)*256 + t;
        int l = idx & 4095;
        int c = (idx >> 12) & 63;
        int b = idx >> 18;
        g_seqT[(64 + c)*MTOT + b*LSEQ + l] = tf32r(skip[idx]);
    } else {
        int sb = bx - 4352;
        if (sb < 256) {
            int i = sb*256 + t;
            g_wrnd[i] = tf32r(w_in[i]);
        } else if (sb < 384) {
            int i = (sb - 256)*256 + t;
            g_wrnd2[i] = tf32r(w_out[i]);
        } else if (sb < 416) {
            int i = (sb - 384)*256 + t;
            g_wrnd3[i] = tf32r(w_co[i]);
        } else if (sb < 480) {
            int i = (sb - 416)*256 + t;
            int row = i >> 8;
            g_wrnd4[i] = (row < 40) ? tf32r(w_xp[row*256 + (i & 255)]) : 0.f;
        }
    }
}

// up_w transpose — must precede k_front's upsample segment (separate launch).
__global__ void k_transpose_upw(const float* __restrict__ upw)
{
    int cin = blockIdx.x;
    int n   = threadIdx.x;
    g_upwT[n*128 + cin] = upw[cin*256 + n];
}

// ---------------------------------------------------------------------------
// 3a. k_mma0: tf32 GEMM, channel-major out. CTA 128n x 128m, 8 warps (4n x 2m).
// ---------------------------------------------------------------------------
__global__ __launch_bounds__(256, 2) void k_mma0(
    const float* __restrict__ W, const float* __restrict__ Bm,
    float* __restrict__ C, int N, int K)
{
    __shared__ float Ws[2][128][20];
    __shared__ float Bs[2][16][136];

    int tid  = threadIdx.x;
    int lane = tid & 31;
    int g    = lane >> 2;
    int tg   = lane & 3;
    int wid  = tid >> 5;
    int wm   = wid & 3;
    int wn   = wid >> 2;
    int nb   = wm * 32;
    int mb   = wn * 64;

    int m0 = blockIdx.x * 128;
    int n0 = blockIdx.y * 128;

    float d[2][8][4];
#pragma unroll
    for (int mt = 0; mt < 2; mt++)
#pragma unroll
        for (int nt = 0; nt < 8; nt++)
#pragma unroll
            for (int q = 0; q < 4; q++) d[mt][nt][q] = 0.f;

    int lb_k = tid >> 5;
    int lb_m = (tid & 31) * 4;
    int lw_n = tid >> 1;
    int lw_k = (tid & 1) * 8;

    unsigned int sB = (unsigned int)__cvta_generic_to_shared(&Bs[0][lb_k][lb_m]);
    unsigned int sW = (unsigned int)__cvta_generic_to_shared(&Ws[0][lw_n][lw_k]);
    const unsigned int bufB = 16*136*4;
    const unsigned int bufW = 128*20*4;
    const unsigned int rowB = 8*136*4;

    const float* gB = Bm + (size_t)lb_k*MTOT + m0 + lb_m;
    const float* gW = W + (size_t)(n0 + lw_n)*K + lw_k;

    auto issue = [&](int buf, int k0) {
        cp_async16(sB + buf*bufB,        gB + (size_t)k0*MTOT);
        cp_async16(sB + buf*bufB + rowB, gB + (size_t)(k0 + 8)*MTOT);
        cp_async16(sW + buf*bufW,        gW + k0);
        cp_async16(sW + buf*bufW + 16,   gW + k0 + 4);
        cp_commit();
    };

    issue(0, 0);
    cp_wait0();
    __syncthreads();

    int p = 0;
    for (int k0 = 0; k0 < K; k0 += 16) {
        if (k0 + 16 < K) issue(p ^ 1, k0 + 16);

#pragma unroll
        for (int ks = 0; ks < 16; ks += 8) {
            unsigned a[2][4];
#pragma unroll
            for (int mt = 0; mt < 2; mt++) {
                int nr = nb + mt*16 + g;
                a[mt][0] = __float_as_uint(Ws[p][nr    ][ks + tg]);
                a[mt][1] = __float_as_uint(Ws[p][nr + 8][ks + tg]);
                a[mt][2] = __float_as_uint(Ws[p][nr    ][ks + tg + 4]);
                a[mt][3] = __float_as_uint(Ws[p][nr + 8][ks + tg + 4]);
            }
            unsigned bf[8][2];
#pragma unroll
            for (int nt = 0; nt < 8; nt++) {
                int mc = mb + nt*8 + g;
                bf[nt][0] = __float_as_uint(Bs[p][ks + tg    ][mc]);
                bf[nt][1] = __float_as_uint(Bs[p][ks + tg + 4][mc]);
            }
#pragma unroll
            for (int mt = 0; mt < 2; mt++)
#pragma unroll
                for (int nt = 0; nt < 8; nt++)
                    mma_tf32(d[mt][nt][0], d[mt][nt][1], d[mt][nt][2], d[mt][nt][3],
                             a[mt][0], a[mt][1], a[mt][2], a[mt][3],
                             bf[nt][0], bf[nt][1]);
        }
        cp_wait0();
        __syncthreads();
        p ^= 1;
    }

#pragma unroll
    for (int mt = 0; mt < 2; mt++) {
        int n_lo = n0 + nb + mt*16 + g;
        int n_hi = n_lo + 8;
#pragma unroll
        for (int nt = 0; nt < 8; nt++) {
            int m = m0 + mb + nt*8 + 2*tg;
            *reinterpret_cast<float2*>(C + (size_t)n_lo*MTOT + m) =
                make_float2(d[mt][nt][0], d[mt][nt][1]);
            *reinterpret_cast<float2*>(C + (size_t)n_hi*MTOT + m) =
                make_float2(d[mt][nt][2], d[mt][nt][3]);
        }
    }
}

// ---------------------------------------------------------------------------
// 3b. k_mma1: row-major [m][ldc] epilogue (out_proj).
// ---------------------------------------------------------------------------
__global__ __launch_bounds__(256, 2) void k_mma1(
    const float* __restrict__ W, const float* __restrict__ Bm,
    float* __restrict__ C, int N, int K, int ldc)
{
    __shared__ float Ws[2][128][20];
    __shared__ float Bs[2][16][136];

    int tid  = threadIdx.x;
    int lane = tid & 31;
    int g    = lane >> 2;
    int tg   = lane & 3;
    int wid  = tid >> 5;
    int wm   = wid & 3;
    int wn   = wid >> 2;
    int nb   = wm * 32;
    int mb   = wn * 64;

    int m0 = blockIdx.x * 128;
    int n0 = blockIdx.y * 128;

    float d[2][8][4];
#pragma unroll
    for (int mt = 0; mt < 2; mt++)
#pragma unroll
        for (int nt = 0; nt < 8; nt++)
#pragma unroll
            for (int q = 0; q < 4; q++) d[mt][nt][q] = 0.f;

    int lb_k = tid >> 5;
    int lb_m = (tid & 31) * 4;
    int lw_n = tid >> 1;
    int lw_k = (tid & 1) * 8;

    unsigned int sB = (unsigned int)__cvta_generic_to_shared(&Bs[0][lb_k][lb_m]);
    unsigned int sW = (unsigned int)__cvta_generic_to_shared(&Ws[0][lw_n][lw_k]);
    const unsigned int bufB = 16*136*4;
    const unsigned int bufW = 128*20*4;
    const unsigned int rowB = 8*136*4;

    const float* gB = Bm + (size_t)lb_k*MTOT + m0 + lb_m;
    const float* gW = W + (size_t)(n0 + lw_n)*K + lw_k;

    auto issue = [&](int buf, int k0) {
        cp_async16(sB + buf*bufB,        gB + (size_t)k0*MTOT);
        cp_async16(sB + buf*bufB + rowB, gB + (size_t)(k0 + 8)*MTOT);
        cp_async16(sW + buf*bufW,        gW + k0);
        cp_async16(sW + buf*bufW + 16,   gW + k0 + 4);
        cp_commit();
    };

    issue(0, 0);
    cp_wait0();
    __syncthreads();

    int p = 0;
    for (int k0 = 0; k0 < K; k0 += 16) {
        if (k0 + 16 < K) issue(p ^ 1, k0 + 16);

#pragma unroll
        for (int ks = 0; ks < 16; ks += 8) {
            unsigned a[2][4];
#pragma unroll
            for (int mt = 0; mt < 2; mt++) {
                int nr = nb + mt*16 + g;
                a[mt][0] = __float_as_uint(Ws[p][nr    ][ks + tg]);
                a[mt][1] = __float_as_uint(Ws[p][nr + 8][ks + tg]);
                a[mt][2] = __float_as_uint(Ws[p][nr    ][ks + tg + 4]);
                a[mt][3] = __float_as_uint(Ws[p][nr + 8][ks + tg + 4]);
            }
            unsigned bf[8][2];
#pragma unroll
            for (int nt = 0; nt < 8; nt++) {
                int mc = mb + nt*8 + g;
                bf[nt][0] = __float_as_uint(Bs[p][ks + tg    ][mc]);
                bf[nt][1] = __float_as_uint(Bs[p][ks + tg + 4][mc]);
            }
#pragma unroll
            for (int mt = 0; mt < 2; mt++)
#pragma unroll
                for (int nt = 0; nt < 8; nt++)
                    mma_tf32(d[mt][nt][0], d[mt][nt][1], d[mt][nt][2], d[mt][nt][3],
                             a[mt][0], a[mt][1], a[mt][2], a[mt][3],
                             bf[nt][0], bf[nt][1]);
        }
        cp_wait0();
        __syncthreads();
        p ^= 1;
    }

#pragma unroll
    for (int mt = 0; mt < 2; mt++) {
        int n_lo = n0 + nb + mt*16 + g;
        int n_hi = n_lo + 8;
#pragma unroll
        for (int nt = 0; nt < 8; nt++) {
            int m = m0 + mb + nt*8 + 2*tg;
            C[(size_t)m*ldc + n_lo]       = d[mt][nt][0];
            C[(size_t)(m+1)*ldc + n_lo]   = d[mt][nt][1];
            C[(size_t)m*ldc + n_hi]       = d[mt][nt][2];
            C[(size_t)(m+1)*ldc + n_hi]   = d[mt][nt][3];
        }
    }
}

// ---------------------------------------------------------------------------
// 3c. k_mma2: convout. 64-n block (2n x 4m warps), NCHW + bias.
// ---------------------------------------------------------------------------
__global__ __launch_bounds__(256, 2) void k_mma2(
    const float* __restrict__ W, const float* __restrict__ Bm,
    float* __restrict__ C, const float* __restrict__ bias, int N, int K)
{
    __shared__ float Ws[2][64][20];
    __shared__ float Bs[2][16][136];

    int tid  = threadIdx.x;
    int lane = tid & 31;
    int g    = lane >> 2;
    int tg   = lane & 3;
    int wid  = tid >> 5;
    int wm   = wid & 1;
    int wn   = wid >> 1;
    int nb   = wm * 32;
    int mb   = wn * 32;

    int m0 = blockIdx.x * 128;

    float d[2][4][4];
#pragma unroll
    for (int mt = 0; mt < 2; mt++)
#pragma unroll
        for (int nt = 0; nt < 4; nt++)
#pragma unroll
            for (int q = 0; q < 4; q++) d[mt][nt][q] = 0.f;

    int lb_k = tid >> 5;
    int lb_m = (tid & 31) * 4;
    int lw_n = tid >> 2;
    int lw_k = (tid & 3) * 4;

    unsigned int sB = (unsigned int)__cvta_generic_to_shared(&Bs[0][lb_k][lb_m]);
    unsigned int sW = (unsigned int)__cvta_generic_to_shared(&Ws[0][lw_n][lw_k]);
    const unsigned int bufB = 16*136*4;
    const unsigned int bufW = 64*20*4;
    const unsigned int rowB = 8*136*4;

    const float* gB = Bm + (size_t)lb_k*MTOT + m0 + lb_m;
    const float* gW = W + (size_t)lw_n*K + lw_k;

    auto issue = [&](int buf, int k0) {
        cp_async16(sB + buf*bufB,        gB + (size_t)k0*MTOT);
        cp_async16(sB + buf*bufB + rowB, gB + (size_t)(k0 + 8)*MTOT);
        cp_async16(sW + buf*bufW,        gW + k0);
        cp_commit();
    };

    issue(0, 0);
    cp_wait0();
    __syncthreads();

    int p = 0;
    for (int k0 = 0; k0 < K; k0 += 16) {
        if (k0 + 16 < K) issue(p ^ 1, k0 + 16);

#pragma unroll
        for (int ks = 0; ks < 16; ks += 8) {
            unsigned a[2][4];
#pragma unroll
            for (int mt = 0; mt < 2; mt++) {
                int nr = nb + mt*16 + g;
                a[mt][0] = __float_as_uint(Ws[p][nr    ][ks + tg]);
                a[mt][1] = __float_as_uint(Ws[p][nr + 8][ks + tg]);
                a[mt][2] = __float_as_uint(Ws[p][nr    ][ks + tg + 4]);
                a[mt][3] = __float_as_uint(Ws[p][nr + 8][ks + tg + 4]);
            }
            unsigned bf[4][2];
#pragma unroll
            for (int nt = 0; nt < 4; nt++) {
                int mc = mb + nt*8 + g;
                bf[nt][0] = __float_as_uint(Bs[p][ks + tg    ][mc]);
                bf[nt][1] = __float_as_uint(Bs[p][ks + tg + 4][mc]);
            }
#pragma unroll
            for (int mt = 0; mt < 2; mt++)
#pragma unroll
                for (int nt = 0; nt < 4; nt++)
                    mma_tf32(d[mt][nt][0], d[mt][nt][1], d[mt][nt][2], d[mt][nt][3],
                             a[mt][0], a[mt][1], a[mt][2], a[mt][3],
                             bf[nt][0], bf[nt][1]);
        }
        cp_wait0();
        __syncthreads();
        p ^= 1;
    }

    int bidx = m0 >> 12;
    int lbase = (m0 & 4095);
#pragma unroll
    for (int mt = 0; mt < 2; mt++) {
        int n_lo = nb + mt*16 + g;
        int n_hi = n_lo + 8;
        float bl = bias[n_lo], bh = bias[n_hi];
#pragma unroll
        for (int nt = 0; nt < 4; nt++) {
            int l = lbase + mb + nt*8 + 2*tg;
            *reinterpret_cast<float2*>(C + (size_t)bidx*N*4096 + (size_t)n_lo*4096 + l) =
                make_float2(d[mt][nt][0] + bl, d[mt][nt][1] + bl);
            *reinterpret_cast<float2*>(C + (size_t)bidx*N*4096 + (size_t)n_hi*4096 + l) =
                make_float2(d[mt][nt][2] + bh, d[mt][nt][3] + bh);
        }
    }
}

// ---------------------------------------------------------------------------
// 3d. k_mma3: x_proj. 64-n block, row-major [m][40] epilogue with guard.
// ---------------------------------------------------------------------------
__global__ __launch_bounds__(256, 2) void k_mma3(
    const float* __restrict__ W, const float* __restrict__ Bm,
    float* __restrict__ C, int K)
{
    __shared__ float Ws[2][64][20];
    __shared__ float Bs[2][16][136];

    int tid  = threadIdx.x;
    int lane = tid & 31;
    int g    = lane >> 2;
    int tg   = lane & 3;
    int wid  = tid >> 5;
    int wm   = wid & 1;
    int wn   = wid >> 1;
    int nb   = wm * 32;
    int mb   = wn * 32;

    int m0 = blockIdx.x * 128;

    float d[2][4][4];
#pragma unroll
    for (int mt = 0; mt < 2; mt++)
#pragma unroll
        for (int nt = 0; nt < 4; nt++)
#pragma unroll
            for (int q = 0; q < 4; q++) d[mt][nt][q] = 0.f;

    int lb_k = tid >> 5;
    int lb_m = (tid & 31) * 4;
    int lw_n = tid >> 2;
    int lw_k = (tid & 3) * 4;

    unsigned int sB = (unsigned int)__cvta_generic_to_shared(&Bs[0][lb_k][lb_m]);
    unsigned int sW = (unsigned int)__cvta_generic_to_shared(&Ws[0][lw_n][lw_k]);
    const unsigned int bufB = 16*136*4;
    const unsigned int bufW = 64*20*4;
    const unsigned int rowB = 8*136*4;

    const float* gB = Bm + (size_t)lb_k*MTOT + m0 + lb_m;
    const float* gW = W + (size_t)lw_n*K + lw_k;

    auto issue = [&](int buf, int k0) {
        cp_async16(sB + buf*bufB,        gB + (size_t)k0*MTOT);
        cp_async16(sB + buf*bufB + rowB, gB + (size_t)(k0 + 8)*MTOT);
        cp_async16(sW + buf*bufW,        gW + k0);
        cp_commit();
    };

    issue(0, 0);
    cp_wait0();
    __syncthreads();

    int p = 0;
    for (int k0 = 0; k0 < K; k0 += 16) {
        if (k0 + 16 < K) issue(p ^ 1, k0 + 16);

#pragma unroll
        for (int ks = 0; ks < 16; ks += 8) {
            unsigned a[2][4];
#pragma unroll
            for (int mt = 0; mt < 2; mt++) {
                int nr = nb + mt*16 + g;
                a[mt][0] = __float_as_uint(Ws[p][nr    ][ks + tg]);
                a[mt][1] = __float_as_uint(Ws[p][nr + 8][ks + tg]);
                a[mt][2] = __float_as_uint(Ws[p][nr    ][ks + tg + 4]);
                a[mt][3] = __float_as_uint(Ws[p][nr + 8][ks + tg + 4]);
            }
            unsigned bf[4][2];
#pragma unroll
            for (int nt = 0; nt < 4; nt++) {
                int mc = mb + nt*8 + g;
                bf[nt][0] = __float_as_uint(Bs[p][ks + tg    ][mc]);
                bf[nt][1] = __float_as_uint(Bs[p][ks + tg + 4][mc]);
            }
#pragma unroll
            for (int mt = 0; mt < 2; mt++)
#pragma unroll
                for (int nt = 0; nt < 4; nt++)
                    mma_tf32(d[mt][nt][0], d[mt][nt][1], d[mt][nt][2], d[mt][nt][3],
                             a[mt][0], a[mt][1], a[mt][2], a[mt][3],
                             bf[nt][0], bf[nt][1]);
        }
        cp_wait0();
        __syncthreads();
        p ^= 1;
    }

#pragma unroll
    for (int mt = 0; mt < 2; mt++) {
        int n_lo = nb + mt*16 + g;
        int n_hi = n_lo + 8;
#pragma unroll
        for (int nt = 0; nt < 4; nt++) {
            int m = m0 + mb + nt*8 + 2*tg;
            if (n_lo < 40) {
                C[(size_t)m*40 + n_lo]     = d[mt][nt][0];
                C[(size_t)(m+1)*40 + n_lo] = d[mt][nt][1];
            }
            if (n_hi < 40) {
                C[(size_t)m*40 + n_hi]     = d[mt][nt][2];
                C[(size_t)(m+1)*40 + n_hi] = d[mt][nt][3];
            }
        }
    }
}

// ---------------------------------------------------------------------------
// 4. depthwise causal conv1d + bias + silu — float4 vectorized
// ---------------------------------------------------------------------------
__global__ __launch_bounds__(256) void k_conv1d_silu(const float* __restrict__ cw,
                                                     const float* __restrict__ cb)
{
    int d = blockIdx.y;
    int m4 = (blockIdx.x*256 + threadIdx.x) * 4;
    int l = m4 & 4095;
    const float* row = g_xzT + (size_t)d*MTOT;

    float w0 = cw[d*4+0], w1 = cw[d*4+1], w2 = cw[d*4+2], w3 = cw[d*4+3];
    float bb = cb[d];

    float4 cur = *reinterpret_cast<const float4*>(row + m4);
    float4 prv = make_float4(0.f, 0.f, 0.f, 0.f);
    if (l >= 4) prv = *reinterpret_cast<const float4*>(row + m4 - 4);

    float x0 = prv.y, x1 = prv.z, x2 = prv.w;
    float r0 = bb + w0*x0 + w1*x1 + w2*x2 + w3*cur.x;
    float r1 = bb + w0*x1 + w1*x2 + w2*cur.x + w3*cur.y;
    float r2 = bb + w0*x2 + w1*cur.x + w2*cur.y + w3*cur.z;
    float r3 = bb + w0*cur.x + w1*cur.y + w2*cur.z + w3*cur.w;

    *reinterpret_cast<float4*>(g_uT + (size_t)d*MTOT + m4) =
        make_float4(silu_f(r0), silu_f(r1), silu_f(r2), silu_f(r3));
}

// ---------------------------------------------------------------------------
// 5. delta = softplus(dt @ dt_proj_w.T + dt_proj_b) -> g_deltaT [d][m]
// ---------------------------------------------------------------------------
__global__ void k_delta(const float* __restrict__ dtw,
                        const float* __restrict__ dtb)
{
    __shared__ float sdt[64][8];
    int tid = threadIdx.x;
    int m0 = blockIdx.x*64;
    for (int i = tid; i < 512; i += 256) {
        int ml = i >> 3, r = i & 7;
        sdt[ml][r] = g_dbc[(size_t)(m0 + ml)*40 + r];
    }
    __syncthreads();
    int ml = tid & 63;
    int dl = tid >> 6;
    for (int it = 0; it < 64; it++) {
        int d = it*4 + dl;
        const float* wr = dtw + d*8;
        float x = dtb[d];
#pragma unroll
        for (int r = 0; r < 8; r++) x += wr[r]*sdt[ml][r];
        float sp = (x > 20.f) ? x : log1pf(__expf(x));
        g_deltaT[(size_t)d*MTOT + m0 + ml] = sp;
    }
}

// ---------------------------------------------------------------------------
// 6. scan pass 1 — float4 broadcast loads, 4 steps per iter
// ---------------------------------------------------------------------------
__global__ __launch_bounds__(128) void k_scan1(const float* __restrict__ A_log)
{
    int lane = threadIdx.x & 31;
    int wgid = blockIdx.x*4 + (threadIdx.x >> 5);
    int ch = wgid & 63;
    int dp = (wgid >> 6) & 127;
    int b  = wgid >> 13;
    int dd = lane >> 4, n = lane & 15;
    int d  = dp*2 + dd;

    float A = -__expf(A_log[d*DSTATE + n]);
    int m0 = b*LSEQ + ch*LCHUNK;
    const float* drow = g_deltaT + (size_t)d*MTOT;
    const float* urow = g_uT     + (size_t)d*MTOT;
    const float* dbc  = g_dbc;

    float h = 0.f, sumd = 0.f;
    for (int l4 = 0; l4 < LCHUNK; l4 += 4) {
        int m = m0 + l4;
        float4 dt4 = *reinterpret_cast<const float4*>(drow + m);
        float4 uu4 = *reinterpret_cast<const float4*>(urow + m);
        float dts[4] = {dt4.x, dt4.y, dt4.z, dt4.w};
        float uus[4] = {uu4.x, uu4.y, uu4.z, uu4.w};
#pragma unroll
        for (int j = 0; j < 4; j++) {
            float Bn = dbc[(size_t)(m + j)*40 + 8 + n];
            h = __expf(dts[j]*A)*h + dts[j]*Bn*uus[j];
            sumd += dts[j];
        }
    }
    int bd = b*DINNER + d;
    g_hend[((size_t)bd*NCHUNK + ch)*DSTATE + n] = h;
    if (n == 0) g_sumd[(size_t)bd*NCHUNK + ch] = sumd;
}

// ---------------------------------------------------------------------------
// 7. scan pass 2
// ---------------------------------------------------------------------------
__global__ void k_scan2(const float* __restrict__ A_log)
{
    int gt = blockIdx.x*256 + threadIdx.x;
    int w  = gt >> 5;
    int lane = gt & 31;
    int dd = lane >> 4, n = lane & 15;
    int bd = w*2 + dd;
    int d  = bd & 255;

    float A = -__expf(A_log[d*DSTATE + n]);
    float h = 0.f;
    for (int ch = 0; ch < NCHUNK; ch++) {
        size_t base = ((size_t)bd*NCHUNK + ch)*DSTATE + n;
        g_hin[base] = h;
        float sd = g_sumd[(size_t)bd*NCHUNK + ch];
        h = __expf(sd*A)*h + g_hend[base];
    }
}

// ---------------------------------------------------------------------------
// 8. scan pass 3 — float4 loads, 4-step unroll, shfl reduction (16-wide)
// ---------------------------------------------------------------------------
__global__ __launch_bounds__(128) void k_scan3(const float* __restrict__ A_log,
                                               const float* __restrict__ Dp)
{
    int lane = threadIdx.x & 31;
    int wgid = blockIdx.x*4 + (threadIdx.x >> 5);
    int ch = wgid & 63;
    int dp = (wgid >> 6) & 127;
    int b  = wgid >> 13;
    int dd = lane >> 4, n = lane & 15;
    int d  = dp*2 + dd;
    int bd = b*DINNER + d;

    float A = -__expf(A_log[d*DSTATE + n]);
    float Dd = Dp[d];
    int m0 = b*LSEQ + ch*LCHUNK;
    const float* drow = g_deltaT + (size_t)d*MTOT;
    const float* urow = g_uT     + (size_t)d*MTOT;
    const float* zrow = g_xzT    + (size_t)(DINNER + d)*MTOT;
    const float* dbc  = g_dbc;
    float*       yrow = g_yT     + (size_t)d*MTOT;

    float h = g_hin[((size_t)bd*NCHUNK + ch)*DSTATE + n];

    for (int l4 = 0; l4 < LCHUNK; l4 += 4) {
        int m = m0 + l4;
        float4 dt4 = *reinterpret_cast<const float4*>(drow + m);
        float4 uu4 = *reinterpret_cast<const float4*>(urow + m);
        float4 z4  = *reinterpret_cast<const float4*>(zrow + m);
        float dts[4] = {dt4.x, dt4.y, dt4.z, dt4.w};
        float uus[4] = {uu4.x, uu4.y, uu4.z, uu4.w};
        float zs[4]  = {z4.x, z4.y, z4.z, z4.w};
        float ys[4];
#pragma unroll
        for (int j = 0; j < 4; j++) {
            float Bn = dbc[(size_t)(m + j)*40 + 8 + n];
            float Cn = dbc[(size_t)(m + j)*40 + 24 + n];
            h = __expf(dts[j]*A)*h + dts[j]*Bn*uus[j];
            ys[j] = h*Cn;
        }
        // 4 independent reduction chains interleave across j
#pragma unroll
        for (int j = 0; j < 4; j++) {
            ys[j] += __shfl_xor_sync(0xffffffffu, ys[j], 8, 16);
            ys[j] += __shfl_xor_sync(0xffffffffu, ys[j], 4, 16);
            ys[j] += __shfl_xor_sync(0xffffffffu, ys[j], 2, 16);
            ys[j] += __shfl_xor_sync(0xffffffffu, ys[j], 1, 16);
        }
        if (n == 0) {
#pragma unroll
            for (int j = 0; j < 4; j++)
                yrow[m + j] = tf32r((ys[j] + uus[j]*Dd) * silu_f(zs[j]));
        }
    }
}

// ---------------------------------------------------------------------------
// 9. LayerNorm over 128 channels + silu ; channel-major tf32 out
// ---------------------------------------------------------------------------
__global__ __launch_bounds__(256) void k_ln_silu(const float* __restrict__ gamma,
                                                 const float* __restrict__ beta)
{
    __shared__ float sT[128][36];
    int tid = threadIdx.x;
    int wid = tid >> 5, lane = tid & 31;
    int m_base = blockIdx.x*32;

    for (int r = 0; r < 4; r++) {
        int mloc = r*8 + wid;
        int m = m_base + mloc;
        float4 v = *reinterpret_cast<const float4*>(g_ym + (size_t)m*128 + lane*4);
        float s  = v.x + v.y + v.z + v.w;
        float s2 = v.x*v.x + v.y*v.y + v.z*v.z + v.w*v.w;
#pragma unroll
        for (int k = 16; k >= 1; k >>= 1) {
            s  += __shfl_xor_sync(0xffffffffu, s,  k);
            s2 += __shfl_xor_sync(0xffffffffu, s2, k);
        }
        float mean = s * (1.f/128.f);
        float var  = s2 * (1.f/128.f) - mean*mean;
        float rstd = rsqrtf(var + 1e-5f);
        float va[4] = {v.x, v.y, v.z, v.w};
#pragma unroll
        for (int i = 0; i < 4; i++) {
            int c = lane*4 + i;
            float t = (va[i] - mean)*rstd*gamma[c] + beta[c];
            sT[c][mloc] = tf32r(silu_f(t));
        }
    }
    __syncthreads();

    int mq = tid & 7;
    int c0 = tid >> 3;
    for (int cc = c0; cc < 128; cc += 32) {
        float4 v = *reinterpret_cast<const float4*>(&sT[cc][mq*4]);
        *reinterpret_cast<float4*>(g_lnT + (size_t)cc*MTOT + m_base + mq*4) = v;
    }
}

// ---------------------------------------------------------------------------
extern "C" void kernel_launch(void* const* d_in, const int* in_sizes, int n_in,
                              void* d_out, int out_size)
{
    const float* x        = (const float*)d_in[0];
    const float* skip_x   = (const float*)d_in[1];
    const float* up_w     = (const float*)d_in[2];
    const float* up_b     = (const float*)d_in[3];
    const float* in_proj  = (const float*)d_in[4];
    const float* conv1d_w = (const float*)d_in[5];
    const float* conv1d_b = (const float*)d_in[6];
    const float* x_proj   = (const float*)d_in[7];
    const float* dt_proj_w= (const float*)d_in[8];
    const float* dt_proj_b= (const float*)d_in[9];
    const float* A_log    = (const float*)d_in[10];
    const float* Dp       = (const float*)d_in[11];
    const float* out_proj = (const float*)d_in[12];
    const float* ln_gamma = (const float*)d_in[13];
    const float* ln_beta  = (const float*)d_in[14];
    const float* convout_w= (const float*)d_in[15];
    const float* convout_b= (const float*)d_in[16];
    float* out = (float*)d_out;

    float *p_seqT, *p_xzT, *p_uT, *p_yT, *p_lnT, *p_dbc, *p_ym;
    float *p_wrnd, *p_wrnd2, *p_wrnd3, *p_wrnd4;
    cudaGetSymbolAddress((void**)&p_seqT, g_seqT);
    cudaGetSymbolAddress((void**)&p_xzT,  g_xzT);
    cudaGetSymbolAddress((void**)&p_uT,   g_uT);
    cudaGetSymbolAddress((void**)&p_yT,   g_yT);
    cudaGetSymbolAddress((void**)&p_lnT,  g_lnT);
    cudaGetSymbolAddress((void**)&p_dbc,  g_dbc);
    cudaGetSymbolAddress((void**)&p_ym,   g_ym);
    cudaGetSymbolAddress((void**)&p_wrnd,  g_wrnd);
    cudaGetSymbolAddress((void**)&p_wrnd2, g_wrnd2);
    cudaGetSymbolAddress((void**)&p_wrnd3, g_wrnd3);
    cudaGetSymbolAddress((void**)&p_wrnd4, g_wrnd4);

    // 0a: up_w transpose precedes k_front's upsample segment
    k_transpose_upw<<<128, 256>>>(up_w);
    // 0b: merged front-end (upsample + copy_skip + weight prep)
    k_front<<<4832, 256>>>(x, up_b, skip_x, in_proj, out_proj,
                           convout_w, x_proj);

    // 3: in_proj (N=512, K=128) -> g_xzT channel-major [tf32]
    k_mma0<<<dim3(MTOT/128, 4), 256>>>(p_wrnd, p_seqT, p_xzT, 512, 128);

    // 4: conv1d + silu -> g_uT (fp32)
    k_conv1d_silu<<<dim3(16, DINNER), 256>>>(conv1d_w, conv1d_b);

    // 5: x_proj (tf32, padded N) -> g_dbc row-major [m][40]
    k_mma3<<<MTOT/128, 256>>>(p_wrnd4, p_uT, p_dbc, 256);

    // 6: delta
    k_delta<<<MTOT/64, 256>>>(dt_proj_w, dt_proj_b);

    // 7-9: chunked selective scan (fp32)
    k_scan1<<<8192, 128>>>(A_log);
    k_scan2<<<64, 256>>>(A_log);
    k_scan3<<<8192, 128>>>(A_log, Dp);

    // 10: out_proj (N=128, K=256) -> g_ym row-major [m][128]  [tf32]
    k_mma1<<<dim3(MTOT/128, 1), 256>>>(p_wrnd2, p_yT, p_ym, 128, 256, 128);

    // 11: LayerNorm + silu -> g_lnT channel-major (tf32)
    k_ln_silu<<<MTOT/32, 256>>>(ln_gamma, ln_beta);

    // 12: convout 1x1 (N=64, K=128) -> d_out NCHW + bias  [tf32]
    k_mma2<<<dim3(MTOT/128, 1), 256>>>(p_wrnd3, p_lnT, out, convout_b, 64, 128);
}

// round 14
// speedup vs baseline: 1.3719x; 1.0319x over previous
#include <cuda_runtime.h>
#include <stdint.h>
#include <math.h>

#define BATCH   4
#define LSEQ    4096
#define MTOT    16384          // BATCH*LSEQ
#define DMODEL  128
#define DINNER  256
#define DSTATE  16
#define NCHUNK  64
#define LCHUNK  64

// ---------------- static scratch (no cudaMalloc anywhere) -------------------
__device__ float g_seqT  [DMODEL  * MTOT];    // [c][m] concat(up,skip) (tf32)
__device__ float g_xzT   [2*DINNER* MTOT];    // [n][m] rows 0..255 u_raw, 256..511 z
__device__ float g_uT    [DINNER  * MTOT];    // [d][m] conv1d+silu (fp32)
__device__ float g_deltaT[DINNER  * MTOT];    // [d][m]
__device__ float g_dbc   [MTOT * 40];         // [m][40]  0..7 dt, 8..23 B, 24..39 C
__device__ float g_yT    [DINNER  * MTOT];    // [d][m] scan out * silu(z) (tf32)
__device__ float g_ym    [MTOT * DMODEL];     // [m][128] out_proj out
__device__ float g_lnT   [DMODEL  * MTOT];    // [c][m] LN+silu out (tf32)
__device__ float g_wrnd  [512*128];           // tf32 in_proj weights
__device__ float g_wrnd2 [128*256];           // tf32 out_proj weights
__device__ float g_wrnd3 [64*128];            // tf32 convout weights
__device__ float g_wrnd4 [64*256];            // tf32 x_proj weights (rows 40..63 zero)

__device__ __forceinline__ float silu_f(float x) {
    return x / (1.0f + __expf(-x));
}
__device__ __forceinline__ float tf32r(float x) {
    unsigned int u;
    asm("cvt.rna.tf32.f32 %0, %1;" : "=r"(u) : "f"(x));
    return __uint_as_float(u);
}

__device__ __forceinline__ void cp_async16(unsigned int s, const void* g) {
    asm volatile("cp.async.cg.shared.global [%0], [%1], 16;" :: "r"(s), "l"(g));
}
__device__ __forceinline__ void cp_commit() {
    asm volatile("cp.async.commit_group;" ::: "memory");
}
__device__ __forceinline__ void cp_wait0() {
    asm volatile("cp.async.wait_group 0;" ::: "memory");
}

__device__ __forceinline__ void mma_tf32(float& d0, float& d1, float& d2, float& d3,
                                         unsigned a0, unsigned a1, unsigned a2, unsigned a3,
                                         unsigned b0, unsigned b1)
{
    asm volatile(
        "mma.sync.aligned.m16n8k8.row.col.f32.tf32.tf32.f32 "
        "{%0,%1,%2,%3}, {%4,%5,%6,%7}, {%8,%9}, {%0,%1,%2,%3};"
        : "+f"(d0), "+f"(d1), "+f"(d2), "+f"(d3)
        : "r"(a0), "r"(a1), "r"(a2), "r"(a3), "r"(b0), "r"(b1));
}

// ---------------------------------------------------------------------------
// 0. merged front-end: upsample + copy_skip(float4) + weight prep, one launch.
//    bx in [0,256)      : upsample (reads up_w directly, coalesced)
//    bx in [256,1280)   : copy skip (float4)
//    bx in [1280,1760)  : weight rounding
// ---------------------------------------------------------------------------
__global__ __launch_bounds__(256) void k_front(
    const float* __restrict__ x, const float* __restrict__ upb,
    const float* __restrict__ skip,
    const float* __restrict__ upw,
    const float* __restrict__ w_in,
    const float* __restrict__ w_out,
    const float* __restrict__ w_co,
    const float* __restrict__ w_xp)
{
    int bx = blockIdx.x;
    int t  = threadIdx.x;

    if (bx < 256) {
        __shared__ float xs[16][128];
        int b  = bx >> 6;
        int p0 = (bx & 63) << 4;

        for (int i = t; i < 16*128; i += 256) {
            int pix = i & 15, cin = i >> 4;
            xs[pix][cin] = x[(b*128 + cin)*1024 + p0 + pix];
        }
        __syncthreads();

        int o  = t >> 2;
        int ij = t & 3;
        int ii = ij >> 1, jj = ij & 1;

        float acc[16];
#pragma unroll
        for (int p = 0; p < 16; p++) acc[p] = 0.f;

        // weight for (cin, t) at upw[cin*256 + t]; coalesced across t
        for (int c4 = 0; c4 < 32; c4++) {
            float w0 = upw[(c4*4 + 0)*256 + t];
            float w1 = upw[(c4*4 + 1)*256 + t];
            float w2 = upw[(c4*4 + 2)*256 + t];
            float w3 = upw[(c4*4 + 3)*256 + t];
#pragma unroll
            for (int p = 0; p < 16; p++) {
                float4 x4 = *reinterpret_cast<const float4*>(&xs[p][c4*4]);
                acc[p] += x4.x*w0 + x4.y*w1 + x4.z*w2 + x4.w*w3;
            }
        }
        float bias = upb[o];
#pragma unroll
        for (int p = 0; p < 16; p++) {
            int hp = (p0 + p) >> 5, wp = (p0 + p) & 31;
            int l  = (2*hp + ii)*64 + 2*wp + jj;
            g_seqT[o*MTOT + b*LSEQ + l] = tf32r(acc[p] + bias);
        }
    } else if (bx < 1280) {
        int i4 = ((bx - 256)*256 + t) * 4;      // element index, l fastest
        float4 v = *reinterpret_cast<const float4*>(skip + i4);
        int l = i4 & 4095;
        int c = (i4 >> 12) & 63;
        int b = i4 >> 18;
        *reinterpret_cast<float4*>(g_seqT + (size_t)(64 + c)*MTOT + b*LSEQ + l) =
            make_float4(tf32r(v.x), tf32r(v.y), tf32r(v.z), tf32r(v.w));
    } else {
        int sb = bx - 1280;
        if (sb < 256) {
            int i = sb*256 + t;
            g_wrnd[i] = tf32r(w_in[i]);
        } else if (sb < 384) {
            int i = (sb - 256)*256 + t;
            g_wrnd2[i] = tf32r(w_out[i]);
        } else if (sb < 416) {
            int i = (sb - 384)*256 + t;
            g_wrnd3[i] = tf32r(w_co[i]);
        } else if (sb < 480) {
            int i = (sb - 416)*256 + t;
            int row = i >> 8;
            g_wrnd4[i] = (row < 40) ? tf32r(w_xp[row*256 + (i & 255)]) : 0.f;
        }
    }
}

// ---------------------------------------------------------------------------
// 3a. k_mma0: tf32 GEMM, channel-major out. CTA 128n x 128m, 8 warps (4n x 2m).
// ---------------------------------------------------------------------------
__global__ __launch_bounds__(256, 2) void k_mma0(
    const float* __restrict__ W, const float* __restrict__ Bm,
    float* __restrict__ C, int N, int K)
{
    __shared__ float Ws[2][128][20];
    __shared__ float Bs[2][16][136];

    int tid  = threadIdx.x;
    int lane = tid & 31;
    int g    = lane >> 2;
    int tg   = lane & 3;
    int wid  = tid >> 5;
    int wm   = wid & 3;
    int wn   = wid >> 2;
    int nb   = wm * 32;
    int mb   = wn * 64;

    int m0 = blockIdx.x * 128;
    int n0 = blockIdx.y * 128;

    float d[2][8][4];
#pragma unroll
    for (int mt = 0; mt < 2; mt++)
#pragma unroll
        for (int nt = 0; nt < 8; nt++)
#pragma unroll
            for (int q = 0; q < 4; q++) d[mt][nt][q] = 0.f;

    int lb_k = tid >> 5;
    int lb_m = (tid & 31) * 4;
    int lw_n = tid >> 1;
    int lw_k = (tid & 1) * 8;

    unsigned int sB = (unsigned int)__cvta_generic_to_shared(&Bs[0][lb_k][lb_m]);
    unsigned int sW = (unsigned int)__cvta_generic_to_shared(&Ws[0][lw_n][lw_k]);
    const unsigned int bufB = 16*136*4;
    const unsigned int bufW = 128*20*4;
    const unsigned int rowB = 8*136*4;

    const float* gB = Bm + (size_t)lb_k*MTOT + m0 + lb_m;
    const float* gW = W + (size_t)(n0 + lw_n)*K + lw_k;

    auto issue = [&](int buf, int k0) {
        cp_async16(sB + buf*bufB,        gB + (size_t)k0*MTOT);
        cp_async16(sB + buf*bufB + rowB, gB + (size_t)(k0 + 8)*MTOT);
        cp_async16(sW + buf*bufW,        gW + k0);
        cp_async16(sW + buf*bufW + 16,   gW + k0 + 4);
        cp_commit();
    };

    issue(0, 0);
    cp_wait0();
    __syncthreads();

    int p = 0;
    for (int k0 = 0; k0 < K; k0 += 16) {
        if (k0 + 16 < K) issue(p ^ 1, k0 + 16);

#pragma unroll
        for (int ks = 0; ks < 16; ks += 8) {
            unsigned a[2][4];
#pragma unroll
            for (int mt = 0; mt < 2; mt++) {
                int nr = nb + mt*16 + g;
                a[mt][0] = __float_as_uint(Ws[p][nr    ][ks + tg]);
                a[mt][1] = __float_as_uint(Ws[p][nr + 8][ks + tg]);
                a[mt][2] = __float_as_uint(Ws[p][nr    ][ks + tg + 4]);
                a[mt][3] = __float_as_uint(Ws[p][nr + 8][ks + tg + 4]);
            }
            unsigned bf[8][2];
#pragma unroll
            for (int nt = 0; nt < 8; nt++) {
                int mc = mb + nt*8 + g;
                bf[nt][0] = __float_as_uint(Bs[p][ks + tg    ][mc]);
                bf[nt][1] = __float_as_uint(Bs[p][ks + tg + 4][mc]);
            }
#pragma unroll
            for (int mt = 0; mt < 2; mt++)
#pragma unroll
                for (int nt = 0; nt < 8; nt++)
                    mma_tf32(d[mt][nt][0], d[mt][nt][1], d[mt][nt][2], d[mt][nt][3],
                             a[mt][0], a[mt][1], a[mt][2], a[mt][3],
                             bf[nt][0], bf[nt][1]);
        }
        cp_wait0();
        __syncthreads();
        p ^= 1;
    }

#pragma unroll
    for (int mt = 0; mt < 2; mt++) {
        int n_lo = n0 + nb + mt*16 + g;
        int n_hi = n_lo + 8;
#pragma unroll
        for (int nt = 0; nt < 8; nt++) {
            int m = m0 + mb + nt*8 + 2*tg;
            *reinterpret_cast<float2*>(C + (size_t)n_lo*MTOT + m) =
                make_float2(d[mt][nt][0], d[mt][nt][1]);
            *reinterpret_cast<float2*>(C + (size_t)n_hi*MTOT + m) =
                make_float2(d[mt][nt][2], d[mt][nt][3]);
        }
    }
}

// ---------------------------------------------------------------------------
// 3b. k_mma1: row-major [m][ldc] epilogue (out_proj).
// ---------------------------------------------------------------------------
__global__ __launch_bounds__(256, 2) void k_mma1(
    const float* __restrict__ W, const float* __restrict__ Bm,
    float* __restrict__ C, int N, int K, int ldc)
{
    __shared__ float Ws[2][128][20];
    __shared__ float Bs[2][16][136];

    int tid  = threadIdx.x;
    int lane = tid & 31;
    int g    = lane >> 2;
    int tg   = lane & 3;
    int wid  = tid >> 5;
    int wm   = wid & 3;
    int wn   = wid >> 2;
    int nb   = wm * 32;
    int mb   = wn * 64;

    int m0 = blockIdx.x * 128;
    int n0 = blockIdx.y * 128;

    float d[2][8][4];
#pragma unroll
    for (int mt = 0; mt < 2; mt++)
#pragma unroll
        for (int nt = 0; nt < 8; nt++)
#pragma unroll
            for (int q = 0; q < 4; q++) d[mt][nt][q] = 0.f;

    int lb_k = tid >> 5;
    int lb_m = (tid & 31) * 4;
    int lw_n = tid >> 1;
    int lw_k = (tid & 1) * 8;

    unsigned int sB = (unsigned int)__cvta_generic_to_shared(&Bs[0][lb_k][lb_m]);
    unsigned int sW = (unsigned int)__cvta_generic_to_shared(&Ws[0][lw_n][lw_k]);
    const unsigned int bufB = 16*136*4;
    const unsigned int bufW = 128*20*4;
    const unsigned int rowB = 8*136*4;

    const float* gB = Bm + (size_t)lb_k*MTOT + m0 + lb_m;
    const float* gW = W + (size_t)(n0 + lw_n)*K + lw_k;

    auto issue = [&](int buf, int k0) {
        cp_async16(sB + buf*bufB,        gB + (size_t)k0*MTOT);
        cp_async16(sB + buf*bufB + rowB, gB + (size_t)(k0 + 8)*MTOT);
        cp_async16(sW + buf*bufW,        gW + k0);
        cp_async16(sW + buf*bufW + 16,   gW + k0 + 4);
        cp_commit();
    };

    issue(0, 0);
    cp_wait0();
    __syncthreads();

    int p = 0;
    for (int k0 = 0; k0 < K; k0 += 16) {
        if (k0 + 16 < K) issue(p ^ 1, k0 + 16);

#pragma unroll
        for (int ks = 0; ks < 16; ks += 8) {
            unsigned a[2][4];
#pragma unroll
            for (int mt = 0; mt < 2; mt++) {
                int nr = nb + mt*16 + g;
                a[mt][0] = __float_as_uint(Ws[p][nr    ][ks + tg]);
                a[mt][1] = __float_as_uint(Ws[p][nr + 8][ks + tg]);
                a[mt][2] = __float_as_uint(Ws[p][nr    ][ks + tg + 4]);
                a[mt][3] = __float_as_uint(Ws[p][nr + 8][ks + tg + 4]);
            }
            unsigned bf[8][2];
#pragma unroll
            for (int nt = 0; nt < 8; nt++) {
                int mc = mb + nt*8 + g;
                bf[nt][0] = __float_as_uint(Bs[p][ks + tg    ][mc]);
                bf[nt][1] = __float_as_uint(Bs[p][ks + tg + 4][mc]);
            }
#pragma unroll
            for (int mt = 0; mt < 2; mt++)
#pragma unroll
                for (int nt = 0; nt < 8; nt++)
                    mma_tf32(d[mt][nt][0], d[mt][nt][1], d[mt][nt][2], d[mt][nt][3],
                             a[mt][0], a[mt][1], a[mt][2], a[mt][3],
                             bf[nt][0], bf[nt][1]);
        }
        cp_wait0();
        __syncthreads();
        p ^= 1;
    }

#pragma unroll
    for (int mt = 0; mt < 2; mt++) {
        int n_lo = n0 + nb + mt*16 + g;
        int n_hi = n_lo + 8;
#pragma unroll
        for (int nt = 0; nt < 8; nt++) {
            int m = m0 + mb + nt*8 + 2*tg;
            C[(size_t)m*ldc + n_lo]       = d[mt][nt][0];
            C[(size_t)(m+1)*ldc + n_lo]   = d[mt][nt][1];
            C[(size_t)m*ldc + n_hi]       = d[mt][nt][2];
            C[(size_t)(m+1)*ldc + n_hi]   = d[mt][nt][3];
        }
    }
}

// ---------------------------------------------------------------------------
// 3c. k_mma2: convout. 64-n block (2n x 4m warps), NCHW + bias.
// ---------------------------------------------------------------------------
__global__ __launch_bounds__(256, 2) void k_mma2(
    const float* __restrict__ W, const float* __restrict__ Bm,
    float* __restrict__ C, const float* __restrict__ bias, int N, int K)
{
    __shared__ float Ws[2][64][20];
    __shared__ float Bs[2][16][136];

    int tid  = threadIdx.x;
    int lane = tid & 31;
    int g    = lane >> 2;
    int tg   = lane & 3;
    int wid  = tid >> 5;
    int wm   = wid & 1;
    int wn   = wid >> 1;
    int nb   = wm * 32;
    int mb   = wn * 32;

    int m0 = blockIdx.x * 128;

    float d[2][4][4];
#pragma unroll
    for (int mt = 0; mt < 2; mt++)
#pragma unroll
        for (int nt = 0; nt < 4; nt++)
#pragma unroll
            for (int q = 0; q < 4; q++) d[mt][nt][q] = 0.f;

    int lb_k = tid >> 5;
    int lb_m = (tid & 31) * 4;
    int lw_n = tid >> 2;
    int lw_k = (tid & 3) * 4;

    unsigned int sB = (unsigned int)__cvta_generic_to_shared(&Bs[0][lb_k][lb_m]);
    unsigned int sW = (unsigned int)__cvta_generic_to_shared(&Ws[0][lw_n][lw_k]);
    const unsigned int bufB = 16*136*4;
    const unsigned int bufW = 64*20*4;
    const unsigned int rowB = 8*136*4;

    const float* gB = Bm + (size_t)lb_k*MTOT + m0 + lb_m;
    const float* gW = W + (size_t)lw_n*K + lw_k;

    auto issue = [&](int buf, int k0) {
        cp_async16(sB + buf*bufB,        gB + (size_t)k0*MTOT);
        cp_async16(sB + buf*bufB + rowB, gB + (size_t)(k0 + 8)*MTOT);
        cp_async16(sW + buf*bufW,        gW + k0);
        cp_commit();
    };

    issue(0, 0);
    cp_wait0();
    __syncthreads();

    int p = 0;
    for (int k0 = 0; k0 < K; k0 += 16) {
        if (k0 + 16 < K) issue(p ^ 1, k0 + 16);

#pragma unroll
        for (int ks = 0; ks < 16; ks += 8) {
            unsigned a[2][4];
#pragma unroll
            for (int mt = 0; mt < 2; mt++) {
                int nr = nb + mt*16 + g;
                a[mt][0] = __float_as_uint(Ws[p][nr    ][ks + tg]);
                a[mt][1] = __float_as_uint(Ws[p][nr + 8][ks + tg]);
                a[mt][2] = __float_as_uint(Ws[p][nr    ][ks + tg + 4]);
                a[mt][3] = __float_as_uint(Ws[p][nr + 8][ks + tg + 4]);
            }
            unsigned bf[4][2];
#pragma unroll
            for (int nt = 0; nt < 4; nt++) {
                int mc = mb + nt*8 + g;
                bf[nt][0] = __float_as_uint(Bs[p][ks + tg    ][mc]);
                bf[nt][1] = __float_as_uint(Bs[p][ks + tg + 4][mc]);
            }
#pragma unroll
            for (int mt = 0; mt < 2; mt++)
#pragma unroll
                for (int nt = 0; nt < 4; nt++)
                    mma_tf32(d[mt][nt][0], d[mt][nt][1], d[mt][nt][2], d[mt][nt][3],
                             a[mt][0], a[mt][1], a[mt][2], a[mt][3],
                             bf[nt][0], bf[nt][1]);
        }
        cp_wait0();
        __syncthreads();
        p ^= 1;
    }

    int bidx = m0 >> 12;
    int lbase = (m0 & 4095);
#pragma unroll
    for (int mt = 0; mt < 2; mt++) {
        int n_lo = nb + mt*16 + g;
        int n_hi = n_lo + 8;
        float bl = bias[n_lo], bh = bias[n_hi];
#pragma unroll
        for (int nt = 0; nt < 4; nt++) {
            int l = lbase + mb + nt*8 + 2*tg;
            *reinterpret_cast<float2*>(C + (size_t)bidx*N*4096 + (size_t)n_lo*4096 + l) =
                make_float2(d[mt][nt][0] + bl, d[mt][nt][1] + bl);
            *reinterpret_cast<float2*>(C + (size_t)bidx*N*4096 + (size_t)n_hi*4096 + l) =
                make_float2(d[mt][nt][2] + bh, d[mt][nt][3] + bh);
        }
    }
}

// ---------------------------------------------------------------------------
// 3d. k_mma3: x_proj. 64-n block, row-major [m][40] epilogue with guard.
// ---------------------------------------------------------------------------
__global__ __launch_bounds__(256, 2) void k_mma3(
    const float* __restrict__ W, const float* __restrict__ Bm,
    float* __restrict__ C, int K)
{
    __shared__ float Ws[2][64][20];
    __shared__ float Bs[2][16][136];

    int tid  = threadIdx.x;
    int lane = tid & 31;
    int g    = lane >> 2;
    int tg   = lane & 3;
    int wid  = tid >> 5;
    int wm   = wid & 1;
    int wn   = wid >> 1;
    int nb   = wm * 32;
    int mb   = wn * 32;

    int m0 = blockIdx.x * 128;

    float d[2][4][4];
#pragma unroll
    for (int mt = 0; mt < 2; mt++)
#pragma unroll
        for (int nt = 0; nt < 4; nt++)
#pragma unroll
            for (int q = 0; q < 4; q++) d[mt][nt][q] = 0.f;

    int lb_k = tid >> 5;
    int lb_m = (tid & 31) * 4;
    int lw_n = tid >> 2;
    int lw_k = (tid & 3) * 4;

    unsigned int sB = (unsigned int)__cvta_generic_to_shared(&Bs[0][lb_k][lb_m]);
    unsigned int sW = (unsigned int)__cvta_generic_to_shared(&Ws[0][lw_n][lw_k]);
    const unsigned int bufB = 16*136*4;
    const unsigned int bufW = 64*20*4;
    const unsigned int rowB = 8*136*4;

    const float* gB = Bm + (size_t)lb_k*MTOT + m0 + lb_m;
    const float* gW = W + (size_t)lw_n*K + lw_k;

    auto issue = [&](int buf, int k0) {
        cp_async16(sB + buf*bufB,        gB + (size_t)k0*MTOT);
        cp_async16(sB + buf*bufB + rowB, gB + (size_t)(k0 + 8)*MTOT);
        cp_async16(sW + buf*bufW,        gW + k0);
        cp_commit();
    };

    issue(0, 0);
    cp_wait0();
    __syncthreads();

    int p = 0;
    for (int k0 = 0; k0 < K; k0 += 16) {
        if (k0 + 16 < K) issue(p ^ 1, k0 + 16);

#pragma unroll
        for (int ks = 0; ks < 16; ks += 8) {
            unsigned a[2][4];
#pragma unroll
            for (int mt = 0; mt < 2; mt++) {
                int nr = nb + mt*16 + g;
                a[mt][0] = __float_as_uint(Ws[p][nr    ][ks + tg]);
                a[mt][1] = __float_as_uint(Ws[p][nr + 8][ks + tg]);
                a[mt][2] = __float_as_uint(Ws[p][nr    ][ks + tg + 4]);
                a[mt][3] = __float_as_uint(Ws[p][nr + 8][ks + tg + 4]);
            }
            unsigned bf[4][2];
#pragma unroll
            for (int nt = 0; nt < 4; nt++) {
                int mc = mb + nt*8 + g;
                bf[nt][0] = __float_as_uint(Bs[p][ks + tg    ][mc]);
                bf[nt][1] = __float_as_uint(Bs[p][ks + tg + 4][mc]);
            }
#pragma unroll
            for (int mt = 0; mt < 2; mt++)
#pragma unroll
                for (int nt = 0; nt < 4; nt++)
                    mma_tf32(d[mt][nt][0], d[mt][nt][1], d[mt][nt][2], d[mt][nt][3],
                             a[mt][0], a[mt][1], a[mt][2], a[mt][3],
                             bf[nt][0], bf[nt][1]);
        }
        cp_wait0();
        __syncthreads();
        p ^= 1;
    }

#pragma unroll
    for (int mt = 0; mt < 2; mt++) {
        int n_lo = nb + mt*16 + g;
        int n_hi = n_lo + 8;
#pragma unroll
        for (int nt = 0; nt < 4; nt++) {
            int m = m0 + mb + nt*8 + 2*tg;
            if (n_lo < 40) {
                C[(size_t)m*40 + n_lo]     = d[mt][nt][0];
                C[(size_t)(m+1)*40 + n_lo] = d[mt][nt][1];
            }
            if (n_hi < 40) {
                C[(size_t)m*40 + n_hi]     = d[mt][nt][2];
                C[(size_t)(m+1)*40 + n_hi] = d[mt][nt][3];
            }
        }
    }
}

// ---------------------------------------------------------------------------
// 4. depthwise causal conv1d + bias + silu — float4 vectorized
// ---------------------------------------------------------------------------
__global__ __launch_bounds__(256) void k_conv1d_silu(const float* __restrict__ cw,
                                                     const float* __restrict__ cb)
{
    int d = blockIdx.y;
    int m4 = (blockIdx.x*256 + threadIdx.x) * 4;
    int l = m4 & 4095;
    const float* row = g_xzT + (size_t)d*MTOT;

    float w0 = cw[d*4+0], w1 = cw[d*4+1], w2 = cw[d*4+2], w3 = cw[d*4+3];
    float bb = cb[d];

    float4 cur = *reinterpret_cast<const float4*>(row + m4);
    float4 prv = make_float4(0.f, 0.f, 0.f, 0.f);
    if (l >= 4) prv = *reinterpret_cast<const float4*>(row + m4 - 4);

    float x0 = prv.y, x1 = prv.z, x2 = prv.w;
    float r0 = bb + w0*x0 + w1*x1 + w2*x2 + w3*cur.x;
    float r1 = bb + w0*x1 + w1*x2 + w2*cur.x + w3*cur.y;
    float r2 = bb + w0*x2 + w1*cur.x + w2*cur.y + w3*cur.z;
    float r3 = bb + w0*cur.x + w1*cur.y + w2*cur.z + w3*cur.w;

    *reinterpret_cast<float4*>(g_uT + (size_t)d*MTOT + m4) =
        make_float4(silu_f(r0), silu_f(r1), silu_f(r2), silu_f(r3));
}

// ---------------------------------------------------------------------------
// 5. delta = softplus(dt @ dt_proj_w.T + dt_proj_b) -> g_deltaT [d][m]
// ---------------------------------------------------------------------------
__global__ void k_delta(const float* __restrict__ dtw,
                        const float* __restrict__ dtb)
{
    __shared__ float sdt[64][8];
    int tid = threadIdx.x;
    int m0 = blockIdx.x*64;
    for (int i = tid; i < 512; i += 256) {
        int ml = i >> 3, r = i & 7;
        sdt[ml][r] = g_dbc[(size_t)(m0 + ml)*40 + r];
    }
    __syncthreads();
    int ml = tid & 63;
    int dl = tid >> 6;
    for (int it = 0; it < 64; it++) {
        int d = it*4 + dl;
        const float* wr = dtw + d*8;
        float x = dtb[d];
#pragma unroll
        for (int r = 0; r < 8; r++) x += wr[r]*sdt[ml][r];
        float sp = (x > 20.f) ? x : log1pf(__expf(x));
        g_deltaT[(size_t)d*MTOT + m0 + ml] = sp;
    }
}

// ---------------------------------------------------------------------------
// 6. fused selective scan: pass1 + carry + pass3 in one kernel.
//    block = (b, d-pair): 512 threads / 16 warps; each warp scans 4 chunks.
// ---------------------------------------------------------------------------
__global__ __launch_bounds__(512) void k_scan_all(const float* __restrict__ A_log,
                                                  const float* __restrict__ Dp)
{
    __shared__ float s_hend[NCHUNK][2][DSTATE];   // 8 KB
    __shared__ float s_hin [NCHUNK][2][DSTATE];   // 8 KB
    __shared__ float s_sumd[NCHUNK][2];           // 0.5 KB

    int tid  = threadIdx.x;
    int lane = tid & 31;
    int w    = tid >> 5;          // 0..15
    int bid  = blockIdx.x;        // 0..511
    int b    = bid >> 7;
    int dp   = bid & 127;
    int dd   = lane >> 4, n = lane & 15;
    int d    = dp*2 + dd;

    float A  = -__expf(A_log[d*DSTATE + n]);
    const float* drow = g_deltaT + (size_t)d*MTOT;
    const float* urow = g_uT     + (size_t)d*MTOT;
    const float* zrow = g_xzT    + (size_t)(DINNER + d)*MTOT;
    const float* dbc  = g_dbc;
    float*       yrow = g_yT     + (size_t)d*MTOT;

    // ---- pass 1: partial scans from h=0 over 4 chunks per warp ----
#pragma unroll
    for (int c = 0; c < 4; c++) {
        int ch = w*4 + c;
        int m0 = b*LSEQ + ch*LCHUNK;
        float h = 0.f, sumd = 0.f;
        for (int l4 = 0; l4 < LCHUNK; l4 += 4) {
            int m = m0 + l4;
            float4 dt4 = *reinterpret_cast<const float4*>(drow + m);
            float4 uu4 = *reinterpret_cast<const float4*>(urow + m);
            float dts[4] = {dt4.x, dt4.y, dt4.z, dt4.w};
            float uus[4] = {uu4.x, uu4.y, uu4.z, uu4.w};
#pragma unroll
            for (int j = 0; j < 4; j++) {
                float Bn = dbc[(size_t)(m + j)*40 + 8 + n];
                h = __expf(dts[j]*A)*h + dts[j]*Bn*uus[j];
                sumd += dts[j];
            }
        }
        s_hend[ch][dd][n] = h;
        if (n == 0) s_sumd[ch][dd] = sumd;
    }
    __syncthreads();

    // ---- pass 2: serial carry across 64 chunks (warp 0 only) ----
    if (w == 0) {
        float h = 0.f;
        for (int ch = 0; ch < NCHUNK; ch++) {
            s_hin[ch][dd][n] = h;
            float sd = s_sumd[ch][dd];
            h = __expf(sd*A)*h + s_hend[ch][dd][n];
        }
    }
    __syncthreads();

    // ---- pass 3: rescan with entry state; y = (h.C + u*Dp)*silu(z) ----
    float Dd = Dp[d];
#pragma unroll
    for (int c = 0; c < 4; c++) {
        int ch = w*4 + c;
        int m0 = b*LSEQ + ch*LCHUNK;
        float h = s_hin[ch][dd][n];
        for (int l4 = 0; l4 < LCHUNK; l4 += 4) {
            int m = m0 + l4;
            float4 dt4 = *reinterpret_cast<const float4*>(drow + m);
            float4 uu4 = *reinterpret_cast<const float4*>(urow + m);
            float4 z4  = *reinterpret_cast<const float4*>(zrow + m);
            float dts[4] = {dt4.x, dt4.y, dt4.z, dt4.w};
            float uus[4] = {uu4.x, uu4.y, uu4.z, uu4.w};
            float zs[4]  = {z4.x, z4.y, z4.z, z4.w};
            float ys[4];
#pragma unroll
            for (int j = 0; j < 4; j++) {
                float Bn = dbc[(size_t)(m + j)*40 + 8 + n];
                float Cn = dbc[(size_t)(m + j)*40 + 24 + n];
                h = __expf(dts[j]*A)*h + dts[j]*Bn*uus[j];
                ys[j] = h*Cn;
            }
#pragma unroll
            for (int j = 0; j < 4; j++) {
                ys[j] += __shfl_xor_sync(0xffffffffu, ys[j], 8, 16);
                ys[j] += __shfl_xor_sync(0xffffffffu, ys[j], 4, 16);
                ys[j] += __shfl_xor_sync(0xffffffffu, ys[j], 2, 16);
                ys[j] += __shfl_xor_sync(0xffffffffu, ys[j], 1, 16);
            }
            if (n == 0) {
#pragma unroll
                for (int j = 0; j < 4; j++)
                    yrow[m + j] = tf32r((ys[j] + uus[j]*Dd) * silu_f(zs[j]));
            }
        }
    }
}

// ---------------------------------------------------------------------------
// 9. LayerNorm over 128 channels + silu ; channel-major tf32 out
// ---------------------------------------------------------------------------
__global__ __launch_bounds__(256) void k_ln_silu(const float* __restrict__ gamma,
                                                 const float* __restrict__ beta)
{
    __shared__ float sT[128][36];
    int tid = threadIdx.x;
    int wid = tid >> 5, lane = tid & 31;
    int m_base = blockIdx.x*32;

    for (int r = 0; r < 4; r++) {
        int mloc = r*8 + wid;
        int m = m_base + mloc;
        float4 v = *reinterpret_cast<const float4*>(g_ym + (size_t)m*128 + lane*4);
        float s  = v.x + v.y + v.z + v.w;
        float s2 = v.x*v.x + v.y*v.y + v.z*v.z + v.w*v.w;
#pragma unroll
        for (int k = 16; k >= 1; k >>= 1) {
            s  += __shfl_xor_sync(0xffffffffu, s,  k);
            s2 += __shfl_xor_sync(0xffffffffu, s2, k);
        }
        float mean = s * (1.f/128.f);
        float var  = s2 * (1.f/128.f) - mean*mean;
        float rstd = rsqrtf(var + 1e-5f);
        float va[4] = {v.x, v.y, v.z, v.w};
#pragma unroll
        for (int i = 0; i < 4; i++) {
            int c = lane*4 + i;
            float t = (va[i] - mean)*rstd*gamma[c] + beta[c];
            sT[c][mloc] = tf32r(silu_f(t));
        }
    }
    __syncthreads();

    int mq = tid & 7;
    int c0 = tid >> 3;
    for (int cc = c0; cc < 128; cc += 32) {
        float4 v = *reinterpret_cast<const float4*>(&sT[cc][mq*4]);
        *reinterpret_cast<float4*>(g_lnT + (size_t)cc*MTOT + m_base + mq*4) = v;
    }
}

// ---------------------------------------------------------------------------
extern "C" void kernel_launch(void* const* d_in, const int* in_sizes, int n_in,
                              void* d_out, int out_size)
{
    const float* x        = (const float*)d_in[0];
    const float* skip_x   = (const float*)d_in[1];
    const float* up_w     = (const float*)d_in[2];
    const float* up_b     = (const float*)d_in[3];
    const float* in_proj  = (const float*)d_in[4];
    const float* conv1d_w = (const float*)d_in[5];
    const float* conv1d_b = (const float*)d_in[6];
    const float* x_proj   = (const float*)d_in[7];
    const float* dt_proj_w= (const float*)d_in[8];
    const float* dt_proj_b= (const float*)d_in[9];
    const float* A_log    = (const float*)d_in[10];
    const float* Dp       = (const float*)d_in[11];
    const float* out_proj = (const float*)d_in[12];
    const float* ln_gamma = (const float*)d_in[13];
    const float* ln_beta  = (const float*)d_in[14];
    const float* convout_w= (const float*)d_in[15];
    const float* convout_b= (const float*)d_in[16];
    float* out = (float*)d_out;

    float *p_seqT, *p_xzT, *p_uT, *p_yT, *p_lnT, *p_dbc, *p_ym;
    float *p_wrnd, *p_wrnd2, *p_wrnd3, *p_wrnd4;
    cudaGetSymbolAddress((void**)&p_seqT, g_seqT);
    cudaGetSymbolAddress((void**)&p_xzT,  g_xzT);
    cudaGetSymbolAddress((void**)&p_uT,   g_uT);
    cudaGetSymbolAddress((void**)&p_yT,   g_yT);
    cudaGetSymbolAddress((void**)&p_lnT,  g_lnT);
    cudaGetSymbolAddress((void**)&p_dbc,  g_dbc);
    cudaGetSymbolAddress((void**)&p_ym,   g_ym);
    cudaGetSymbolAddress((void**)&p_wrnd,  g_wrnd);
    cudaGetSymbolAddress((void**)&p_wrnd2, g_wrnd2);
    cudaGetSymbolAddress((void**)&p_wrnd3, g_wrnd3);
    cudaGetSymbolAddress((void**)&p_wrnd4, g_wrnd4);

    // 0: merged front-end (upsample + copy_skip + weight prep)
    k_front<<<1760, 256>>>(x, up_b, skip_x, up_w, in_proj, out_proj,
                           convout_w, x_proj);

    // 1: in_proj (N=512, K=128) -> g_xzT channel-major [tf32]
    k_mma0<<<dim3(MTOT/128, 4), 256>>>(p_wrnd, p_seqT, p_xzT, 512, 128);

    // 2: conv1d + silu -> g_uT (fp32)
    k_conv1d_silu<<<dim3(16, DINNER), 256>>>(conv1d_w, conv1d_b);

    // 3: x_proj (tf32, padded N) -> g_dbc row-major [m][40]
    k_mma3<<<MTOT/128, 256>>>(p_wrnd4, p_uT, p_dbc, 256);

    // 4: delta
    k_delta<<<MTOT/64, 256>>>(dt_proj_w, dt_proj_b);

    // 5: fused selective scan (fp32)
    k_scan_all<<<BATCH*128, 512>>>(A_log, Dp);

    // 6: out_proj (N=128, K=256) -> g_ym row-major [m][128]  [tf32]
    k_mma1<<<dim3(MTOT/128, 1), 256>>>(p_wrnd2, p_yT, p_ym, 128, 256, 128);

    // 7: LayerNorm + silu -> g_lnT channel-major (tf32)
    k_ln_silu<<<MTOT/32, 256>>>(ln_gamma, ln_beta);

    // 8: convout 1x1 (N=64, K=128) -> d_out NCHW + bias  [tf32]
    k_mma2<<<dim3(MTOT/128, 1), 256>>>(p_wrnd3, p_lnT, out, convout_b, 64, 128);
}